// round 5
// baseline (speedup 1.0000x reference)
#include <cuda_runtime.h>
#include <math.h>
#include <stdint.h>

#define TT   1024
#define DMM  1024
#define HH   16
#define RNK  32
#define NT   16
#define NPAIR 136
#define SCALE 0.125f
#define NPROJ 3120     // 3*1024 + 32 + 16

// ---------------- scratch (device globals) ----------------------------------
__device__ float g_q   [TT*DMM];
__device__ float g_k   [TT*DMM];
__device__ float g_v   [TT*DMM];
__device__ float g_wpre[TT*DMM];
__device__ float g_w   [TT*DMM];
__device__ float g_xw1 [TT*RNK];
__device__ float g_beta[TT*HH];
__device__ float g_M [HH*TT*TT];
__device__ float g_Mk[HH*TT*TT];
__device__ float g_G [HH*TT*TT];   // Aqw -> G in place
__device__ float g_S [HH*TT*TT];   // QK -> scaled logits
__device__ float g_invA[HH*NT*64*64];
__device__ float g_o [TT*DMM];

// ---------------- split-tf32 helpers -----------------------------------------
__device__ __forceinline__ void splitf(float x, uint32_t& hi, uint32_t& lo) {
    uint32_t h; asm("cvt.rna.tf32.f32 %0, %1;" : "=r"(h) : "f"(x));
    float hf = __uint_as_float(h);
    asm("cvt.rna.tf32.f32 %0, %1;" : "=r"(lo) : "f"(x - hf));
    hi = h;
}

__device__ __forceinline__ void mma8(float (&c)[4], const uint32_t (&a)[4],
                                     const uint32_t (&b)[2]) {
    asm volatile(
        "mma.sync.aligned.m16n8k8.row.col.f32.tf32.tf32.f32 "
        "{%0,%1,%2,%3},{%4,%5,%6,%7},{%8,%9},{%0,%1,%2,%3};"
        : "+f"(c[0]), "+f"(c[1]), "+f"(c[2]), "+f"(c[3])
        : "r"(a[0]), "r"(a[1]), "r"(a[2]), "r"(a[3]), "r"(b[0]), "r"(b[1]));
}

#define WARP_IDX                                   \
    int tid = threadIdx.x;                         \
    int lane = tid & 31, wid = tid >> 5;           \
    int wr = (wid >> 2) * 32, wc = (wid & 3) * 16; \
    int g = lane >> 2, tig = lane & 3;

#define ACC_ROW(mi,e) (wr + (mi)*16 + g + ((e)>>1)*8)
#define ACC_COL(ni,e) (wc + (ni)*8 + tig*2 + ((e)&1))

// 64x64x64 tile: raw fp32 in smem, split hi/lo, 3-mma emulation (~fp32 exact)
template<int PA, int PB>
__device__ __forceinline__ void mma_tile_sp(const float (*As)[PA], const float (*Bs)[PB],
                                            float (&acc)[2][2][4],
                                            int wr, int wc, int g, int tig)
{
#pragma unroll
    for (int kb = 0; kb < 64; kb += 8) {
        uint32_t ah[2][4], al[2][4], bh[2][2], bl[2][2];
#pragma unroll
        for (int mi = 0; mi < 2; mi++) {
            int r0 = wr + mi*16 + g;
            splitf(As[r0    ][kb+tig  ], ah[mi][0], al[mi][0]);
            splitf(As[r0 + 8][kb+tig  ], ah[mi][1], al[mi][1]);
            splitf(As[r0    ][kb+tig+4], ah[mi][2], al[mi][2]);
            splitf(As[r0 + 8][kb+tig+4], ah[mi][3], al[mi][3]);
        }
#pragma unroll
        for (int ni = 0; ni < 2; ni++) {
            int c0 = wc + ni*8 + g;
            splitf(Bs[kb+tig  ][c0], bh[ni][0], bl[ni][0]);
            splitf(Bs[kb+tig+4][c0], bh[ni][1], bl[ni][1]);
        }
#pragma unroll
        for (int mi = 0; mi < 2; mi++)
#pragma unroll
        for (int ni = 0; ni < 2; ni++) {
            mma8(acc[mi][ni], ah[mi], bl[ni]);
            mma8(acc[mi][ni], al[mi], bh[ni]);
            mma8(acc[mi][ni], ah[mi], bh[ni]);
        }
    }
}

// dual-B variant: share A fragments across two products
template<int PA, int PB>
__device__ __forceinline__ void mma_tile_sp2(const float (*As)[PA],
        const float (*B1)[PB], const float (*B2)[PB],
        float (&c1)[2][2][4], float (&c2)[2][2][4],
        int wr, int wc, int g, int tig)
{
#pragma unroll
    for (int kb = 0; kb < 64; kb += 8) {
        uint32_t ah[2][4], al[2][4];
        uint32_t b1h[2][2], b1l[2][2], b2h[2][2], b2l[2][2];
#pragma unroll
        for (int mi = 0; mi < 2; mi++) {
            int r0 = wr + mi*16 + g;
            splitf(As[r0    ][kb+tig  ], ah[mi][0], al[mi][0]);
            splitf(As[r0 + 8][kb+tig  ], ah[mi][1], al[mi][1]);
            splitf(As[r0    ][kb+tig+4], ah[mi][2], al[mi][2]);
            splitf(As[r0 + 8][kb+tig+4], ah[mi][3], al[mi][3]);
        }
#pragma unroll
        for (int ni = 0; ni < 2; ni++) {
            int c0 = wc + ni*8 + g;
            splitf(B1[kb+tig  ][c0], b1h[ni][0], b1l[ni][0]);
            splitf(B1[kb+tig+4][c0], b1h[ni][1], b1l[ni][1]);
            splitf(B2[kb+tig  ][c0], b2h[ni][0], b2l[ni][0]);
            splitf(B2[kb+tig+4][c0], b2h[ni][1], b2l[ni][1]);
        }
#pragma unroll
        for (int mi = 0; mi < 2; mi++)
#pragma unroll
        for (int ni = 0; ni < 2; ni++) {
            mma8(c1[mi][ni], ah[mi], b1l[ni]);
            mma8(c1[mi][ni], al[mi], b1h[ni]);
            mma8(c1[mi][ni], ah[mi], b1h[ni]);
            mma8(c2[mi][ni], ah[mi], b2l[ni]);
            mma8(c2[mi][ni], al[mi], b2h[ni]);
            mma8(c2[mi][ni], ah[mi], b2h[ni]);
        }
    }
}

__device__ __forceinline__ void pair_map(int p, int& bi, int& bj) {
    int b = 0;
    while ((b+1)*(b+2)/2 <= p) b++;
    bi = b; bj = p - b*(b+1)/2;
}

// ---------------- fused projection: x @ [Wq|Wk|Wv|Ww1|Wb] --------------------
__global__ __launch_bounds__(256) void proj_kernel(
    const float* __restrict__ x,  const float* __restrict__ Wq,
    const float* __restrict__ Wk, const float* __restrict__ Wv,
    const float* __restrict__ Ww1,const float* __restrict__ Wb)
{
    __shared__ float As[64][68];
    __shared__ float Bs[64][73];
    WARP_IDX;
    int bm = blockIdx.y * 64, bn = blockIdx.x * 64;
    float acc[2][2][4] = {};
    for (int kt = 0; kt < DMM; kt += 64) {
        __syncthreads();
        for (int l = tid; l < 4096; l += 256) {
            int r = l >> 6, c = l & 63;
            As[r][c] = x[(size_t)(bm + r)*DMM + kt + c];
        }
        for (int l = tid; l < 4096; l += 256) {
            int r = l >> 6, c = l & 63;
            int n = bn + c, kk = kt + r;
            float v = 0.f;
            if (n < 3072) {
                const float* W = (n < 1024) ? Wq : (n < 2048) ? Wk : Wv;
                v = W[(size_t)kk*DMM + (n & 1023)];
            } else if (n < 3104) v = Ww1[kk*RNK + (n - 3072)];
            else if (n < NPROJ)  v = Wb [kk*HH  + (n - 3104)];
            Bs[r][c] = v;
        }
        __syncthreads();
        mma_tile_sp(As, Bs, acc, wr, wc, g, tig);
    }
#pragma unroll
    for (int mi = 0; mi < 2; mi++)
#pragma unroll
    for (int ni = 0; ni < 2; ni++)
#pragma unroll
    for (int e = 0; e < 4; e++) {
        int row = bm + ACC_ROW(mi, e);
        int col = bn + ACC_COL(ni, e);
        float v = acc[mi][ni][e];
        if      (col < 1024)  g_q[(size_t)row*DMM + col] = v;
        else if (col < 2048)  g_k[(size_t)row*DMM + (col - 1024)] = v;
        else if (col < 3072)  g_v[(size_t)row*DMM + (col - 2048)] = v;
        else if (col < 3104)  g_xw1[row*RNK + (col - 3072)] = v;
        else if (col < NPROJ) g_beta[row*HH + (col - 3104)] = 2.f/(1.f + expf(-v));
    }
}

// ---------------- generic C = A@B --------------------------------------------
__global__ __launch_bounds__(256) void gemm_tc(
    const float* __restrict__ A, const float* __restrict__ B,
    float* __restrict__ C, int N, int K)
{
    __shared__ float As[64][68];
    __shared__ float Bs[64][73];
    WARP_IDX;
    int bm = blockIdx.y * 64, bn = blockIdx.x * 64;
    float acc[2][2][4] = {};
    for (int kt = 0; kt < K; kt += 64) {
        __syncthreads();
        for (int l = tid; l < 4096; l += 256) {
            int r = l >> 6, c = l & 63;
            As[r][c] = (kt + c < K) ? A[(size_t)(bm + r)*K + kt + c] : 0.f;
        }
        for (int l = tid; l < 4096; l += 256) {
            int r = l >> 6, c = l & 63;
            Bs[r][c] = (kt + r < K) ? B[(size_t)(kt + r)*N + bn + c] : 0.f;
        }
        __syncthreads();
        mma_tile_sp(As, Bs, acc, wr, wc, g, tig);
    }
#pragma unroll
    for (int mi = 0; mi < 2; mi++)
#pragma unroll
    for (int ni = 0; ni < 2; ni++)
#pragma unroll
    for (int e = 0; e < 4; e++)
        C[(size_t)(bm + ACC_ROW(mi, e))*N + bn + ACC_COL(ni, e)] = acc[mi][ni][e];
}

// ---------------- causal depthwise conv(3) + SiLU + per-head L2 norm ---------
__global__ void conv_norm_kernel(const float* __restrict__ conv_w)
{
    int t = blockIdx.x;
    int c = threadIdx.x;
    float x0  = g_wpre[t*DMM + c];
    float xm1 = (t >= 1) ? g_wpre[(t-1)*DMM + c] : 0.f;
    float xm2 = (t >= 2) ? g_wpre[(t-2)*DMM + c] : 0.f;
    float y = conv_w[c*3+0]*xm2 + conv_w[c*3+1]*xm1 + conv_w[c*3+2]*x0;
    y = y / (1.f + expf(-y));
    float y2 = y * y;
#pragma unroll
    for (int o = 16; o; o >>= 1) y2 += __shfl_xor_sync(0xffffffffu, y2, o);
    __shared__ float wsum[32];
    if ((c & 31) == 0) wsum[c >> 5] = y2;
    __syncthreads();
    int h = c >> 6;
    float ss = wsum[2*h] + wsum[2*h+1];
    g_w[t*DMM + c] = y * rsqrtf(ss + 1e-6f);
}

// ---------------- fused headdot: M, Mk, Aqw, QK per (pair, head) -------------
__global__ __launch_bounds__(256) void headdot4_kernel()
{
    extern __shared__ float dsm[];
    float (*Aq)[68] = (float(*)[68])dsm;                     // [i][d]
    float (*Aw)[68] = (float(*)[68])(dsm + 64*68);
    float (*Bw)[73] = (float(*)[73])(dsm + 2*64*68);         // [d][j]
    float (*Bk)[73] = (float(*)[73])(dsm + 2*64*68 + 64*73);
    int bi, bj; pair_map(blockIdx.x, bi, bj);
    int h = blockIdx.y;
    WARP_IDX;
    for (int l = tid; l < 4096; l += 256) {
        int r = l >> 6, c = l & 63;
        Aq[r][c] = g_q[(size_t)(bi*64 + r)*DMM + h*64 + c];
        Aw[r][c] = g_w[(size_t)(bi*64 + r)*DMM + h*64 + c];
        Bw[c][r] = g_w[(size_t)(bj*64 + r)*DMM + h*64 + c];
        Bk[c][r] = g_k[(size_t)(bj*64 + r)*DMM + h*64 + c];
    }
    __syncthreads();
    size_t base = (size_t)h*TT*TT;

    // pass 1: Aqw = q.w (causal), QK = q.k
    {
        float aqw[2][2][4] = {}, aqk[2][2][4] = {};
        mma_tile_sp2(Aq, Bw, Bk, aqw, aqk, wr, wc, g, tig);
#pragma unroll
        for (int mi = 0; mi < 2; mi++)
#pragma unroll
        for (int ni = 0; ni < 2; ni++)
#pragma unroll
        for (int e = 0; e < 4; e++) {
            int r = bi*64 + ACC_ROW(mi, e), c = bj*64 + ACC_COL(ni, e);
            g_G[base + (size_t)r*TT + c] = (c <= r) ? aqw[mi][ni][e] : 0.f;
            g_S[base + (size_t)r*TT + c] = aqk[mi][ni][e];
        }
    }
    // pass 2: M = beta * w.w (strict), Mk = beta * w.k (strict)
    {
        float am[2][2][4] = {}, amk[2][2][4] = {};
        mma_tile_sp2(Aw, Bw, Bk, am, amk, wr, wc, g, tig);
#pragma unroll
        for (int mi = 0; mi < 2; mi++)
#pragma unroll
        for (int ni = 0; ni < 2; ni++)
#pragma unroll
        for (int e = 0; e < 4; e++) {
            int r = bi*64 + ACC_ROW(mi, e), c = bj*64 + ACC_COL(ni, e);
            float be = (r > c) ? g_beta[r*HH + h] : 0.f;
            g_M [base + (size_t)r*TT + c] = be * am [mi][ni][e];
            g_Mk[base + (size_t)r*TT + c] = be * amk[mi][ni][e];
        }
    }
}

// ---------------- invert unit-lower diagonal blocks of A = I + M -------------
__global__ void inv_diag_kernel()
{
    int J = blockIdx.x, h = blockIdx.y;
    int c = threadIdx.x;
    __shared__ float L[64][65];
    __shared__ float X[64][65];
    const float* Mt = &g_M[(size_t)h*TT*TT + (size_t)(J*64)*TT + J*64];
    for (int r = 0; r < 64; r++) {
        L[r][c] = (r > c) ? Mt[(size_t)r*TT + c] : (r == c ? 1.f : 0.f);
        X[r][c] = (r == c) ? 1.f : 0.f;
    }
    __syncthreads();
    for (int r = 1; r < 64; r++) {
        if (c < r) {
            float a = 0.f;
            for (int s = c; s < r; s++) a += L[r][s] * X[s][c];
            X[r][c] = -a;
        }
        __syncthreads();
    }
    float* out = &g_invA[((size_t)h*NT + J)*4096];
    for (int r = 0; r < 64; r++) out[r*64 + c] = X[r][c];
}

// ---------------- per-(head, block-row): solve + S + softmax + PV ------------
__global__ __launch_bounds__(256) void row_kernel()
{
    int I = NT - 1 - blockIdx.x;         // heavy rows first
    int h = blockIdx.y;
    size_t base = (size_t)h*TT*TT;
    __shared__ float Gs[64][68];
    __shared__ float Ms[64][73];
    __shared__ float rmax[64], rinv[64], red[64][4];
    WARP_IDX;

    // ---- blocked back-substitution across row I (J descending) ----
    for (int J = I; J >= 0; J--) {
        float acc[2][2][4];
        const float* Aqw = &g_G[base + (size_t)(I*64)*TT + J*64];
#pragma unroll
        for (int mi = 0; mi < 2; mi++)
#pragma unroll
        for (int ni = 0; ni < 2; ni++)
#pragma unroll
        for (int e = 0; e < 4; e++)
            acc[mi][ni][e] = Aqw[(size_t)ACC_ROW(mi,e)*TT + ACC_COL(ni,e)];

        for (int S = J + 1; S <= I; S++) {
            __syncthreads();
            const float* Gp = &g_G[base + (size_t)(I*64)*TT + S*64];
            const float* Mp = &g_M[base + (size_t)(S*64)*TT + J*64];
            for (int l = tid; l < 4096; l += 256) {
                int r = l >> 6, c = l & 63;
                Gs[r][c] =  Gp[(size_t)r*TT + c];
                Ms[r][c] = -Mp[(size_t)r*TT + c];
            }
            __syncthreads();
            mma_tile_sp(Gs, Ms, acc, wr, wc, g, tig);
        }
        __syncthreads();
        // multiply by invA_J
#pragma unroll
        for (int mi = 0; mi < 2; mi++)
#pragma unroll
        for (int ni = 0; ni < 2; ni++)
#pragma unroll
        for (int e = 0; e < 4; e++)
            Gs[ACC_ROW(mi,e)][ACC_COL(ni,e)] = acc[mi][ni][e];
        const float* Ip = &g_invA[((size_t)h*NT + J)*4096];
        for (int l = tid; l < 4096; l += 256) {
            int r = l >> 6, c = l & 63;
            Ms[r][c] = Ip[l];
        }
        __syncthreads();
        float fin[2][2][4] = {};
        mma_tile_sp(Gs, Ms, fin, wr, wc, g, tig);
        float* Gout = &g_G[base + (size_t)(I*64)*TT + J*64];
#pragma unroll
        for (int mi = 0; mi < 2; mi++)
#pragma unroll
        for (int ni = 0; ni < 2; ni++)
#pragma unroll
        for (int e = 0; e < 4; e++)
            Gout[(size_t)ACC_ROW(mi,e)*TT + ACC_COL(ni,e)] = fin[mi][ni][e];
        __syncthreads();
    }

    // ---- S row: S[I,bj] = (QK - G Mk) * scale ----
    for (int bj = 0; bj <= I; bj++) {
        float acc[2][2][4];
        const float* QK = &g_S[base + (size_t)(I*64)*TT + bj*64];
#pragma unroll
        for (int mi = 0; mi < 2; mi++)
#pragma unroll
        for (int ni = 0; ni < 2; ni++)
#pragma unroll
        for (int e = 0; e < 4; e++)
            acc[mi][ni][e] = QK[(size_t)ACC_ROW(mi,e)*TT + ACC_COL(ni,e)];

        for (int S = bj; S <= I; S++) {
            __syncthreads();
            const float* Gp = &g_G [base + (size_t)(I*64)*TT + S*64];
            const float* Mp = &g_Mk[base + (size_t)(S*64)*TT + bj*64];
            for (int l = tid; l < 4096; l += 256) {
                int r = l >> 6, c = l & 63;
                Gs[r][c] =  Gp[(size_t)r*TT + c];
                Ms[r][c] = -Mp[(size_t)r*TT + c];
            }
            __syncthreads();
            mma_tile_sp(Gs, Ms, acc, wr, wc, g, tig);
        }
        float* Sp = &g_S[base + (size_t)(I*64)*TT + bj*64];
#pragma unroll
        for (int mi = 0; mi < 2; mi++)
#pragma unroll
        for (int ni = 0; ni < 2; ni++)
#pragma unroll
        for (int e = 0; e < 4; e++) {
            int r = ACC_ROW(mi,e), c = ACC_COL(ni,e);
            float v = acc[mi][ni][e] * SCALE;
            if (bj == I && c > r) v = -1e30f;      // causal mask on diagonal tile
            Sp[(size_t)r*TT + c] = v;
        }
        __syncthreads();
    }

    // ---- row softmax stats ----
    {
        int r = tid >> 2, part = tid & 3;
        const float* Srow = &g_S[base + (size_t)(I*64 + r)*TT];
        int ncols = (I + 1) * 64;
        float m = -1e30f;
        for (int c = part; c < ncols; c += 4) m = fmaxf(m, Srow[c]);
        red[r][part] = m;
        __syncthreads();
        m = fmaxf(fmaxf(red[r][0], red[r][1]), fmaxf(red[r][2], red[r][3]));
        float s = 0.f;
        for (int c = part; c < ncols; c += 4) s += __expf(Srow[c] - m);
        __syncthreads();
        red[r][part] = s;
        __syncthreads();
        if (part == 0) {
            rmax[r] = m;
            rinv[r] = 1.f / (red[r][0] + red[r][1] + red[r][2] + red[r][3]);
        }
        __syncthreads();
    }

    // ---- o[I] = P @ V ----
    float oacc[2][2][4] = {};
    for (int bj = 0; bj <= I; bj++) {
        __syncthreads();
        const float* Sp = &g_S[base + (size_t)(I*64)*TT + bj*64];
        for (int l = tid; l < 4096; l += 256) {
            int r = l >> 6, c = l & 63;
            Gs[r][c] = __expf(Sp[(size_t)r*TT + c] - rmax[r]) * rinv[r];
            Ms[r][c] = g_v[(size_t)(bj*64 + r)*DMM + h*64 + c];
        }
        __syncthreads();
        mma_tile_sp(Gs, Ms, oacc, wr, wc, g, tig);
    }
#pragma unroll
    for (int mi = 0; mi < 2; mi++)
#pragma unroll
    for (int ni = 0; ni < 2; ni++)
#pragma unroll
    for (int e = 0; e < 4; e++)
        g_o[(size_t)(I*64 + ACC_ROW(mi,e))*DMM + h*64 + ACC_COL(ni,e)] = oacc[mi][ni][e];
}

// ---------------- launcher ----------------------------------------------------
extern "C" void kernel_launch(void* const* d_in, const int* in_sizes, int n_in,
                              void* d_out, int out_size)
{
    const float* x     = (const float*)d_in[0];
    const float* Wq    = (const float*)d_in[1];
    const float* Wk    = (const float*)d_in[2];
    const float* Wv    = (const float*)d_in[3];
    const float* Ww1   = (const float*)d_in[4];
    const float* Ww2   = (const float*)d_in[5];
    const float* convw = (const float*)d_in[6];
    const float* Wb    = (const float*)d_in[7];
    const float* Wo    = (const float*)d_in[8];

    float *xw1, *wpre, *o;
    cudaGetSymbolAddress((void**)&xw1,  g_xw1);
    cudaGetSymbolAddress((void**)&wpre, g_wpre);
    cudaGetSymbolAddress((void**)&o,    g_o);

    static bool attr_set = false;
    const int HD4_SMEM = (2*64*68 + 2*64*73) * 4;   // 72192 B
    if (!attr_set) {
        cudaFuncSetAttribute(headdot4_kernel,
                             cudaFuncAttributeMaxDynamicSharedMemorySize, HD4_SMEM);
        attr_set = true;
    }

    dim3 blk(256);

    // fused projections: q | k | v | xw1 | beta
    proj_kernel<<<dim3((NPROJ + 63)/64, 16), blk>>>(x, Wq, Wk, Wv, Ww1, Wb);

    // wpre = xw1 @ Ww2  (K=32)
    gemm_tc<<<dim3(16, 16), blk>>>(xw1, Ww2, wpre, DMM, RNK);

    // conv + silu + per-head l2 norm
    conv_norm_kernel<<<TT, 1024>>>(convw);

    // fused per-head products on lower tiles: M, Mk, Aqw, QK
    headdot4_kernel<<<dim3(NPAIR, HH), blk, HD4_SMEM>>>();

    // invert diagonal blocks of I + M
    inv_diag_kernel<<<dim3(NT, HH), 64>>>();

    // one CTA per (head, block-row): solve + S + softmax + PV
    row_kernel<<<dim3(NT, HH), blk>>>();

    // output projection
    gemm_tc<<<dim3(16, 16), blk>>>(o, Wo, (float*)d_out, DMM, DMM);
}

// round 6
// speedup vs baseline: 1.7171x; 1.7171x over previous
#include <cuda_runtime.h>
#include <math.h>
#include <stdint.h>

#define TT   1024
#define DMM  1024
#define HH   16
#define RNK  32
#define NT   16
#define NPAIR 136
#define SCALE 0.125f
#define NPROJ 3120     // 3*1024 + 32 + 16

// ---------------- scratch (device globals) ----------------------------------
__device__ float g_q   [TT*DMM];
__device__ float g_k   [TT*DMM];
__device__ float g_v   [TT*DMM];
__device__ float g_wpre[TT*DMM];
__device__ float g_w   [TT*DMM];
__device__ float g_xw1 [TT*RNK];
__device__ float g_beta[TT*HH];
__device__ float g_M [HH*TT*TT];
__device__ float g_Mk[HH*TT*TT];
__device__ float g_G [HH*TT*TT];   // Aqw -> G in place
__device__ float g_S [HH*TT*TT];   // QK -> scaled logits
__device__ float g_invA[HH*NT*64*64];
__device__ float g_o [TT*DMM];

// ---------------- tf32 helpers ------------------------------------------------
__device__ __forceinline__ float to_tf32(float x) {
    uint32_t u; asm("cvt.rna.tf32.f32 %0, %1;" : "=r"(u) : "f"(x));
    return __uint_as_float(u);
}

__device__ __forceinline__ void mma8(float (&c)[4], const uint32_t (&a)[4],
                                     const uint32_t (&b)[2]) {
    asm volatile(
        "mma.sync.aligned.m16n8k8.row.col.f32.tf32.tf32.f32 "
        "{%0,%1,%2,%3},{%4,%5,%6,%7},{%8,%9},{%0,%1,%2,%3};"
        : "+f"(c[0]), "+f"(c[1]), "+f"(c[2]), "+f"(c[3])
        : "r"(a[0]), "r"(a[1]), "r"(a[2]), "r"(a[3]), "r"(b[0]), "r"(b[1]));
}

// ---- 8-warp (256 thread) layout: warp tile 32x16 ------------------------------
#define WARP_IDX                                   \
    int tid = threadIdx.x;                         \
    int lane = tid & 31, wid = tid >> 5;           \
    int wr = (wid >> 2) * 32, wc = (wid & 3) * 16; \
    int g = lane >> 2, tig = lane & 3;

#define ACC_ROW(mi,e) (wr + (mi)*16 + g + ((e)>>1)*8)
#define ACC_COL(ni,e) (wc + (ni)*8 + tig*2 + ((e)&1))

template<int PA, int PB>
__device__ __forceinline__ void mma_tile(const float (*As)[PA], const float (*Bs)[PB],
                                         float (&acc)[2][2][4],
                                         int wr, int wc, int g, int tig)
{
#pragma unroll
    for (int kb = 0; kb < 64; kb += 8) {
        uint32_t a[2][4], b[2][2];
#pragma unroll
        for (int mi = 0; mi < 2; mi++) {
            int r0 = wr + mi*16 + g;
            a[mi][0] = __float_as_uint(As[r0    ][kb + tig    ]);
            a[mi][1] = __float_as_uint(As[r0 + 8][kb + tig    ]);
            a[mi][2] = __float_as_uint(As[r0    ][kb + tig + 4]);
            a[mi][3] = __float_as_uint(As[r0 + 8][kb + tig + 4]);
        }
#pragma unroll
        for (int ni = 0; ni < 2; ni++) {
            int c0 = wc + ni*8 + g;
            b[ni][0] = __float_as_uint(Bs[kb + tig    ][c0]);
            b[ni][1] = __float_as_uint(Bs[kb + tig + 4][c0]);
        }
#pragma unroll
        for (int mi = 0; mi < 2; mi++)
#pragma unroll
            for (int ni = 0; ni < 2; ni++)
                mma8(acc[mi][ni], a[mi], b[ni]);
    }
}

// dual-B: share A fragments across two products
template<int PA, int PB>
__device__ __forceinline__ void mma_tile2(const float (*As)[PA],
        const float (*B1)[PB], const float (*B2)[PB],
        float (&c1)[2][2][4], float (&c2)[2][2][4],
        int wr, int wc, int g, int tig)
{
#pragma unroll
    for (int kb = 0; kb < 64; kb += 8) {
        uint32_t a[2][4], b1[2][2], b2[2][2];
#pragma unroll
        for (int mi = 0; mi < 2; mi++) {
            int r0 = wr + mi*16 + g;
            a[mi][0] = __float_as_uint(As[r0    ][kb + tig    ]);
            a[mi][1] = __float_as_uint(As[r0 + 8][kb + tig    ]);
            a[mi][2] = __float_as_uint(As[r0    ][kb + tig + 4]);
            a[mi][3] = __float_as_uint(As[r0 + 8][kb + tig + 4]);
        }
#pragma unroll
        for (int ni = 0; ni < 2; ni++) {
            int c0 = wc + ni*8 + g;
            b1[ni][0] = __float_as_uint(B1[kb + tig    ][c0]);
            b1[ni][1] = __float_as_uint(B1[kb + tig + 4][c0]);
            b2[ni][0] = __float_as_uint(B2[kb + tig    ][c0]);
            b2[ni][1] = __float_as_uint(B2[kb + tig + 4][c0]);
        }
#pragma unroll
        for (int mi = 0; mi < 2; mi++)
#pragma unroll
        for (int ni = 0; ni < 2; ni++) {
            mma8(c1[mi][ni], a[mi], b1[ni]);
            mma8(c2[mi][ni], a[mi], b2[ni]);
        }
    }
}

// ---- 16-warp (512 thread) layout: warp tile 16x16 -----------------------------
#define WARP_IDX16                                 \
    int tid = threadIdx.x;                         \
    int lane = tid & 31, wid = tid >> 5;           \
    int wr = (wid >> 2) * 16, wc = (wid & 3) * 16; \
    int g = lane >> 2, tig = lane & 3;

#define A16_ROW(e)    (wr + g + ((e)>>1)*8)
#define A16_COL(ni,e) (wc + (ni)*8 + tig*2 + ((e)&1))

template<int PA, int PB>
__device__ __forceinline__ void mma_tile16(const float (*As)[PA], const float (*Bs)[PB],
                                           float (&acc)[2][4],
                                           int wr, int wc, int g, int tig)
{
#pragma unroll
    for (int kb = 0; kb < 64; kb += 8) {
        uint32_t a[4], b[2][2];
        a[0] = __float_as_uint(As[wr + g    ][kb + tig    ]);
        a[1] = __float_as_uint(As[wr + g + 8][kb + tig    ]);
        a[2] = __float_as_uint(As[wr + g    ][kb + tig + 4]);
        a[3] = __float_as_uint(As[wr + g + 8][kb + tig + 4]);
#pragma unroll
        for (int ni = 0; ni < 2; ni++) {
            int c0 = wc + ni*8 + g;
            b[ni][0] = __float_as_uint(Bs[kb + tig    ][c0]);
            b[ni][1] = __float_as_uint(Bs[kb + tig + 4][c0]);
        }
        mma8(acc[0], a, b[0]);
        mma8(acc[1], a, b[1]);
    }
}

__device__ __forceinline__ void pair_map(int p, int& bi, int& bj) {
    int b = 0;
    while ((b+1)*(b+2)/2 <= p) b++;
    bi = b; bj = p - b*(b+1)/2;
}

// ---------------- fused projection: x @ [Wq|Wk|Wv|Ww1|Wb] ----------------------
__global__ __launch_bounds__(256) void proj_kernel(
    const float* __restrict__ x,  const float* __restrict__ Wq,
    const float* __restrict__ Wk, const float* __restrict__ Wv,
    const float* __restrict__ Ww1,const float* __restrict__ Wb)
{
    __shared__ float As[64][68];
    __shared__ float Bs[64][73];
    WARP_IDX;
    int bm = blockIdx.y * 64, bn = blockIdx.x * 64;
    float acc[2][2][4] = {};
    for (int kt = 0; kt < DMM; kt += 64) {
        __syncthreads();
        for (int l = tid; l < 4096; l += 256) {
            int r = l >> 6, c = l & 63;
            As[r][c] = to_tf32(x[(size_t)(bm + r)*DMM + kt + c]);
        }
        for (int l = tid; l < 4096; l += 256) {
            int r = l >> 6, c = l & 63;
            int n = bn + c, kk = kt + r;
            float v = 0.f;
            if (n < 3072) {
                const float* W = (n < 1024) ? Wq : (n < 2048) ? Wk : Wv;
                v = W[(size_t)kk*DMM + (n & 1023)];
            } else if (n < 3104) v = Ww1[kk*RNK + (n - 3072)];
            else if (n < NPROJ)  v = Wb [kk*HH  + (n - 3104)];
            Bs[r][c] = to_tf32(v);
        }
        __syncthreads();
        mma_tile(As, Bs, acc, wr, wc, g, tig);
    }
#pragma unroll
    for (int mi = 0; mi < 2; mi++)
#pragma unroll
    for (int ni = 0; ni < 2; ni++)
#pragma unroll
    for (int e = 0; e < 4; e++) {
        int row = bm + ACC_ROW(mi, e);
        int col = bn + ACC_COL(ni, e);
        float v = acc[mi][ni][e];
        if      (col < 1024)  g_q[(size_t)row*DMM + col] = v;
        else if (col < 2048)  g_k[(size_t)row*DMM + (col - 1024)] = v;
        else if (col < 3072)  g_v[(size_t)row*DMM + (col - 2048)] = v;
        else if (col < 3104)  g_xw1[row*RNK + (col - 3072)] = v;
        else if (col < NPROJ) g_beta[row*HH + (col - 3104)] = 2.f/(1.f + expf(-v));
    }
}

// ---------------- generic C = A@B ----------------------------------------------
__global__ __launch_bounds__(256) void gemm_tc(
    const float* __restrict__ A, const float* __restrict__ B,
    float* __restrict__ C, int N, int K)
{
    __shared__ float As[64][68];
    __shared__ float Bs[64][73];
    WARP_IDX;
    int bm = blockIdx.y * 64, bn = blockIdx.x * 64;
    float acc[2][2][4] = {};
    for (int kt = 0; kt < K; kt += 64) {
        __syncthreads();
        for (int l = tid; l < 4096; l += 256) {
            int r = l >> 6, c = l & 63;
            As[r][c] = (kt + c < K) ? to_tf32(A[(size_t)(bm + r)*K + kt + c]) : 0.f;
        }
        for (int l = tid; l < 4096; l += 256) {
            int r = l >> 6, c = l & 63;
            Bs[r][c] = (kt + r < K) ? to_tf32(B[(size_t)(kt + r)*N + bn + c]) : 0.f;
        }
        __syncthreads();
        mma_tile(As, Bs, acc, wr, wc, g, tig);
    }
#pragma unroll
    for (int mi = 0; mi < 2; mi++)
#pragma unroll
    for (int ni = 0; ni < 2; ni++)
#pragma unroll
    for (int e = 0; e < 4; e++)
        C[(size_t)(bm + ACC_ROW(mi, e))*N + bn + ACC_COL(ni, e)] = acc[mi][ni][e];
}

// ---------------- causal depthwise conv(3) + SiLU + per-head L2 norm -----------
__global__ void conv_norm_kernel(const float* __restrict__ conv_w)
{
    int t = blockIdx.x;
    int c = threadIdx.x;
    float x0  = g_wpre[t*DMM + c];
    float xm1 = (t >= 1) ? g_wpre[(t-1)*DMM + c] : 0.f;
    float xm2 = (t >= 2) ? g_wpre[(t-2)*DMM + c] : 0.f;
    float y = conv_w[c*3+0]*xm2 + conv_w[c*3+1]*xm1 + conv_w[c*3+2]*x0;
    y = y / (1.f + expf(-y));
    float y2 = y * y;
#pragma unroll
    for (int o = 16; o; o >>= 1) y2 += __shfl_xor_sync(0xffffffffu, y2, o);
    __shared__ float wsum[32];
    if ((c & 31) == 0) wsum[c >> 5] = y2;
    __syncthreads();
    int h = c >> 6;
    float ss = wsum[2*h] + wsum[2*h+1];
    g_w[t*DMM + c] = y * rsqrtf(ss + 1e-6f);
}

// ---------------- fused headdot: M, Mk, Aqw, QK per (pair, head) ---------------
__global__ __launch_bounds__(256) void headdot4_kernel()
{
    extern __shared__ float dsm[];
    float (*Aq)[68] = (float(*)[68])dsm;                     // [i][d]
    float (*Aw)[68] = (float(*)[68])(dsm + 64*68);
    float (*Bw)[73] = (float(*)[73])(dsm + 2*64*68);         // [d][j]
    float (*Bk)[73] = (float(*)[73])(dsm + 2*64*68 + 64*73);
    int bi, bj; pair_map(blockIdx.x, bi, bj);
    int h = blockIdx.y;
    WARP_IDX;
    for (int l = tid; l < 4096; l += 256) {
        int r = l >> 6, c = l & 63;
        Aq[r][c] = to_tf32(g_q[(size_t)(bi*64 + r)*DMM + h*64 + c]);
        Aw[r][c] = to_tf32(g_w[(size_t)(bi*64 + r)*DMM + h*64 + c]);
        Bw[c][r] = to_tf32(g_w[(size_t)(bj*64 + r)*DMM + h*64 + c]);
        Bk[c][r] = to_tf32(g_k[(size_t)(bj*64 + r)*DMM + h*64 + c]);
    }
    __syncthreads();
    size_t base = (size_t)h*TT*TT;

    {   // pass 1: Aqw = q.w (causal), QK = q.k
        float aqw[2][2][4] = {}, aqk[2][2][4] = {};
        mma_tile2(Aq, Bw, Bk, aqw, aqk, wr, wc, g, tig);
#pragma unroll
        for (int mi = 0; mi < 2; mi++)
#pragma unroll
        for (int ni = 0; ni < 2; ni++)
#pragma unroll
        for (int e = 0; e < 4; e++) {
            int r = bi*64 + ACC_ROW(mi, e), c = bj*64 + ACC_COL(ni, e);
            g_G[base + (size_t)r*TT + c] = (c <= r) ? aqw[mi][ni][e] : 0.f;
            g_S[base + (size_t)r*TT + c] = aqk[mi][ni][e];
        }
    }
    {   // pass 2: M = beta * w.w (strict), Mk = beta * w.k (strict)
        float am[2][2][4] = {}, amk[2][2][4] = {};
        mma_tile2(Aw, Bw, Bk, am, amk, wr, wc, g, tig);
#pragma unroll
        for (int mi = 0; mi < 2; mi++)
#pragma unroll
        for (int ni = 0; ni < 2; ni++)
#pragma unroll
        for (int e = 0; e < 4; e++) {
            int r = bi*64 + ACC_ROW(mi, e), c = bj*64 + ACC_COL(ni, e);
            float be = (r > c) ? g_beta[r*HH + h] : 0.f;
            g_M [base + (size_t)r*TT + c] = be * am [mi][ni][e];
            g_Mk[base + (size_t)r*TT + c] = be * amk[mi][ni][e];
        }
    }
}

// ---------------- invert unit-lower diagonal blocks of A = I + M ---------------
__global__ void inv_diag_kernel()
{
    int J = blockIdx.x, h = blockIdx.y;
    int c = threadIdx.x;
    __shared__ float L[64][65];
    __shared__ float X[64][65];
    const float* Mt = &g_M[(size_t)h*TT*TT + (size_t)(J*64)*TT + J*64];
    for (int r = 0; r < 64; r++) {
        L[r][c] = (r > c) ? Mt[(size_t)r*TT + c] : (r == c ? 1.f : 0.f);
        X[r][c] = (r == c) ? 1.f : 0.f;
    }
    __syncthreads();
    for (int r = 1; r < 64; r++) {
        if (c < r) {
            float a = 0.f;
            for (int s = c; s < r; s++) a += L[r][s] * X[s][c];
            X[r][c] = -a;
        }
        __syncthreads();
    }
    float* out = &g_invA[((size_t)h*NT + J)*4096];
    for (int r = 0; r < 64; r++) out[r*64 + c] = X[r][c];
}

// ---------------- per-(head, block-row): solve + S + softmax + PV --------------
__global__ __launch_bounds__(512) void row_kernel()
{
    int h = blockIdx.x;
    int I = NT - 1 - blockIdx.y;         // heavy rows launch first
    size_t base = (size_t)h*TT*TT;
    __shared__ float Gs[64][68];
    __shared__ float Ms[64][73];
    __shared__ float rmax[64], rinv[64], red[64][8];
    WARP_IDX16;

    // ---- blocked back-substitution across row I (J descending) ----
    for (int J = I; J >= 0; J--) {
        float acc[2][4];
        const float* Aqw = &g_G[base + (size_t)(I*64)*TT + J*64];
#pragma unroll
        for (int ni = 0; ni < 2; ni++)
#pragma unroll
        for (int e = 0; e < 4; e++)
            acc[ni][e] = Aqw[(size_t)A16_ROW(e)*TT + A16_COL(ni,e)];

        for (int S = J + 1; S <= I; S++) {
            __syncthreads();
            const float* Gp = &g_G[base + (size_t)(I*64)*TT + S*64];
            const float* Mp = &g_M[base + (size_t)(S*64)*TT + J*64];
            for (int l = tid; l < 4096; l += 512) {
                int r = l >> 6, c = l & 63;
                Gs[r][c] = to_tf32( Gp[(size_t)r*TT + c]);
                Ms[r][c] = to_tf32(-Mp[(size_t)r*TT + c]);
            }
            __syncthreads();
            mma_tile16(Gs, Ms, acc, wr, wc, g, tig);
        }
        __syncthreads();
        // multiply by invA_J
#pragma unroll
        for (int ni = 0; ni < 2; ni++)
#pragma unroll
        for (int e = 0; e < 4; e++)
            Gs[A16_ROW(e)][A16_COL(ni,e)] = to_tf32(acc[ni][e]);
        const float* Ip = &g_invA[((size_t)h*NT + J)*4096];
        for (int l = tid; l < 4096; l += 512)
            Ms[l >> 6][l & 63] = to_tf32(Ip[l]);
        __syncthreads();
        float fin[2][4] = {};
        mma_tile16(Gs, Ms, fin, wr, wc, g, tig);
        float* Gout = &g_G[base + (size_t)(I*64)*TT + J*64];
#pragma unroll
        for (int ni = 0; ni < 2; ni++)
#pragma unroll
        for (int e = 0; e < 4; e++)
            Gout[(size_t)A16_ROW(e)*TT + A16_COL(ni,e)] = fin[ni][e];
        __syncthreads();
    }

    // ---- S row: S[I,bj] = (QK - G Mk) * scale ----
    for (int bj = 0; bj <= I; bj++) {
        float acc[2][4];
        const float* QK = &g_S[base + (size_t)(I*64)*TT + bj*64];
#pragma unroll
        for (int ni = 0; ni < 2; ni++)
#pragma unroll
        for (int e = 0; e < 4; e++)
            acc[ni][e] = QK[(size_t)A16_ROW(e)*TT + A16_COL(ni,e)];

        for (int S = bj; S <= I; S++) {
            __syncthreads();
            const float* Gp = &g_G [base + (size_t)(I*64)*TT + S*64];
            const float* Mp = &g_Mk[base + (size_t)(S*64)*TT + bj*64];
            for (int l = tid; l < 4096; l += 512) {
                int r = l >> 6, c = l & 63;
                Gs[r][c] = to_tf32( Gp[(size_t)r*TT + c]);
                Ms[r][c] = to_tf32(-Mp[(size_t)r*TT + c]);
            }
            __syncthreads();
            mma_tile16(Gs, Ms, acc, wr, wc, g, tig);
        }
        float* Sp = &g_S[base + (size_t)(I*64)*TT + bj*64];
#pragma unroll
        for (int ni = 0; ni < 2; ni++)
#pragma unroll
        for (int e = 0; e < 4; e++) {
            int r = A16_ROW(e), c = A16_COL(ni,e);
            float v = acc[ni][e] * SCALE;
            if (bj == I && c > r) v = -1e30f;
            Sp[(size_t)r*TT + c] = v;
        }
        __syncthreads();
    }

    // ---- row softmax stats ----
    {
        int r = tid >> 3, part = tid & 7;
        const float* Srow = &g_S[base + (size_t)(I*64 + r)*TT];
        int ncols = (I + 1) * 64;
        float m = -1e30f;
        for (int c = part; c < ncols; c += 8) m = fmaxf(m, Srow[c]);
        red[r][part] = m;
        __syncthreads();
#pragma unroll
        for (int u = 0; u < 8; u++) m = fmaxf(m, red[r][u]);
        float s = 0.f;
        for (int c = part; c < ncols; c += 8) s += __expf(Srow[c] - m);
        __syncthreads();
        red[r][part] = s;
        __syncthreads();
        if (part == 0) {
            float t = 0.f;
#pragma unroll
            for (int u = 0; u < 8; u++) t += red[r][u];
            rmax[r] = m;
            rinv[r] = 1.f / t;
        }
        __syncthreads();
    }

    // ---- o[I] = P @ V ----
    float oacc[2][4] = {};
    for (int bj = 0; bj <= I; bj++) {
        __syncthreads();
        const float* Sp = &g_S[base + (size_t)(I*64)*TT + bj*64];
        for (int l = tid; l < 4096; l += 512) {
            int r = l >> 6, c = l & 63;
            Gs[r][c] = to_tf32(__expf(Sp[(size_t)r*TT + c] - rmax[r]) * rinv[r]);
            Ms[r][c] = to_tf32(g_v[(size_t)(bj*64 + r)*DMM + h*64 + c]);
        }
        __syncthreads();
        mma_tile16(Gs, Ms, oacc, wr, wc, g, tig);
    }
#pragma unroll
    for (int ni = 0; ni < 2; ni++)
#pragma unroll
    for (int e = 0; e < 4; e++)
        g_o[(size_t)(I*64 + A16_ROW(e))*DMM + h*64 + A16_COL(ni,e)] = oacc[ni][e];
}

// ---------------- launcher ------------------------------------------------------
extern "C" void kernel_launch(void* const* d_in, const int* in_sizes, int n_in,
                              void* d_out, int out_size)
{
    const float* x     = (const float*)d_in[0];
    const float* Wq    = (const float*)d_in[1];
    const float* Wk    = (const float*)d_in[2];
    const float* Wv    = (const float*)d_in[3];
    const float* Ww1   = (const float*)d_in[4];
    const float* Ww2   = (const float*)d_in[5];
    const float* convw = (const float*)d_in[6];
    const float* Wb    = (const float*)d_in[7];
    const float* Wo    = (const float*)d_in[8];

    float *xw1, *wpre, *o;
    cudaGetSymbolAddress((void**)&xw1,  g_xw1);
    cudaGetSymbolAddress((void**)&wpre, g_wpre);
    cudaGetSymbolAddress((void**)&o,    g_o);

    const int HD4_SMEM = (2*64*68 + 2*64*73) * 4;   // 72192 B
    static bool attr_set = false;
    if (!attr_set) {
        cudaFuncSetAttribute(headdot4_kernel,
                             cudaFuncAttributeMaxDynamicSharedMemorySize, HD4_SMEM);
        attr_set = true;
    }

    dim3 blk(256);

    // fused projections: q | k | v | xw1 | beta
    proj_kernel<<<dim3((NPROJ + 63)/64, 16), blk>>>(x, Wq, Wk, Wv, Ww1, Wb);

    // wpre = xw1 @ Ww2  (K=32)
    gemm_tc<<<dim3(16, 16), blk>>>(xw1, Ww2, wpre, DMM, RNK);

    // conv + silu + per-head l2 norm
    conv_norm_kernel<<<TT, 1024>>>(convw);

    // fused per-head products on lower tiles: M, Mk, Aqw, QK
    headdot4_kernel<<<dim3(NPAIR, HH), blk, HD4_SMEM>>>();

    // invert diagonal blocks of I + M
    inv_diag_kernel<<<dim3(NT, HH), 64>>>();

    // one CTA per (head, block-row): solve + S + softmax + PV
    row_kernel<<<dim3(HH, NT), 512>>>();

    // output projection
    gemm_tc<<<dim3(16, 16), blk>>>(o, Wo, (float*)d_out, DMM, DMM);
}

// round 7
// speedup vs baseline: 2.4403x; 1.4212x over previous
#include <cuda_runtime.h>
#include <math.h>
#include <stdint.h>

#define TT   1024
#define DMM  1024
#define HH   16
#define RNK  32
#define NT   16
#define NPAIR 136
#define SCALE 0.125f
#define NPROJ 3120     // 3*1024 + 32 + 16

// ---------------- scratch (device globals) ----------------------------------
__device__ float g_q   [TT*DMM];
__device__ float g_k   [TT*DMM];
__device__ float g_v   [TT*DMM];
__device__ float g_wpre[TT*DMM];
__device__ float g_w   [TT*DMM];
__device__ float g_xw1 [TT*RNK];
__device__ float g_beta[TT*HH];
__device__ float g_M [HH*TT*TT];
__device__ float g_Mk[HH*TT*TT];
__device__ float g_G [HH*TT*TT];   // Aqw -> G in place
__device__ float g_S [HH*TT*TT];   // QK -> scaled logits
__device__ float g_invA[HH*NT*64*64];
__device__ float g_o [TT*DMM];

// ---------------- tf32 helpers ------------------------------------------------
__device__ __forceinline__ float to_tf32(float x) {
    uint32_t u; asm("cvt.rna.tf32.f32 %0, %1;" : "=r"(u) : "f"(x));
    return __uint_as_float(u);
}
__device__ __forceinline__ float4 tf4(float4 v) {
    v.x = to_tf32(v.x); v.y = to_tf32(v.y); v.z = to_tf32(v.z); v.w = to_tf32(v.w);
    return v;
}
__device__ __forceinline__ float4 tf4n(float4 v) {
    v.x = to_tf32(-v.x); v.y = to_tf32(-v.y); v.z = to_tf32(-v.z); v.w = to_tf32(-v.w);
    return v;
}

__device__ __forceinline__ void mma8(float (&c)[4], const uint32_t (&a)[4],
                                     const uint32_t (&b)[2]) {
    asm volatile(
        "mma.sync.aligned.m16n8k8.row.col.f32.tf32.tf32.f32 "
        "{%0,%1,%2,%3},{%4,%5,%6,%7},{%8,%9},{%0,%1,%2,%3};"
        : "+f"(c[0]), "+f"(c[1]), "+f"(c[2]), "+f"(c[3])
        : "r"(a[0]), "r"(a[1]), "r"(a[2]), "r"(a[3]), "r"(b[0]), "r"(b[1]));
}

// ---- 8-warp (256 thread) layout: warp tile 32x16 ------------------------------
#define WARP_IDX                                   \
    int tid = threadIdx.x;                         \
    int lane = tid & 31, wid = tid >> 5;           \
    int wr = (wid >> 2) * 32, wc = (wid & 3) * 16; \
    int g = lane >> 2, tig = lane & 3;

#define ACC_ROW(mi,e) (wr + (mi)*16 + g + ((e)>>1)*8)
#define ACC_COL(ni,e) (wc + (ni)*8 + tig*2 + ((e)&1))

template<int PA, int PB>
__device__ __forceinline__ void mma_tile(const float (*As)[PA], const float (*Bs)[PB],
                                         float (&acc)[2][2][4],
                                         int wr, int wc, int g, int tig)
{
#pragma unroll
    for (int kb = 0; kb < 64; kb += 8) {
        uint32_t a[2][4], b[2][2];
#pragma unroll
        for (int mi = 0; mi < 2; mi++) {
            int r0 = wr + mi*16 + g;
            a[mi][0] = __float_as_uint(As[r0    ][kb + tig    ]);
            a[mi][1] = __float_as_uint(As[r0 + 8][kb + tig    ]);
            a[mi][2] = __float_as_uint(As[r0    ][kb + tig + 4]);
            a[mi][3] = __float_as_uint(As[r0 + 8][kb + tig + 4]);
        }
#pragma unroll
        for (int ni = 0; ni < 2; ni++) {
            int c0 = wc + ni*8 + g;
            b[ni][0] = __float_as_uint(Bs[kb + tig    ][c0]);
            b[ni][1] = __float_as_uint(Bs[kb + tig + 4][c0]);
        }
#pragma unroll
        for (int mi = 0; mi < 2; mi++)
#pragma unroll
            for (int ni = 0; ni < 2; ni++)
                mma8(acc[mi][ni], a[mi], b[ni]);
    }
}

// dual-B: share A fragments across two products
template<int PA, int PB>
__device__ __forceinline__ void mma_tile2(const float (*As)[PA],
        const float (*B1)[PB], const float (*B2)[PB],
        float (&c1)[2][2][4], float (&c2)[2][2][4],
        int wr, int wc, int g, int tig)
{
#pragma unroll
    for (int kb = 0; kb < 64; kb += 8) {
        uint32_t a[2][4], b1[2][2], b2[2][2];
#pragma unroll
        for (int mi = 0; mi < 2; mi++) {
            int r0 = wr + mi*16 + g;
            a[mi][0] = __float_as_uint(As[r0    ][kb + tig    ]);
            a[mi][1] = __float_as_uint(As[r0 + 8][kb + tig    ]);
            a[mi][2] = __float_as_uint(As[r0    ][kb + tig + 4]);
            a[mi][3] = __float_as_uint(As[r0 + 8][kb + tig + 4]);
        }
#pragma unroll
        for (int ni = 0; ni < 2; ni++) {
            int c0 = wc + ni*8 + g;
            b1[ni][0] = __float_as_uint(B1[kb + tig    ][c0]);
            b1[ni][1] = __float_as_uint(B1[kb + tig + 4][c0]);
            b2[ni][0] = __float_as_uint(B2[kb + tig    ][c0]);
            b2[ni][1] = __float_as_uint(B2[kb + tig + 4][c0]);
        }
#pragma unroll
        for (int mi = 0; mi < 2; mi++)
#pragma unroll
        for (int ni = 0; ni < 2; ni++) {
            mma8(c1[mi][ni], a[mi], b1[ni]);
            mma8(c2[mi][ni], a[mi], b2[ni]);
        }
    }
}

// ---- 16-warp (512 thread) layout: warp tile 16x16 -----------------------------
#define WARP_IDX16                                 \
    int tid = threadIdx.x;                         \
    int lane = tid & 31, wid = tid >> 5;           \
    int wr = (wid >> 2) * 16, wc = (wid & 3) * 16; \
    int g = lane >> 2, tig = lane & 3;

#define A16_ROW(e)    (wr + g + ((e)>>1)*8)
#define A16_COL(ni,e) (wc + (ni)*8 + tig*2 + ((e)&1))

template<int PA, int PB>
__device__ __forceinline__ void mma_tile16(const float (*As)[PA], const float (*Bs)[PB],
                                           float (&acc)[2][4],
                                           int wr, int wc, int g, int tig)
{
#pragma unroll
    for (int kb = 0; kb < 64; kb += 8) {
        uint32_t a[4], b[2][2];
        a[0] = __float_as_uint(As[wr + g    ][kb + tig    ]);
        a[1] = __float_as_uint(As[wr + g + 8][kb + tig    ]);
        a[2] = __float_as_uint(As[wr + g    ][kb + tig + 4]);
        a[3] = __float_as_uint(As[wr + g + 8][kb + tig + 4]);
#pragma unroll
        for (int ni = 0; ni < 2; ni++) {
            int c0 = wc + ni*8 + g;
            b[ni][0] = __float_as_uint(Bs[kb + tig    ][c0]);
            b[ni][1] = __float_as_uint(Bs[kb + tig + 4][c0]);
        }
        mma8(acc[0], a, b[0]);
        mma8(acc[1], a, b[1]);
    }
}

__device__ __forceinline__ void pair_map(int p, int& bi, int& bj) {
    int b = 0;
    while ((b+1)*(b+2)/2 <= p) b++;
    bi = b; bj = p - b*(b+1)/2;
}

// ---------------- fused projection: x @ [Wq|Wk|Wv|Ww1|Wb] ----------------------
__global__ __launch_bounds__(256) void proj_kernel(
    const float* __restrict__ x,  const float* __restrict__ Wq,
    const float* __restrict__ Wk, const float* __restrict__ Wv,
    const float* __restrict__ Ww1,const float* __restrict__ Wb)
{
    __shared__ float As[64][68];
    __shared__ float Bs[64][76];
    WARP_IDX;
    int bm = blockIdx.y * 64, bn = blockIdx.x * 64;
    float acc[2][2][4] = {};
    for (int kt = 0; kt < DMM; kt += 64) {
        __syncthreads();
        for (int l = tid*4; l < 4096; l += 1024) {
            int r = l >> 6, c = l & 63;
            float4 v = *(const float4*)&x[(size_t)(bm + r)*DMM + kt + c];
            *(float4*)&As[r][c] = tf4(v);
        }
        for (int l = tid*4; l < 4096; l += 1024) {
            int r = l >> 6, c = l & 63;
            int kk = kt + r;
            float4 v;
            if (bn < 3072) {
                const float* W = (bn < 1024) ? Wq : (bn < 2048) ? Wk : Wv;
                v = *(const float4*)&W[(size_t)kk*DMM + ((bn + c) & 1023)];
            } else {
                float t[4];
#pragma unroll
                for (int u = 0; u < 4; u++) {
                    int nn = bn + c + u;
                    t[u] = (nn < 3104) ? Ww1[kk*RNK + (nn - 3072)]
                         : (nn < NPROJ) ? Wb[kk*HH + (nn - 3104)] : 0.f;
                }
                v = make_float4(t[0], t[1], t[2], t[3]);
            }
            *(float4*)&Bs[r][c] = tf4(v);
        }
        __syncthreads();
        mma_tile(As, Bs, acc, wr, wc, g, tig);
    }
#pragma unroll
    for (int mi = 0; mi < 2; mi++)
#pragma unroll
    for (int ni = 0; ni < 2; ni++)
#pragma unroll
    for (int e = 0; e < 4; e++) {
        int row = bm + ACC_ROW(mi, e);
        int col = bn + ACC_COL(ni, e);
        float v = acc[mi][ni][e];
        if      (col < 1024)  g_q[(size_t)row*DMM + col] = v;
        else if (col < 2048)  g_k[(size_t)row*DMM + (col - 1024)] = v;
        else if (col < 3072)  g_v[(size_t)row*DMM + (col - 2048)] = v;
        else if (col < 3104)  g_xw1[row*RNK + (col - 3072)] = v;
        else if (col < NPROJ) g_beta[row*HH + (col - 3104)] = 2.f/(1.f + expf(-v));
    }
}

// ---------------- generic C = A@B (M,N mult of 64, K mult of 4) ----------------
__global__ __launch_bounds__(256) void gemm_tc(
    const float* __restrict__ A, const float* __restrict__ B,
    float* __restrict__ C, int N, int K)
{
    __shared__ float As[64][68];
    __shared__ float Bs[64][76];
    WARP_IDX;
    int bm = blockIdx.y * 64, bn = blockIdx.x * 64;
    float acc[2][2][4] = {};
    for (int kt = 0; kt < K; kt += 64) {
        __syncthreads();
        for (int l = tid*4; l < 4096; l += 1024) {
            int r = l >> 6, c = l & 63;
            float4 v = (kt + c < K) ? *(const float4*)&A[(size_t)(bm + r)*K + kt + c]
                                    : make_float4(0.f,0.f,0.f,0.f);
            *(float4*)&As[r][c] = tf4(v);
        }
        for (int l = tid*4; l < 4096; l += 1024) {
            int r = l >> 6, c = l & 63;
            float4 v = (kt + r < K) ? *(const float4*)&B[(size_t)(kt + r)*N + bn + c]
                                    : make_float4(0.f,0.f,0.f,0.f);
            *(float4*)&Bs[r][c] = tf4(v);
        }
        __syncthreads();
        mma_tile(As, Bs, acc, wr, wc, g, tig);
    }
#pragma unroll
    for (int mi = 0; mi < 2; mi++)
#pragma unroll
    for (int ni = 0; ni < 2; ni++)
#pragma unroll
    for (int e = 0; e < 4; e++)
        C[(size_t)(bm + ACC_ROW(mi, e))*N + bn + ACC_COL(ni, e)] = acc[mi][ni][e];
}

// ---------------- causal depthwise conv(3) + SiLU + per-head L2 norm -----------
__global__ void conv_norm_kernel(const float* __restrict__ conv_w)
{
    int t = blockIdx.x;
    int c = threadIdx.x;
    float x0  = g_wpre[t*DMM + c];
    float xm1 = (t >= 1) ? g_wpre[(t-1)*DMM + c] : 0.f;
    float xm2 = (t >= 2) ? g_wpre[(t-2)*DMM + c] : 0.f;
    float y = conv_w[c*3+0]*xm2 + conv_w[c*3+1]*xm1 + conv_w[c*3+2]*x0;
    y = y / (1.f + expf(-y));
    float y2 = y * y;
#pragma unroll
    for (int o = 16; o; o >>= 1) y2 += __shfl_xor_sync(0xffffffffu, y2, o);
    __shared__ float wsum[32];
    if ((c & 31) == 0) wsum[c >> 5] = y2;
    __syncthreads();
    int h = c >> 6;
    float ss = wsum[2*h] + wsum[2*h+1];
    g_w[t*DMM + c] = y * rsqrtf(ss + 1e-6f);
}

// ---------------- fused headdot: M, Mk, Aqw, QK per (pair, head) ---------------
__global__ __launch_bounds__(256) void headdot4_kernel()
{
    extern __shared__ float dsm[];
    float (*Aq)[68] = (float(*)[68])dsm;                     // [i][d]
    float (*Aw)[68] = (float(*)[68])(dsm + 64*68);
    float (*Bw)[73] = (float(*)[73])(dsm + 2*64*68);         // [d][j]
    float (*Bk)[73] = (float(*)[73])(dsm + 2*64*68 + 64*73);
    int bi, bj; pair_map(blockIdx.x, bi, bj);
    int h = blockIdx.y;
    WARP_IDX;
    for (int l = tid*4; l < 4096; l += 1024) {
        int r = l >> 6, c = l & 63;
        float4 q4 = *(const float4*)&g_q[(size_t)(bi*64 + r)*DMM + h*64 + c];
        float4 wi = *(const float4*)&g_w[(size_t)(bi*64 + r)*DMM + h*64 + c];
        float4 wj = *(const float4*)&g_w[(size_t)(bj*64 + r)*DMM + h*64 + c];
        float4 kj = *(const float4*)&g_k[(size_t)(bj*64 + r)*DMM + h*64 + c];
        *(float4*)&Aq[r][c] = tf4(q4);
        *(float4*)&Aw[r][c] = tf4(wi);
        Bw[c  ][r] = to_tf32(wj.x); Bw[c+1][r] = to_tf32(wj.y);
        Bw[c+2][r] = to_tf32(wj.z); Bw[c+3][r] = to_tf32(wj.w);
        Bk[c  ][r] = to_tf32(kj.x); Bk[c+1][r] = to_tf32(kj.y);
        Bk[c+2][r] = to_tf32(kj.z); Bk[c+3][r] = to_tf32(kj.w);
    }
    __syncthreads();
    size_t base = (size_t)h*TT*TT;

    {   // pass 1: Aqw = q.w (causal), QK = q.k
        float aqw[2][2][4] = {}, aqk[2][2][4] = {};
        mma_tile2(Aq, Bw, Bk, aqw, aqk, wr, wc, g, tig);
#pragma unroll
        for (int mi = 0; mi < 2; mi++)
#pragma unroll
        for (int ni = 0; ni < 2; ni++)
#pragma unroll
        for (int e = 0; e < 4; e += 2) {
            int r = bi*64 + ACC_ROW(mi, e), c = bj*64 + ACC_COL(ni, e);
            float2 gv, sv;
            gv.x = (c     <= r) ? aqw[mi][ni][e]   : 0.f;
            gv.y = (c + 1 <= r) ? aqw[mi][ni][e+1] : 0.f;
            sv.x = aqk[mi][ni][e]; sv.y = aqk[mi][ni][e+1];
            *(float2*)&g_G[base + (size_t)r*TT + c] = gv;
            *(float2*)&g_S[base + (size_t)r*TT + c] = sv;
        }
    }
    {   // pass 2: M = beta * w.w (strict), Mk = beta * w.k (strict)
        float am[2][2][4] = {}, amk[2][2][4] = {};
        mma_tile2(Aw, Bw, Bk, am, amk, wr, wc, g, tig);
#pragma unroll
        for (int mi = 0; mi < 2; mi++)
#pragma unroll
        for (int ni = 0; ni < 2; ni++)
#pragma unroll
        for (int e = 0; e < 4; e += 2) {
            int r = bi*64 + ACC_ROW(mi, e), c = bj*64 + ACC_COL(ni, e);
            float beta = g_beta[r*HH + h];
            float2 mv, kv;
            mv.x = (r > c    ) ? beta * am [mi][ni][e]   : 0.f;
            mv.y = (r > c + 1) ? beta * am [mi][ni][e+1] : 0.f;
            kv.x = (r > c    ) ? beta * amk[mi][ni][e]   : 0.f;
            kv.y = (r > c + 1) ? beta * amk[mi][ni][e+1] : 0.f;
            *(float2*)&g_M [base + (size_t)r*TT + c] = mv;
            *(float2*)&g_Mk[base + (size_t)r*TT + c] = kv;
        }
    }
}

// ---------------- invert unit-lower diagonal blocks of A = I + M ---------------
__global__ void inv_diag_kernel()
{
    int J = blockIdx.x, h = blockIdx.y;
    int c = threadIdx.x;
    __shared__ float L[64][65];
    __shared__ float X[64][65];
    const float* Mt = &g_M[(size_t)h*TT*TT + (size_t)(J*64)*TT + J*64];
    for (int r = 0; r < 64; r++) {
        L[r][c] = (r > c) ? Mt[(size_t)r*TT + c] : (r == c ? 1.f : 0.f);
        X[r][c] = (r == c) ? 1.f : 0.f;
    }
    __syncthreads();
    for (int r = 1; r < 64; r++) {
        if (c < r) {
            float a = 0.f;
            for (int s = c; s < r; s++) a += L[r][s] * X[s][c];
            X[r][c] = -a;
        }
        __syncthreads();
    }
    float* out = &g_invA[((size_t)h*NT + J)*4096];
    for (int r = 0; r < 64; r++) out[r*64 + c] = X[r][c];
}

// ---------------- per-(head, block-row) back-substitution only -----------------
__global__ __launch_bounds__(512) void solve_kernel()
{
    int h = blockIdx.x;
    int I = NT - 1 - blockIdx.y;         // heavy rows launch first
    size_t base = (size_t)h*TT*TT;
    __shared__ float Gs[64][68];
    __shared__ float Ms[64][76];
    WARP_IDX16;

    for (int J = I; J >= 0; J--) {
        float acc[2][4];
        const float* Aqw = &g_G[base + (size_t)(I*64)*TT + J*64];
#pragma unroll
        for (int ni = 0; ni < 2; ni++)
#pragma unroll
        for (int e = 0; e < 4; e++)
            acc[ni][e] = Aqw[(size_t)A16_ROW(e)*TT + A16_COL(ni,e)];

        for (int S = J + 1; S <= I; S++) {
            __syncthreads();
            const float* Gp = &g_G[base + (size_t)(I*64)*TT + S*64];
            const float* Mp = &g_M[base + (size_t)(S*64)*TT + J*64];
            for (int l = tid*4; l < 4096; l += 2048) {
                int r = l >> 6, c = l & 63;
                *(float4*)&Gs[r][c] = tf4 (*(const float4*)&Gp[(size_t)r*TT + c]);
                *(float4*)&Ms[r][c] = tf4n(*(const float4*)&Mp[(size_t)r*TT + c]);
            }
            __syncthreads();
            mma_tile16(Gs, Ms, acc, wr, wc, g, tig);
        }
        __syncthreads();
        // multiply by invA_J
#pragma unroll
        for (int ni = 0; ni < 2; ni++)
#pragma unroll
        for (int e = 0; e < 4; e++)
            Gs[A16_ROW(e)][A16_COL(ni,e)] = to_tf32(acc[ni][e]);
        const float* Ip = &g_invA[((size_t)h*NT + J)*4096];
        for (int l = tid*4; l < 4096; l += 2048)
            *(float4*)&Ms[l >> 6][l & 63] = tf4(*(const float4*)&Ip[l]);
        __syncthreads();
        float fin[2][4] = {};
        mma_tile16(Gs, Ms, fin, wr, wc, g, tig);
        float* Gout = &g_G[base + (size_t)(I*64)*TT + J*64];
#pragma unroll
        for (int ni = 0; ni < 2; ni++)
#pragma unroll
        for (int e = 0; e < 4; e += 2) {
            float2 v = make_float2(fin[ni][e], fin[ni][e+1]);
            *(float2*)&Gout[(size_t)A16_ROW(e)*TT + A16_COL(ni,e)] = v;
        }
        __syncthreads();
    }
}

// ---------------- pair-parallel S = (QK - G @ Mk) * scale ----------------------
__global__ __launch_bounds__(256) void s_kernel()
{
    // work-descending pair enumeration: long diagonals first
    int rem = blockIdx.x, kd = NT - 1;
    while (rem >= NT - kd) { rem -= NT - kd; kd--; }
    int bj = rem, bi = rem + kd;
    int h = blockIdx.y;
    size_t base = (size_t)h*TT*TT;
    __shared__ float Gs[64][68];
    __shared__ float Ms[64][76];
    WARP_IDX;
    float acc[2][2][4];
    const float* QK = &g_S[base + (size_t)(bi*64)*TT + bj*64];
#pragma unroll
    for (int mi = 0; mi < 2; mi++)
#pragma unroll
    for (int ni = 0; ni < 2; ni++)
#pragma unroll
    for (int e = 0; e < 4; e++)
        acc[mi][ni][e] = QK[(size_t)ACC_ROW(mi,e)*TT + ACC_COL(ni,e)];

    for (int S = bj; S <= bi; S++) {
        __syncthreads();
        const float* Gp = &g_G [base + (size_t)(bi*64)*TT + S*64];
        const float* Mp = &g_Mk[base + (size_t)(S*64)*TT + bj*64];
        for (int l = tid*4; l < 4096; l += 1024) {
            int r = l >> 6, c = l & 63;
            *(float4*)&Gs[r][c] = tf4 (*(const float4*)&Gp[(size_t)r*TT + c]);
            *(float4*)&Ms[r][c] = tf4n(*(const float4*)&Mp[(size_t)r*TT + c]);
        }
        __syncthreads();
        mma_tile(Gs, Ms, acc, wr, wc, g, tig);
    }
    float* Sp = &g_S[base + (size_t)(bi*64)*TT + bj*64];
#pragma unroll
    for (int mi = 0; mi < 2; mi++)
#pragma unroll
    for (int ni = 0; ni < 2; ni++)
#pragma unroll
    for (int e = 0; e < 4; e += 2) {
        int r = ACC_ROW(mi,e), c = ACC_COL(ni,e);
        float2 v;
        v.x = (bi == bj && c     > r) ? -1e30f : acc[mi][ni][e]   * SCALE;
        v.y = (bi == bj && c + 1 > r) ? -1e30f : acc[mi][ni][e+1] * SCALE;
        *(float2*)&Sp[(size_t)r*TT + c] = v;
    }
}

// ---------------- per-(head, block-row): softmax + P @ V -----------------------
__global__ __launch_bounds__(256) void pv_kernel()
{
    int h = blockIdx.x;
    int I = NT - 1 - blockIdx.y;
    size_t base = (size_t)h*TT*TT;
    __shared__ float Gs[64][68];
    __shared__ float Ms[64][76];
    __shared__ float rmax[64], rinv[64], red[64][4];
    WARP_IDX;

    // ---- row softmax stats ----
    {
        int r = tid >> 2, part = tid & 3;
        const float* Srow = &g_S[base + (size_t)(I*64 + r)*TT];
        int ncols = (I + 1) * 64;
        float m = -1e30f;
        for (int c = part*4; c < ncols; c += 16) {
            float4 v = *(const float4*)&Srow[c];
            m = fmaxf(m, fmaxf(fmaxf(v.x, v.y), fmaxf(v.z, v.w)));
        }
        red[r][part] = m;
        __syncthreads();
        m = fmaxf(fmaxf(red[r][0], red[r][1]), fmaxf(red[r][2], red[r][3]));
        float s = 0.f;
        for (int c = part*4; c < ncols; c += 16) {
            float4 v = *(const float4*)&Srow[c];
            s += __expf(v.x - m) + __expf(v.y - m) + __expf(v.z - m) + __expf(v.w - m);
        }
        __syncthreads();
        red[r][part] = s;
        __syncthreads();
        if (part == 0) {
            rmax[r] = m;
            rinv[r] = 1.f / (red[r][0] + red[r][1] + red[r][2] + red[r][3]);
        }
        __syncthreads();
    }

    // ---- o[I] = P @ V ----
    float oacc[2][2][4] = {};
    for (int bj = 0; bj <= I; bj++) {
        __syncthreads();
        const float* Sp = &g_S[base + (size_t)(I*64)*TT + bj*64];
        for (int l = tid*4; l < 4096; l += 1024) {
            int r = l >> 6, c = l & 63;
            float4 v = *(const float4*)&Sp[(size_t)r*TT + c];
            float mr = rmax[r], iv = rinv[r];
            v.x = __expf(v.x - mr) * iv; v.y = __expf(v.y - mr) * iv;
            v.z = __expf(v.z - mr) * iv; v.w = __expf(v.w - mr) * iv;
            *(float4*)&Gs[r][c] = tf4(v);
            *(float4*)&Ms[r][c] = tf4(*(const float4*)&g_v[(size_t)(bj*64 + r)*DMM + h*64 + c]);
        }
        __syncthreads();
        mma_tile(Gs, Ms, oacc, wr, wc, g, tig);
    }
#pragma unroll
    for (int mi = 0; mi < 2; mi++)
#pragma unroll
    for (int ni = 0; ni < 2; ni++)
#pragma unroll
    for (int e = 0; e < 4; e += 2) {
        float2 v = make_float2(oacc[mi][ni][e], oacc[mi][ni][e+1]);
        *(float2*)&g_o[(size_t)(I*64 + ACC_ROW(mi,e))*DMM + h*64 + ACC_COL(ni,e)] = v;
    }
}

// ---------------- launcher ------------------------------------------------------
extern "C" void kernel_launch(void* const* d_in, const int* in_sizes, int n_in,
                              void* d_out, int out_size)
{
    const float* x     = (const float*)d_in[0];
    const float* Wq    = (const float*)d_in[1];
    const float* Wk    = (const float*)d_in[2];
    const float* Wv    = (const float*)d_in[3];
    const float* Ww1   = (const float*)d_in[4];
    const float* Ww2   = (const float*)d_in[5];
    const float* convw = (const float*)d_in[6];
    const float* Wb    = (const float*)d_in[7];
    const float* Wo    = (const float*)d_in[8];

    float *xw1, *wpre, *o;
    cudaGetSymbolAddress((void**)&xw1,  g_xw1);
    cudaGetSymbolAddress((void**)&wpre, g_wpre);
    cudaGetSymbolAddress((void**)&o,    g_o);

    const int HD4_SMEM = (2*64*68 + 2*64*73) * 4;   // 72192 B
    static bool attr_set = false;
    if (!attr_set) {
        cudaFuncSetAttribute(headdot4_kernel,
                             cudaFuncAttributeMaxDynamicSharedMemorySize, HD4_SMEM);
        attr_set = true;
    }

    dim3 blk(256);

    // fused projections: q | k | v | xw1 | beta
    proj_kernel<<<dim3((NPROJ + 63)/64, 16), blk>>>(x, Wq, Wk, Wv, Ww1, Wb);

    // wpre = xw1 @ Ww2  (K=32)
    gemm_tc<<<dim3(16, 16), blk>>>(xw1, Ww2, wpre, DMM, RNK);

    // conv + silu + per-head l2 norm
    conv_norm_kernel<<<TT, 1024>>>(convw);

    // fused per-head products on lower tiles: M, Mk, Aqw, QK
    headdot4_kernel<<<dim3(NPAIR, HH), blk, HD4_SMEM>>>();

    // invert diagonal blocks of I + M
    inv_diag_kernel<<<dim3(NT, HH), 64>>>();

    // per-(head, block-row) back-substitution (serial part only)
    solve_kernel<<<dim3(HH, NT), 512>>>();

    // pair-parallel S = (QK - G Mk)*scale, then softmax+PV per row
    s_kernel<<<dim3(NPAIR, HH), blk>>>();
    pv_kernel<<<dim3(HH, NT), blk>>>();

    // output projection
    gemm_tc<<<dim3(16, 16), blk>>>(o, Wo, (float*)d_out, DMM, DMM);
}

// round 8
// speedup vs baseline: 2.9507x; 1.2091x over previous
#include <cuda_runtime.h>
#include <math.h>
#include <stdint.h>

#define TT   1024
#define DMM  1024
#define HH   16
#define RNK  32
#define NT   16
#define NPAIR 136
#define SCALE 0.125f
#define NPROJ 3120     // 3*1024 + 32 + 16

#define PA_  68        // pad for A-tiles / row-major-B tiles (4*g+tig banks)
#define PB_  72        // pad for col-major-B tiles (8*tig+g banks)
#define ASZ  (64*PA_)
#define BSZ  (64*PB_)

// ---------------- scratch (device globals) ----------------------------------
__device__ float g_q   [TT*DMM];
__device__ float g_k   [TT*DMM];
__device__ float g_v   [TT*DMM];
__device__ float g_wpre[TT*DMM];
__device__ float g_w   [TT*DMM];
__device__ float g_xw1 [TT*RNK];
__device__ float g_beta[TT*HH];
__device__ float g_M [HH*TT*TT];
__device__ float g_Mk[HH*TT*TT];
__device__ float g_G [HH*TT*TT];   // Aqw -> G in place
__device__ float g_S [HH*TT*TT];   // QK -> scaled logits
__device__ float g_invA[HH*NT*64*64];
__device__ float g_o [TT*DMM];

// ---------------- tf32 helpers ------------------------------------------------
__device__ __forceinline__ float to_tf32(float x) {
    uint32_t u; asm("cvt.rna.tf32.f32 %0, %1;" : "=r"(u) : "f"(x));
    return __uint_as_float(u);
}
__device__ __forceinline__ float4 tf4(float4 v) {
    v.x = to_tf32(v.x); v.y = to_tf32(v.y); v.z = to_tf32(v.z); v.w = to_tf32(v.w);
    return v;
}
__device__ __forceinline__ float4 tf4n(float4 v) {
    v.x = to_tf32(-v.x); v.y = to_tf32(-v.y); v.z = to_tf32(-v.z); v.w = to_tf32(-v.w);
    return v;
}

__device__ __forceinline__ void mma8(float (&c)[4], const uint32_t (&a)[4],
                                     const uint32_t (&b)[2]) {
    asm volatile(
        "mma.sync.aligned.m16n8k8.row.col.f32.tf32.tf32.f32 "
        "{%0,%1,%2,%3},{%4,%5,%6,%7},{%8,%9},{%0,%1,%2,%3};"
        : "+f"(c[0]), "+f"(c[1]), "+f"(c[2]), "+f"(c[3])
        : "r"(a[0]), "r"(a[1]), "r"(a[2]), "r"(a[3]), "r"(b[0]), "r"(b[1]));
}

// ---- 8-warp (256 thread) layout: warp tile 32x16 ------------------------------
#define WARP_IDX                                   \
    int tid = threadIdx.x;                         \
    int lane = tid & 31, wid = tid >> 5;           \
    int wr = (wid >> 2) * 32, wc = (wid & 3) * 16; \
    int g = lane >> 2, tig = lane & 3;

#define ACC_ROW(mi,e) (wr + (mi)*16 + g + ((e)>>1)*8)
#define ACC_COL(ni,e) (wc + (ni)*8 + tig*2 + ((e)&1))

// col-major-B tile mma (B in [k][n] layout, pad PB_)
__device__ __forceinline__ void mma_tile8(const float (*As)[PA_], const float (*Bs)[PB_],
                                          float (&acc)[2][2][4],
                                          int wr, int wc, int g, int tig)
{
#pragma unroll
    for (int kb = 0; kb < 64; kb += 8) {
        uint32_t a[2][4], b[2][2];
#pragma unroll
        for (int mi = 0; mi < 2; mi++) {
            int r0 = wr + mi*16 + g;
            a[mi][0] = __float_as_uint(As[r0    ][kb + tig    ]);
            a[mi][1] = __float_as_uint(As[r0 + 8][kb + tig    ]);
            a[mi][2] = __float_as_uint(As[r0    ][kb + tig + 4]);
            a[mi][3] = __float_as_uint(As[r0 + 8][kb + tig + 4]);
        }
#pragma unroll
        for (int ni = 0; ni < 2; ni++) {
            int c0 = wc + ni*8 + g;
            b[ni][0] = __float_as_uint(Bs[kb + tig    ][c0]);
            b[ni][1] = __float_as_uint(Bs[kb + tig + 4][c0]);
        }
#pragma unroll
        for (int mi = 0; mi < 2; mi++)
#pragma unroll
            for (int ni = 0; ni < 2; ni++)
                mma8(acc[mi][ni], a[mi], b[ni]);
    }
}

// dual row-major-B tile mma (B in [n][k] layout, pad PA_) — shares A fragments
__device__ __forceinline__ void mma_tile2r(const float (*As)[PA_],
        const float (*B1)[PA_], const float (*B2)[PA_],
        float (&c1)[2][2][4], float (&c2)[2][2][4],
        int wr, int wc, int g, int tig)
{
#pragma unroll
    for (int kb = 0; kb < 64; kb += 8) {
        uint32_t a[2][4], b1[2][2], b2[2][2];
#pragma unroll
        for (int mi = 0; mi < 2; mi++) {
            int r0 = wr + mi*16 + g;
            a[mi][0] = __float_as_uint(As[r0    ][kb + tig    ]);
            a[mi][1] = __float_as_uint(As[r0 + 8][kb + tig    ]);
            a[mi][2] = __float_as_uint(As[r0    ][kb + tig + 4]);
            a[mi][3] = __float_as_uint(As[r0 + 8][kb + tig + 4]);
        }
#pragma unroll
        for (int ni = 0; ni < 2; ni++) {
            int c0 = wc + ni*8 + g;
            b1[ni][0] = __float_as_uint(B1[c0][kb + tig    ]);
            b1[ni][1] = __float_as_uint(B1[c0][kb + tig + 4]);
            b2[ni][0] = __float_as_uint(B2[c0][kb + tig    ]);
            b2[ni][1] = __float_as_uint(B2[c0][kb + tig + 4]);
        }
#pragma unroll
        for (int mi = 0; mi < 2; mi++)
#pragma unroll
        for (int ni = 0; ni < 2; ni++) {
            mma8(c1[mi][ni], a[mi], b1[ni]);
            mma8(c2[mi][ni], a[mi], b2[ni]);
        }
    }
}

// ---- 16-warp (512 thread) layout: warp tile 16x16 -----------------------------
#define WARP_IDX16                                 \
    int tid = threadIdx.x;                         \
    int lane = tid & 31, wid = tid >> 5;           \
    int wr = (wid >> 2) * 16, wc = (wid & 3) * 16; \
    int g = lane >> 2, tig = lane & 3;

#define A16_ROW(e)    (wr + g + ((e)>>1)*8)
#define A16_COL(ni,e) (wc + (ni)*8 + tig*2 + ((e)&1))

__device__ __forceinline__ void mma_tile16(const float (*As)[PA_], const float (*Bs)[PB_],
                                           float (&acc)[2][4],
                                           int wr, int wc, int g, int tig)
{
#pragma unroll
    for (int kb = 0; kb < 64; kb += 8) {
        uint32_t a[4], b[2][2];
        a[0] = __float_as_uint(As[wr + g    ][kb + tig    ]);
        a[1] = __float_as_uint(As[wr + g + 8][kb + tig    ]);
        a[2] = __float_as_uint(As[wr + g    ][kb + tig + 4]);
        a[3] = __float_as_uint(As[wr + g + 8][kb + tig + 4]);
#pragma unroll
        for (int ni = 0; ni < 2; ni++) {
            int c0 = wc + ni*8 + g;
            b[ni][0] = __float_as_uint(Bs[kb + tig    ][c0]);
            b[ni][1] = __float_as_uint(Bs[kb + tig + 4][c0]);
        }
        mma8(acc[0], a, b[0]);
        mma8(acc[1], a, b[1]);
    }
}

__device__ __forceinline__ void pair_map(int p, int& bi, int& bj) {
    int b = 0;
    while ((b+1)*(b+2)/2 <= p) b++;
    bi = b; bj = p - b*(b+1)/2;
}

// ---------------- staging helpers (256 / 512 thread) ---------------------------
__device__ __forceinline__ void ldg4_256(const float* __restrict__ p, int ld, float4 (&v)[4]) {
    int t = threadIdx.x * 4;
#pragma unroll
    for (int u = 0; u < 4; u++) {
        int l = t + u*1024;
        v[u] = *(const float4*)(p + (size_t)(l >> 6)*ld + (l & 63));
    }
}
template<int P>
__device__ __forceinline__ void sts4_256(float (*Ts)[P], const float4 (&v)[4]) {
    int t = threadIdx.x * 4;
#pragma unroll
    for (int u = 0; u < 4; u++) {
        int l = t + u*1024;
        *(float4*)&Ts[l >> 6][l & 63] = tf4(v[u]);
    }
}
template<int P>
__device__ __forceinline__ void sts4_256n(float (*Ts)[P], const float4 (&v)[4]) {
    int t = threadIdx.x * 4;
#pragma unroll
    for (int u = 0; u < 4; u++) {
        int l = t + u*1024;
        *(float4*)&Ts[l >> 6][l & 63] = tf4n(v[u]);
    }
}
__device__ __forceinline__ void ldg4_512(const float* __restrict__ p, int ld, float4 (&v)[2]) {
    int t = threadIdx.x * 4;
#pragma unroll
    for (int u = 0; u < 2; u++) {
        int l = t + u*2048;
        v[u] = *(const float4*)(p + (size_t)(l >> 6)*ld + (l & 63));
    }
}
template<int P>
__device__ __forceinline__ void sts4_512(float (*Ts)[P], const float4 (&v)[2]) {
    int t = threadIdx.x * 4;
#pragma unroll
    for (int u = 0; u < 2; u++) {
        int l = t + u*2048;
        *(float4*)&Ts[l >> 6][l & 63] = tf4(v[u]);
    }
}
template<int P>
__device__ __forceinline__ void sts4_512n(float (*Ts)[P], const float4 (&v)[2]) {
    int t = threadIdx.x * 4;
#pragma unroll
    for (int u = 0; u < 2; u++) {
        int l = t + u*2048;
        *(float4*)&Ts[l >> 6][l & 63] = tf4n(v[u]);
    }
}

// ---------------- fused projection: x @ [Wq|Wk|Wv|Ww1|Wb] ----------------------
__global__ __launch_bounds__(256, 2) void proj_kernel(
    const float* __restrict__ x,  const float* __restrict__ Wq,
    const float* __restrict__ Wk, const float* __restrict__ Wv,
    const float* __restrict__ Ww1,const float* __restrict__ Wb)
{
    extern __shared__ float sm[];
    float (*Ab0)[PA_] = (float(*)[PA_])sm;
    float (*Ab1)[PA_] = (float(*)[PA_])(sm + ASZ);
    float (*Bb0)[PB_] = (float(*)[PB_])(sm + 2*ASZ);
    float (*Bb1)[PB_] = (float(*)[PB_])(sm + 2*ASZ + BSZ);
    float (*Ab[2])[PA_] = {Ab0, Ab1};
    float (*Bb[2])[PB_] = {Bb0, Bb1};
    WARP_IDX;
    int bm = blockIdx.y * 64, bn = blockIdx.x * 64;
    float acc[2][2][4] = {};
    float4 va[4], vb[4];

    auto ldB = [&](int kt) {
        int t = tid * 4;
#pragma unroll
        for (int u = 0; u < 4; u++) {
            int l = t + u*1024, r = l >> 6, c = l & 63;
            int kk = kt + r;
            if (bn < 3072) {
                const float* W = (bn < 1024) ? Wq : (bn < 2048) ? Wk : Wv;
                vb[u] = *(const float4*)&W[(size_t)kk*DMM + ((bn + c) & 1023)];
            } else {
                float tv[4];
#pragma unroll
                for (int q2 = 0; q2 < 4; q2++) {
                    int nn = bn + c + q2;
                    tv[q2] = (nn < 3104) ? Ww1[kk*RNK + (nn - 3072)]
                           : (nn < NPROJ) ? Wb[kk*HH + (nn - 3104)] : 0.f;
                }
                vb[u] = make_float4(tv[0], tv[1], tv[2], tv[3]);
            }
        }
    };

    ldg4_256(&x[(size_t)bm*DMM], DMM, va);
    ldB(0);
    sts4_256<PA_>(Ab[0], va);
    sts4_256<PB_>(Bb[0], vb);
    __syncthreads();
    int cur = 0;
    for (int i = 0; i < 16; i++) {
        if (i < 15) { ldg4_256(&x[(size_t)bm*DMM + (i+1)*64], DMM, va); ldB((i+1)*64); }
        mma_tile8(Ab[cur], Bb[cur], acc, wr, wc, g, tig);
        if (i < 15) {
            sts4_256<PA_>(Ab[cur^1], va);
            sts4_256<PB_>(Bb[cur^1], vb);
            __syncthreads();
            cur ^= 1;
        }
    }
#pragma unroll
    for (int mi = 0; mi < 2; mi++)
#pragma unroll
    for (int ni = 0; ni < 2; ni++)
#pragma unroll
    for (int e = 0; e < 4; e++) {
        int row = bm + ACC_ROW(mi, e);
        int col = bn + ACC_COL(ni, e);
        float v = acc[mi][ni][e];
        if      (col < 1024)  g_q[(size_t)row*DMM + col] = v;
        else if (col < 2048)  g_k[(size_t)row*DMM + (col - 1024)] = v;
        else if (col < 3072)  g_v[(size_t)row*DMM + (col - 2048)] = v;
        else if (col < 3104)  g_xw1[row*RNK + (col - 3072)] = v;
        else if (col < NPROJ) g_beta[row*HH + (col - 3104)] = 2.f/(1.f + expf(-v));
    }
}

// ---------------- generic C = A@B (M,N mult of 64, K mult of 4) ----------------
__global__ __launch_bounds__(256, 2) void gemm_tc(
    const float* __restrict__ A, const float* __restrict__ B,
    float* __restrict__ C, int N, int K)
{
    extern __shared__ float sm[];
    float (*Ab0)[PA_] = (float(*)[PA_])sm;
    float (*Ab1)[PA_] = (float(*)[PA_])(sm + ASZ);
    float (*Bb0)[PB_] = (float(*)[PB_])(sm + 2*ASZ);
    float (*Bb1)[PB_] = (float(*)[PB_])(sm + 2*ASZ + BSZ);
    float (*Ab[2])[PA_] = {Ab0, Ab1};
    float (*Bb[2])[PB_] = {Bb0, Bb1};
    WARP_IDX;
    int bm = blockIdx.y * 64, bn = blockIdx.x * 64;
    float acc[2][2][4] = {};
    float4 va[4], vb[4];

    auto ldA = [&](int kt) {
        int t = tid * 4;
#pragma unroll
        for (int u = 0; u < 4; u++) {
            int l = t + u*1024, r = l >> 6, c = l & 63;
            va[u] = (kt + c < K) ? *(const float4*)&A[(size_t)(bm + r)*K + kt + c]
                                 : make_float4(0.f, 0.f, 0.f, 0.f);
        }
    };
    auto ldB = [&](int kt) {
        int t = tid * 4;
#pragma unroll
        for (int u = 0; u < 4; u++) {
            int l = t + u*1024, r = l >> 6, c = l & 63;
            vb[u] = (kt + r < K) ? *(const float4*)&B[(size_t)(kt + r)*N + bn + c]
                                 : make_float4(0.f, 0.f, 0.f, 0.f);
        }
    };

    int nk = (K + 63) / 64;
    ldA(0); ldB(0);
    sts4_256<PA_>(Ab[0], va);
    sts4_256<PB_>(Bb[0], vb);
    __syncthreads();
    int cur = 0;
    for (int i = 0; i < nk; i++) {
        if (i < nk - 1) { ldA((i+1)*64); ldB((i+1)*64); }
        mma_tile8(Ab[cur], Bb[cur], acc, wr, wc, g, tig);
        if (i < nk - 1) {
            sts4_256<PA_>(Ab[cur^1], va);
            sts4_256<PB_>(Bb[cur^1], vb);
            __syncthreads();
            cur ^= 1;
        }
    }
#pragma unroll
    for (int mi = 0; mi < 2; mi++)
#pragma unroll
    for (int ni = 0; ni < 2; ni++)
#pragma unroll
    for (int e = 0; e < 4; e++)
        C[(size_t)(bm + ACC_ROW(mi, e))*N + bn + ACC_COL(ni, e)] = acc[mi][ni][e];
}

// ---------------- causal depthwise conv(3) + SiLU + per-head L2 norm -----------
__global__ void conv_norm_kernel(const float* __restrict__ conv_w)
{
    int t = blockIdx.x;
    int c = threadIdx.x;
    float x0  = g_wpre[t*DMM + c];
    float xm1 = (t >= 1) ? g_wpre[(t-1)*DMM + c] : 0.f;
    float xm2 = (t >= 2) ? g_wpre[(t-2)*DMM + c] : 0.f;
    float y = conv_w[c*3+0]*xm2 + conv_w[c*3+1]*xm1 + conv_w[c*3+2]*x0;
    y = y / (1.f + expf(-y));
    float y2 = y * y;
#pragma unroll
    for (int o = 16; o; o >>= 1) y2 += __shfl_xor_sync(0xffffffffu, y2, o);
    __shared__ float wsum[32];
    if ((c & 31) == 0) wsum[c >> 5] = y2;
    __syncthreads();
    int h = c >> 6;
    float ss = wsum[2*h] + wsum[2*h+1];
    g_w[t*DMM + c] = y * rsqrtf(ss + 1e-6f);
}

// ---------------- fused headdot: M, Mk, Aqw, QK per (pair, head) ---------------
__global__ __launch_bounds__(256, 2) void headdot4_kernel()
{
    extern __shared__ float sm[];
    float (*Aq)[PA_] = (float(*)[PA_])sm;                 // [i][d]
    float (*Aw)[PA_] = (float(*)[PA_])(sm + ASZ);         // [i][d]
    float (*Bw)[PA_] = (float(*)[PA_])(sm + 2*ASZ);       // [j][d] row-major
    float (*Bk)[PA_] = (float(*)[PA_])(sm + 3*ASZ);       // [j][d] row-major
    int bi, bj; pair_map(blockIdx.x, bi, bj);
    int h = blockIdx.y;
    WARP_IDX;
    {
        int t = tid * 4;
#pragma unroll
        for (int u = 0; u < 4; u++) {
            int l = t + u*1024, r = l >> 6, c = l & 63;
            *(float4*)&Aq[r][c] = tf4(*(const float4*)&g_q[(size_t)(bi*64 + r)*DMM + h*64 + c]);
            *(float4*)&Aw[r][c] = tf4(*(const float4*)&g_w[(size_t)(bi*64 + r)*DMM + h*64 + c]);
            *(float4*)&Bw[r][c] = tf4(*(const float4*)&g_w[(size_t)(bj*64 + r)*DMM + h*64 + c]);
            *(float4*)&Bk[r][c] = tf4(*(const float4*)&g_k[(size_t)(bj*64 + r)*DMM + h*64 + c]);
        }
    }
    __syncthreads();
    size_t base = (size_t)h*TT*TT;

    {   // pass 1: Aqw = q.w (causal), QK = q.k
        float aqw[2][2][4] = {}, aqk[2][2][4] = {};
        mma_tile2r(Aq, Bw, Bk, aqw, aqk, wr, wc, g, tig);
#pragma unroll
        for (int mi = 0; mi < 2; mi++)
#pragma unroll
        for (int ni = 0; ni < 2; ni++)
#pragma unroll
        for (int e = 0; e < 4; e += 2) {
            int r = bi*64 + ACC_ROW(mi, e), c = bj*64 + ACC_COL(ni, e);
            float2 gv, sv;
            gv.x = (c     <= r) ? aqw[mi][ni][e]   : 0.f;
            gv.y = (c + 1 <= r) ? aqw[mi][ni][e+1] : 0.f;
            sv.x = aqk[mi][ni][e]; sv.y = aqk[mi][ni][e+1];
            *(float2*)&g_G[base + (size_t)r*TT + c] = gv;
            *(float2*)&g_S[base + (size_t)r*TT + c] = sv;
        }
    }
    {   // pass 2: M = beta * w.w (strict), Mk = beta * w.k (strict)
        float am[2][2][4] = {}, amk[2][2][4] = {};
        mma_tile2r(Aw, Bw, Bk, am, amk, wr, wc, g, tig);
#pragma unroll
        for (int mi = 0; mi < 2; mi++)
#pragma unroll
        for (int ni = 0; ni < 2; ni++)
#pragma unroll
        for (int e = 0; e < 4; e += 2) {
            int r = bi*64 + ACC_ROW(mi, e), c = bj*64 + ACC_COL(ni, e);
            float beta = g_beta[r*HH + h];
            float2 mv, kv;
            mv.x = (r > c    ) ? beta * am [mi][ni][e]   : 0.f;
            mv.y = (r > c + 1) ? beta * am [mi][ni][e+1] : 0.f;
            kv.x = (r > c    ) ? beta * amk[mi][ni][e]   : 0.f;
            kv.y = (r > c + 1) ? beta * amk[mi][ni][e+1] : 0.f;
            *(float2*)&g_M [base + (size_t)r*TT + c] = mv;
            *(float2*)&g_Mk[base + (size_t)r*TT + c] = kv;
        }
    }
}

// ---------------- invert unit-lower diagonal blocks of A = I + M ---------------
__global__ void inv_diag_kernel()
{
    int J = blockIdx.x, h = blockIdx.y;
    int c = threadIdx.x;
    __shared__ float L[64][65];
    __shared__ float X[64][65];
    const float* Mt = &g_M[(size_t)h*TT*TT + (size_t)(J*64)*TT + J*64];
    for (int r = 0; r < 64; r++) {
        L[r][c] = (r > c) ? Mt[(size_t)r*TT + c] : (r == c ? 1.f : 0.f);
        X[r][c] = (r == c) ? 1.f : 0.f;
    }
    __syncthreads();
    for (int r = 1; r < 64; r++) {
        if (c < r) {
            float a = 0.f;
            for (int s = c; s < r; s++) a += L[r][s] * X[s][c];
            X[r][c] = -a;
        }
        __syncthreads();
    }
    float* out = &g_invA[((size_t)h*NT + J)*4096];
    for (int r = 0; r < 64; r++) out[r*64 + c] = X[r][c];
}

// ---------------- per-(head, block-row) back-substitution ----------------------
__global__ __launch_bounds__(512) void solve_kernel()
{
    extern __shared__ float sm[];
    float (*Gb0)[PA_] = (float(*)[PA_])sm;
    float (*Gb1)[PA_] = (float(*)[PA_])(sm + ASZ);
    float (*Mb0)[PB_] = (float(*)[PB_])(sm + 2*ASZ);
    float (*Mb1)[PB_] = (float(*)[PB_])(sm + 2*ASZ + BSZ);
    float (*Gb[2])[PA_] = {Gb0, Gb1};
    float (*Mb[2])[PB_] = {Mb0, Mb1};
    int h = blockIdx.x;
    int I = NT - 1 - blockIdx.y;         // heavy rows launch first
    size_t base = (size_t)h*TT*TT;
    WARP_IDX16;
    float4 vg[2], vm[2], vi[2];

    for (int J = I; J >= 0; J--) {
        float acc[2][4];
        const float* Aqw = &g_G[base + (size_t)(I*64)*TT + J*64];
#pragma unroll
        for (int ni = 0; ni < 2; ni++)
#pragma unroll
        for (int e = 0; e < 4; e++)
            acc[ni][e] = Aqw[(size_t)A16_ROW(e)*TT + A16_COL(ni,e)];

        const float* Ip = &g_invA[((size_t)h*NT + J)*4096];
        int cur = 0;
        if (J < I) {
            ldg4_512(&g_G[base + (size_t)(I*64)*TT + (J+1)*64], TT, vg);
            ldg4_512(&g_M[base + (size_t)((J+1)*64)*TT + J*64], TT, vm);
            sts4_512<PA_>(Gb[0], vg);
            sts4_512n<PB_>(Mb[0], vm);
            __syncthreads();
            for (int S = J + 1; S <= I; S++) {
                if (S < I) {
                    ldg4_512(&g_G[base + (size_t)(I*64)*TT + (S+1)*64], TT, vg);
                    ldg4_512(&g_M[base + (size_t)((S+1)*64)*TT + J*64], TT, vm);
                } else {
                    ldg4_512(Ip, 64, vi);
                }
                mma_tile16(Gb[cur], Mb[cur], acc, wr, wc, g, tig);
                if (S < I) {
                    sts4_512<PA_>(Gb[cur^1], vg);
                    sts4_512n<PB_>(Mb[cur^1], vm);
                    __syncthreads();
                    cur ^= 1;
                }
            }
        } else {
            ldg4_512(Ip, 64, vi);
        }
        __syncthreads();
        // multiply by invA_J
#pragma unroll
        for (int ni = 0; ni < 2; ni++)
#pragma unroll
        for (int e = 0; e < 4; e++)
            Gb[cur][A16_ROW(e)][A16_COL(ni,e)] = to_tf32(acc[ni][e]);
        sts4_512<PB_>(Mb[cur], vi);
        __syncthreads();
        float fin[2][4] = {};
        mma_tile16(Gb[cur], Mb[cur], fin, wr, wc, g, tig);
        float* Gout = &g_G[base + (size_t)(I*64)*TT + J*64];
#pragma unroll
        for (int ni = 0; ni < 2; ni++)
#pragma unroll
        for (int e = 0; e < 4; e += 2) {
            float2 v = make_float2(fin[ni][e], fin[ni][e+1]);
            *(float2*)&Gout[(size_t)A16_ROW(e)*TT + A16_COL(ni,e)] = v;
        }
        __syncthreads();
    }
}

// ---------------- pair-parallel S = (QK - G @ Mk) * scale ----------------------
__global__ __launch_bounds__(256, 2) void s_kernel()
{
    extern __shared__ float sm[];
    float (*Gb0)[PA_] = (float(*)[PA_])sm;
    float (*Gb1)[PA_] = (float(*)[PA_])(sm + ASZ);
    float (*Mb0)[PB_] = (float(*)[PB_])(sm + 2*ASZ);
    float (*Mb1)[PB_] = (float(*)[PB_])(sm + 2*ASZ + BSZ);
    float (*Gb[2])[PA_] = {Gb0, Gb1};
    float (*Mb[2])[PB_] = {Mb0, Mb1};
    // work-descending pair enumeration: long diagonals first
    int rem = blockIdx.x, kd = NT - 1;
    while (rem >= NT - kd) { rem -= NT - kd; kd--; }
    int bj = rem, bi = rem + kd;
    int h = blockIdx.y;
    size_t base = (size_t)h*TT*TT;
    WARP_IDX;
    float acc[2][2][4];
    const float* QK = &g_S[base + (size_t)(bi*64)*TT + bj*64];
#pragma unroll
    for (int mi = 0; mi < 2; mi++)
#pragma unroll
    for (int ni = 0; ni < 2; ni++)
#pragma unroll
    for (int e = 0; e < 4; e++)
        acc[mi][ni][e] = QK[(size_t)ACC_ROW(mi,e)*TT + ACC_COL(ni,e)];

    float4 vg[4], vm[4];
    ldg4_256(&g_G [base + (size_t)(bi*64)*TT + bj*64], TT, vg);
    ldg4_256(&g_Mk[base + (size_t)(bj*64)*TT + bj*64], TT, vm);
    sts4_256<PA_>(Gb[0], vg);
    sts4_256n<PB_>(Mb[0], vm);
    __syncthreads();
    int cur = 0;
    for (int S = bj; S <= bi; S++) {
        if (S < bi) {
            ldg4_256(&g_G [base + (size_t)(bi*64)*TT + (S+1)*64], TT, vg);
            ldg4_256(&g_Mk[base + (size_t)((S+1)*64)*TT + bj*64], TT, vm);
        }
        mma_tile8(Gb[cur], Mb[cur], acc, wr, wc, g, tig);
        if (S < bi) {
            sts4_256<PA_>(Gb[cur^1], vg);
            sts4_256n<PB_>(Mb[cur^1], vm);
            __syncthreads();
            cur ^= 1;
        }
    }
    float* Sp = &g_S[base + (size_t)(bi*64)*TT + bj*64];
#pragma unroll
    for (int mi = 0; mi < 2; mi++)
#pragma unroll
    for (int ni = 0; ni < 2; ni++)
#pragma unroll
    for (int e = 0; e < 4; e += 2) {
        int r = ACC_ROW(mi,e), c = ACC_COL(ni,e);
        float2 v;
        v.x = (bi == bj && c     > r) ? -1e30f : acc[mi][ni][e]   * SCALE;
        v.y = (bi == bj && c + 1 > r) ? -1e30f : acc[mi][ni][e+1] * SCALE;
        *(float2*)&Sp[(size_t)r*TT + c] = v;
    }
}

// ---------------- per-(head, block-row): softmax + P @ V -----------------------
__global__ __launch_bounds__(256, 2) void pv_kernel()
{
    extern __shared__ float sm[];
    float (*Pb0)[PA_] = (float(*)[PA_])sm;
    float (*Pb1)[PA_] = (float(*)[PA_])(sm + ASZ);
    float (*Vb0)[PB_] = (float(*)[PB_])(sm + 2*ASZ);
    float (*Vb1)[PB_] = (float(*)[PB_])(sm + 2*ASZ + BSZ);
    float (*Pb[2])[PA_] = {Pb0, Pb1};
    float (*Vb[2])[PB_] = {Vb0, Vb1};
    __shared__ float rmax[64], rinv[64], red[64][4];
    int h = blockIdx.x;
    int I = NT - 1 - blockIdx.y;
    size_t base = (size_t)h*TT*TT;
    WARP_IDX;

    // ---- row softmax stats ----
    {
        int r = tid >> 2, part = tid & 3;
        const float* Srow = &g_S[base + (size_t)(I*64 + r)*TT];
        int ncols = (I + 1) * 64;
        float m = -1e30f;
        for (int c = part*4; c < ncols; c += 16) {
            float4 v = *(const float4*)&Srow[c];
            m = fmaxf(m, fmaxf(fmaxf(v.x, v.y), fmaxf(v.z, v.w)));
        }
        red[r][part] = m;
        __syncthreads();
        m = fmaxf(fmaxf(red[r][0], red[r][1]), fmaxf(red[r][2], red[r][3]));
        float s = 0.f;
        for (int c = part*4; c < ncols; c += 16) {
            float4 v = *(const float4*)&Srow[c];
            s += __expf(v.x - m) + __expf(v.y - m) + __expf(v.z - m) + __expf(v.w - m);
        }
        __syncthreads();
        red[r][part] = s;
        __syncthreads();
        if (part == 0) {
            rmax[r] = m;
            rinv[r] = 1.f / (red[r][0] + red[r][1] + red[r][2] + red[r][3]);
        }
        __syncthreads();
    }

    auto stsP = [&](float (*Ts)[PA_], const float4 (&v)[4]) {
        int t = tid * 4;
#pragma unroll
        for (int u = 0; u < 4; u++) {
            int l = t + u*1024, r = l >> 6, c = l & 63;
            float mr = rmax[r], iv = rinv[r];
            float4 w4;
            w4.x = to_tf32(__expf(v[u].x - mr) * iv);
            w4.y = to_tf32(__expf(v[u].y - mr) * iv);
            w4.z = to_tf32(__expf(v[u].z - mr) * iv);
            w4.w = to_tf32(__expf(v[u].w - mr) * iv);
            *(float4*)&Ts[r][c] = w4;
        }
    };

    // ---- o[I] = P @ V ----
    float oacc[2][2][4] = {};
    float4 vp[4], vv[4];
    ldg4_256(&g_S[base + (size_t)(I*64)*TT], TT, vp);
    ldg4_256(&g_v[h*64], DMM, vv);
    stsP(Pb[0], vp);
    sts4_256<PB_>(Vb[0], vv);
    __syncthreads();
    int cur = 0;
    for (int bj = 0; bj <= I; bj++) {
        if (bj < I) {
            ldg4_256(&g_S[base + (size_t)(I*64)*TT + (bj+1)*64], TT, vp);
            ldg4_256(&g_v[(size_t)((bj+1)*64)*DMM + h*64], DMM, vv);
        }
        mma_tile8(Pb[cur], Vb[cur], oacc, wr, wc, g, tig);
        if (bj < I) {
            stsP(Pb[cur^1], vp);
            sts4_256<PB_>(Vb[cur^1], vv);
            __syncthreads();
            cur ^= 1;
        }
    }
#pragma unroll
    for (int mi = 0; mi < 2; mi++)
#pragma unroll
    for (int ni = 0; ni < 2; ni++)
#pragma unroll
    for (int e = 0; e < 4; e += 2) {
        float2 v = make_float2(oacc[mi][ni][e], oacc[mi][ni][e+1]);
        *(float2*)&g_o[(size_t)(I*64 + ACC_ROW(mi,e))*DMM + h*64 + ACC_COL(ni,e)] = v;
    }
}

// ---------------- launcher ------------------------------------------------------
extern "C" void kernel_launch(void* const* d_in, const int* in_sizes, int n_in,
                              void* d_out, int out_size)
{
    const float* x     = (const float*)d_in[0];
    const float* Wq    = (const float*)d_in[1];
    const float* Wk    = (const float*)d_in[2];
    const float* Wv    = (const float*)d_in[3];
    const float* Ww1   = (const float*)d_in[4];
    const float* Ww2   = (const float*)d_in[5];
    const float* convw = (const float*)d_in[6];
    const float* Wb    = (const float*)d_in[7];
    const float* Wo    = (const float*)d_in[8];

    float *xw1, *wpre, *o;
    cudaGetSymbolAddress((void**)&xw1,  g_xw1);
    cudaGetSymbolAddress((void**)&wpre, g_wpre);
    cudaGetSymbolAddress((void**)&o,    g_o);

    const int SM_DB  = (2*ASZ + 2*BSZ) * 4;   // 71680 B (double-buffered pair)
    const int SM_HD4 = 4*ASZ*4;               // 69632 B
    static bool attr_set = false;
    if (!attr_set) {
        cudaFuncSetAttribute(proj_kernel,    cudaFuncAttributeMaxDynamicSharedMemorySize, SM_DB);
        cudaFuncSetAttribute(gemm_tc,        cudaFuncAttributeMaxDynamicSharedMemorySize, SM_DB);
        cudaFuncSetAttribute(headdot4_kernel,cudaFuncAttributeMaxDynamicSharedMemorySize, SM_HD4);
        cudaFuncSetAttribute(solve_kernel,   cudaFuncAttributeMaxDynamicSharedMemorySize, SM_DB);
        cudaFuncSetAttribute(s_kernel,       cudaFuncAttributeMaxDynamicSharedMemorySize, SM_DB);
        cudaFuncSetAttribute(pv_kernel,      cudaFuncAttributeMaxDynamicSharedMemorySize, SM_DB);
        attr_set = true;
    }

    dim3 blk(256);

    // fused projections: q | k | v | xw1 | beta
    proj_kernel<<<dim3((NPROJ + 63)/64, 16), blk, SM_DB>>>(x, Wq, Wk, Wv, Ww1, Wb);

    // wpre = xw1 @ Ww2  (K=32)
    gemm_tc<<<dim3(16, 16), blk, SM_DB>>>(xw1, Ww2, wpre, DMM, RNK);

    // conv + silu + per-head l2 norm
    conv_norm_kernel<<<TT, 1024>>>(convw);

    // fused per-head products on lower tiles: M, Mk, Aqw, QK
    headdot4_kernel<<<dim3(NPAIR, HH), blk, SM_HD4>>>();

    // invert diagonal blocks of I + M
    inv_diag_kernel<<<dim3(NT, HH), 64>>>();

    // per-(head, block-row) back-substitution (serial part only)
    solve_kernel<<<dim3(HH, NT), 512, SM_DB>>>();

    // pair-parallel S = (QK - G Mk)*scale, then softmax+PV per row
    s_kernel<<<dim3(NPAIR, HH), blk, SM_DB>>>();
    pv_kernel<<<dim3(HH, NT), blk, SM_DB>>>();

    // output projection
    gemm_tc<<<dim3(16, 16), blk, SM_DB>>>(o, Wo, (float*)d_out, DMM, DMM);
}

// round 9
// speedup vs baseline: 5.5074x; 1.8665x over previous
#include <cuda_runtime.h>
#include <math.h>
#include <stdint.h>

#define TT   1024
#define DMM  1024
#define HH   16
#define RNK  32
#define NT   16
#define NPAIR 136
#define SCALE 0.125f
#define NPROJ 3120     // 3*1024 + 32 + 16

#define PA_  68
#define PB_  72
#define ASZ  (64*PA_)
#define BSZ  (64*PB_)

// ---------------- scratch (device globals) ----------------------------------
__device__ float g_q   [TT*DMM];
__device__ float g_k   [TT*DMM];
__device__ float g_v   [TT*DMM];
__device__ float g_wpre[TT*DMM];
__device__ float g_w   [TT*DMM];
__device__ float g_xw1 [TT*RNK];
__device__ float g_beta[TT*HH];
__device__ float g_G [HH*TT*TT];     // Aqw (causal)
__device__ float g_S [HH*TT*TT];     // QK -> scaled logits
__device__ float g_invA[HH*NT*64*64];
__device__ float g_Md [HH*NT*64*64]; // strict diag M blocks
__device__ float g_MkD[HH*NT*64*64]; // strict diag Mk blocks, NEGATED
__device__ float g_o [TT*DMM];

// ---------------- tf32 helpers ------------------------------------------------
__device__ __forceinline__ float to_tf32(float x) {
    uint32_t u; asm("cvt.rna.tf32.f32 %0, %1;" : "=r"(u) : "f"(x));
    return __uint_as_float(u);
}
__device__ __forceinline__ float4 tf4(float4 v) {
    v.x = to_tf32(v.x); v.y = to_tf32(v.y); v.z = to_tf32(v.z); v.w = to_tf32(v.w);
    return v;
}
__device__ __forceinline__ float4 tf4n(float4 v) {
    v.x = to_tf32(-v.x); v.y = to_tf32(-v.y); v.z = to_tf32(-v.z); v.w = to_tf32(-v.w);
    return v;
}

__device__ __forceinline__ void mma8(float (&c)[4], const uint32_t (&a)[4],
                                     const uint32_t (&b)[2]) {
    asm volatile(
        "mma.sync.aligned.m16n8k8.row.col.f32.tf32.tf32.f32 "
        "{%0,%1,%2,%3},{%4,%5,%6,%7},{%8,%9},{%0,%1,%2,%3};"
        : "+f"(c[0]), "+f"(c[1]), "+f"(c[2]), "+f"(c[3])
        : "r"(a[0]), "r"(a[1]), "r"(a[2]), "r"(a[3]), "r"(b[0]), "r"(b[1]));
}

// ---- 8-warp layout ----
#define WARP_IDX                                   \
    int tid = threadIdx.x;                         \
    int lane = tid & 31, wid = tid >> 5;           \
    int wr = (wid >> 2) * 32, wc = (wid & 3) * 16; \
    int g = lane >> 2, tig = lane & 3;

#define ACC_ROW(mi,e) (wr + (mi)*16 + g + ((e)>>1)*8)
#define ACC_COL(ni,e) (wc + (ni)*8 + tig*2 + ((e)&1))

__device__ __forceinline__ void mma_tile8(const float (*As)[PA_], const float (*Bs)[PB_],
                                          float (&acc)[2][2][4],
                                          int wr, int wc, int g, int tig)
{
#pragma unroll
    for (int kb = 0; kb < 64; kb += 8) {
        uint32_t a[2][4], b[2][2];
#pragma unroll
        for (int mi = 0; mi < 2; mi++) {
            int r0 = wr + mi*16 + g;
            a[mi][0] = __float_as_uint(As[r0    ][kb + tig    ]);
            a[mi][1] = __float_as_uint(As[r0 + 8][kb + tig    ]);
            a[mi][2] = __float_as_uint(As[r0    ][kb + tig + 4]);
            a[mi][3] = __float_as_uint(As[r0 + 8][kb + tig + 4]);
        }
#pragma unroll
        for (int ni = 0; ni < 2; ni++) {
            int c0 = wc + ni*8 + g;
            b[ni][0] = __float_as_uint(Bs[kb + tig    ][c0]);
            b[ni][1] = __float_as_uint(Bs[kb + tig + 4][c0]);
        }
#pragma unroll
        for (int mi = 0; mi < 2; mi++)
#pragma unroll
            for (int ni = 0; ni < 2; ni++)
                mma8(acc[mi][ni], a[mi], b[ni]);
    }
}

__device__ __forceinline__ void mma_tile2r(const float (*As)[PA_],
        const float (*B1)[PA_], const float (*B2)[PA_],
        float (&c1)[2][2][4], float (&c2)[2][2][4],
        int wr, int wc, int g, int tig)
{
#pragma unroll
    for (int kb = 0; kb < 64; kb += 8) {
        uint32_t a[2][4], b1[2][2], b2[2][2];
#pragma unroll
        for (int mi = 0; mi < 2; mi++) {
            int r0 = wr + mi*16 + g;
            a[mi][0] = __float_as_uint(As[r0    ][kb + tig    ]);
            a[mi][1] = __float_as_uint(As[r0 + 8][kb + tig    ]);
            a[mi][2] = __float_as_uint(As[r0    ][kb + tig + 4]);
            a[mi][3] = __float_as_uint(As[r0 + 8][kb + tig + 4]);
        }
#pragma unroll
        for (int ni = 0; ni < 2; ni++) {
            int c0 = wc + ni*8 + g;
            b1[ni][0] = __float_as_uint(B1[c0][kb + tig    ]);
            b1[ni][1] = __float_as_uint(B1[c0][kb + tig + 4]);
            b2[ni][0] = __float_as_uint(B2[c0][kb + tig    ]);
            b2[ni][1] = __float_as_uint(B2[c0][kb + tig + 4]);
        }
#pragma unroll
        for (int mi = 0; mi < 2; mi++)
#pragma unroll
        for (int ni = 0; ni < 2; ni++) {
            mma8(c1[mi][ni], a[mi], b1[ni]);
            mma8(c2[mi][ni], a[mi], b2[ni]);
        }
    }
}

// ---- 16-warp layout ----
#define WARP_IDX16                                 \
    int tid = threadIdx.x;                         \
    int lane = tid & 31, wid = tid >> 5;           \
    int wr = (wid >> 2) * 16, wc = (wid & 3) * 16; \
    int g = lane >> 2, tig = lane & 3;

__device__ __forceinline__ void mma_tile16(const float (*As)[PA_], const float (*Bs)[PB_],
                                           float (&acc)[2][4],
                                           int wr, int wc, int g, int tig)
{
#pragma unroll
    for (int kb = 0; kb < 64; kb += 8) {
        uint32_t a[4], b[2][2];
        a[0] = __float_as_uint(As[wr + g    ][kb + tig    ]);
        a[1] = __float_as_uint(As[wr + g + 8][kb + tig    ]);
        a[2] = __float_as_uint(As[wr + g    ][kb + tig + 4]);
        a[3] = __float_as_uint(As[wr + g + 8][kb + tig + 4]);
#pragma unroll
        for (int ni = 0; ni < 2; ni++) {
            int c0 = wc + ni*8 + g;
            b[ni][0] = __float_as_uint(Bs[kb + tig    ][c0]);
            b[ni][1] = __float_as_uint(Bs[kb + tig + 4][c0]);
        }
        mma8(acc[0], a, b[0]);
        mma8(acc[1], a, b[1]);
    }
}

__device__ __forceinline__ void mma_tile16r(const float (*As)[PA_], const float (*Bs)[PA_],
                                            float (&acc)[2][4],
                                            int wr, int wc, int g, int tig)
{
#pragma unroll
    for (int kb = 0; kb < 64; kb += 8) {
        uint32_t a[4], b[2][2];
        a[0] = __float_as_uint(As[wr + g    ][kb + tig    ]);
        a[1] = __float_as_uint(As[wr + g + 8][kb + tig    ]);
        a[2] = __float_as_uint(As[wr + g    ][kb + tig + 4]);
        a[3] = __float_as_uint(As[wr + g + 8][kb + tig + 4]);
#pragma unroll
        for (int ni = 0; ni < 2; ni++) {
            int c0 = wc + ni*8 + g;
            b[ni][0] = __float_as_uint(Bs[c0][kb + tig    ]);
            b[ni][1] = __float_as_uint(Bs[c0][kb + tig + 4]);
        }
        mma8(acc[0], a, b[0]);
        mma8(acc[1], a, b[1]);
    }
}

__device__ __forceinline__ void pair_map(int p, int& bi, int& bj) {
    int b = 0;
    while ((b+1)*(b+2)/2 <= p) b++;
    bi = b; bj = p - b*(b+1)/2;
}

// ---------------- staging helpers ----------------------------------------------
__device__ __forceinline__ void ldg4_256(const float* __restrict__ p, int ld, float4 (&v)[4]) {
    int t = threadIdx.x * 4;
#pragma unroll
    for (int u = 0; u < 4; u++) {
        int l = t + u*1024;
        v[u] = *(const float4*)(p + (size_t)(l >> 6)*ld + (l & 63));
    }
}
template<int P>
__device__ __forceinline__ void sts4_256(float (*Ts)[P], const float4 (&v)[4]) {
    int t = threadIdx.x * 4;
#pragma unroll
    for (int u = 0; u < 4; u++) {
        int l = t + u*1024;
        *(float4*)&Ts[l >> 6][l & 63] = tf4(v[u]);
    }
}
template<int P, bool NEG>
__device__ __forceinline__ void stage512f(float (*Ts)[P], const float* __restrict__ p, int ld) {
    int t = threadIdx.x * 4;
#pragma unroll
    for (int u = 0; u < 2; u++) {
        int l = t + u*2048, r = l >> 6, c = l & 63;
        float4 v = *(const float4*)(p + (size_t)r*ld + c);
        *(float4*)&Ts[r][c] = NEG ? tf4n(v) : tf4(v);
    }
}
__device__ __forceinline__ void stageBW512(float (*Ts)[PB_], const float* __restrict__ wp,
                                           const float* __restrict__ bp) {
    int t = threadIdx.x * 4;
#pragma unroll
    for (int u = 0; u < 2; u++) {
        int l = t + u*2048, r = l >> 6, c = l & 63;
        float be = bp[r*HH];
        float4 v = *(const float4*)(wp + (size_t)r*DMM + c);
        v.x *= be; v.y *= be; v.z *= be; v.w *= be;
        *(float4*)&Ts[r][c] = tf4(v);
    }
}

// ---------------- fused projection ----------------------------------------------
__global__ __launch_bounds__(256, 2) void proj_kernel(
    const float* __restrict__ x,  const float* __restrict__ Wq,
    const float* __restrict__ Wk, const float* __restrict__ Wv,
    const float* __restrict__ Ww1,const float* __restrict__ Wb)
{
    extern __shared__ float sm[];
    float (*Ab0)[PA_] = (float(*)[PA_])sm;
    float (*Ab1)[PA_] = (float(*)[PA_])(sm + ASZ);
    float (*Bb0)[PB_] = (float(*)[PB_])(sm + 2*ASZ);
    float (*Bb1)[PB_] = (float(*)[PB_])(sm + 2*ASZ + BSZ);
    float (*Ab[2])[PA_] = {Ab0, Ab1};
    float (*Bb[2])[PB_] = {Bb0, Bb1};
    WARP_IDX;
    int bm = blockIdx.y * 64, bn = blockIdx.x * 64;
    float acc[2][2][4] = {};
    float4 va[4], vb[4];

    auto ldB = [&](int kt) {
        int t = tid * 4;
#pragma unroll
        for (int u = 0; u < 4; u++) {
            int l = t + u*1024, r = l >> 6, c = l & 63;
            int kk = kt + r;
            if (bn < 3072) {
                const float* W = (bn < 1024) ? Wq : (bn < 2048) ? Wk : Wv;
                vb[u] = *(const float4*)&W[(size_t)kk*DMM + ((bn + c) & 1023)];
            } else {
                float tv[4];
#pragma unroll
                for (int q2 = 0; q2 < 4; q2++) {
                    int nn = bn + c + q2;
                    tv[q2] = (nn < 3104) ? Ww1[kk*RNK + (nn - 3072)]
                           : (nn < NPROJ) ? Wb[kk*HH + (nn - 3104)] : 0.f;
                }
                vb[u] = make_float4(tv[0], tv[1], tv[2], tv[3]);
            }
        }
    };

    ldg4_256(&x[(size_t)bm*DMM], DMM, va);
    ldB(0);
    sts4_256<PA_>(Ab[0], va);
    sts4_256<PB_>(Bb[0], vb);
    __syncthreads();
    int cur = 0;
    for (int i = 0; i < 16; i++) {
        if (i < 15) { ldg4_256(&x[(size_t)bm*DMM + (i+1)*64], DMM, va); ldB((i+1)*64); }
        mma_tile8(Ab[cur], Bb[cur], acc, wr, wc, g, tig);
        if (i < 15) {
            sts4_256<PA_>(Ab[cur^1], va);
            sts4_256<PB_>(Bb[cur^1], vb);
            __syncthreads();
            cur ^= 1;
        }
    }
#pragma unroll
    for (int mi = 0; mi < 2; mi++)
#pragma unroll
    for (int ni = 0; ni < 2; ni++)
#pragma unroll
    for (int e = 0; e < 4; e++) {
        int row = bm + ACC_ROW(mi, e);
        int col = bn + ACC_COL(ni, e);
        float v = acc[mi][ni][e];
        if      (col < 1024)  g_q[(size_t)row*DMM + col] = v;
        else if (col < 2048)  g_k[(size_t)row*DMM + (col - 1024)] = v;
        else if (col < 3072)  g_v[(size_t)row*DMM + (col - 2048)] = v;
        else if (col < 3104)  g_xw1[row*RNK + (col - 3072)] = v;
        else if (col < NPROJ) g_beta[row*HH + (col - 3104)] = 2.f/(1.f + expf(-v));
    }
}

// ---------------- generic C = A@B -------------------------------------------------
__global__ __launch_bounds__(256, 2) void gemm_tc(
    const float* __restrict__ A, const float* __restrict__ B,
    float* __restrict__ C, int N, int K)
{
    extern __shared__ float sm[];
    float (*Ab0)[PA_] = (float(*)[PA_])sm;
    float (*Ab1)[PA_] = (float(*)[PA_])(sm + ASZ);
    float (*Bb0)[PB_] = (float(*)[PB_])(sm + 2*ASZ);
    float (*Bb1)[PB_] = (float(*)[PB_])(sm + 2*ASZ + BSZ);
    float (*Ab[2])[PA_] = {Ab0, Ab1};
    float (*Bb[2])[PB_] = {Bb0, Bb1};
    WARP_IDX;
    int bm = blockIdx.y * 64, bn = blockIdx.x * 64;
    float acc[2][2][4] = {};
    float4 va[4], vb[4];

    auto ldA = [&](int kt) {
        int t = tid * 4;
#pragma unroll
        for (int u = 0; u < 4; u++) {
            int l = t + u*1024, r = l >> 6, c = l & 63;
            va[u] = (kt + c < K) ? *(const float4*)&A[(size_t)(bm + r)*K + kt + c]
                                 : make_float4(0.f, 0.f, 0.f, 0.f);
        }
    };
    auto ldB = [&](int kt) {
        int t = tid * 4;
#pragma unroll
        for (int u = 0; u < 4; u++) {
            int l = t + u*1024, r = l >> 6, c = l & 63;
            vb[u] = (kt + r < K) ? *(const float4*)&B[(size_t)(kt + r)*N + bn + c]
                                 : make_float4(0.f, 0.f, 0.f, 0.f);
        }
    };

    int nk = (K + 63) / 64;
    ldA(0); ldB(0);
    sts4_256<PA_>(Ab[0], va);
    sts4_256<PB_>(Bb[0], vb);
    __syncthreads();
    int cur = 0;
    for (int i = 0; i < nk; i++) {
        if (i < nk - 1) { ldA((i+1)*64); ldB((i+1)*64); }
        mma_tile8(Ab[cur], Bb[cur], acc, wr, wc, g, tig);
        if (i < nk - 1) {
            sts4_256<PA_>(Ab[cur^1], va);
            sts4_256<PB_>(Bb[cur^1], vb);
            __syncthreads();
            cur ^= 1;
        }
    }
#pragma unroll
    for (int mi = 0; mi < 2; mi++)
#pragma unroll
    for (int ni = 0; ni < 2; ni++)
#pragma unroll
    for (int e = 0; e < 4; e++)
        C[(size_t)(bm + ACC_ROW(mi, e))*N + bn + ACC_COL(ni, e)] = acc[mi][ni][e];
}

// ---------------- conv + SiLU + per-head L2 norm ----------------------------------
__global__ void conv_norm_kernel(const float* __restrict__ conv_w)
{
    int t = blockIdx.x;
    int c = threadIdx.x;
    float x0  = g_wpre[t*DMM + c];
    float xm1 = (t >= 1) ? g_wpre[(t-1)*DMM + c] : 0.f;
    float xm2 = (t >= 2) ? g_wpre[(t-2)*DMM + c] : 0.f;
    float y = conv_w[c*3+0]*xm2 + conv_w[c*3+1]*xm1 + conv_w[c*3+2]*x0;
    y = y / (1.f + expf(-y));
    float y2 = y * y;
#pragma unroll
    for (int o = 16; o; o >>= 1) y2 += __shfl_xor_sync(0xffffffffu, y2, o);
    __shared__ float wsum[32];
    if ((c & 31) == 0) wsum[c >> 5] = y2;
    __syncthreads();
    int h = c >> 6;
    float ss = wsum[2*h] + wsum[2*h+1];
    g_w[t*DMM + c] = y * rsqrtf(ss + 1e-6f);
}

// ---------------- headdot2: Aqw (causal) + QK -------------------------------------
__global__ __launch_bounds__(256, 2) void headdot2_kernel()
{
    extern __shared__ float sm[];
    float (*Aq)[PA_] = (float(*)[PA_])sm;
    float (*Bw)[PA_] = (float(*)[PA_])(sm + ASZ);
    float (*Bk)[PA_] = (float(*)[PA_])(sm + 2*ASZ);
    int bi, bj; pair_map(blockIdx.x, bi, bj);
    int h = blockIdx.y;
    WARP_IDX;
    {
        int t = tid * 4;
#pragma unroll
        for (int u = 0; u < 4; u++) {
            int l = t + u*1024, r = l >> 6, c = l & 63;
            *(float4*)&Aq[r][c] = tf4(*(const float4*)&g_q[(size_t)(bi*64 + r)*DMM + h*64 + c]);
            *(float4*)&Bw[r][c] = tf4(*(const float4*)&g_w[(size_t)(bj*64 + r)*DMM + h*64 + c]);
            *(float4*)&Bk[r][c] = tf4(*(const float4*)&g_k[(size_t)(bj*64 + r)*DMM + h*64 + c]);
        }
    }
    __syncthreads();
    size_t base = (size_t)h*TT*TT;
    float aqw[2][2][4] = {}, aqk[2][2][4] = {};
    mma_tile2r(Aq, Bw, Bk, aqw, aqk, wr, wc, g, tig);
#pragma unroll
    for (int mi = 0; mi < 2; mi++)
#pragma unroll
    for (int ni = 0; ni < 2; ni++)
#pragma unroll
    for (int e = 0; e < 4; e += 2) {
        int r = bi*64 + ACC_ROW(mi, e), c = bj*64 + ACC_COL(ni, e);
        float2 gv, sv;
        gv.x = (c     <= r) ? aqw[mi][ni][e]   : 0.f;
        gv.y = (c + 1 <= r) ? aqw[mi][ni][e+1] : 0.f;
        sv.x = aqk[mi][ni][e]; sv.y = aqk[mi][ni][e+1];
        *(float2*)&g_G[base + (size_t)r*TT + c] = gv;
        *(float2*)&g_S[base + (size_t)r*TT + c] = sv;
    }
}

// ---------------- diag blocks: Md (strict) and -MkD (strict) ----------------------
__global__ __launch_bounds__(256) void diagblk_kernel()
{
    __shared__ float Aw[64][PA_];
    __shared__ float Bk[64][PA_];
    int J = blockIdx.x, h = blockIdx.y;
    WARP_IDX;
    {
        int t = tid * 4;
#pragma unroll
        for (int u = 0; u < 4; u++) {
            int l = t + u*1024, r = l >> 6, c = l & 63;
            *(float4*)&Aw[r][c] = tf4(*(const float4*)&g_w[(size_t)(J*64 + r)*DMM + h*64 + c]);
            *(float4*)&Bk[r][c] = tf4(*(const float4*)&g_k[(size_t)(J*64 + r)*DMM + h*64 + c]);
        }
    }
    __syncthreads();
    float am[2][2][4] = {}, amk[2][2][4] = {};
    mma_tile2r(Aw, Aw, Bk, am, amk, wr, wc, g, tig);
    size_t ofs = ((size_t)h*NT + J)*4096;
#pragma unroll
    for (int mi = 0; mi < 2; mi++)
#pragma unroll
    for (int ni = 0; ni < 2; ni++)
#pragma unroll
    for (int e = 0; e < 4; e += 2) {
        int r = ACC_ROW(mi, e), c = ACC_COL(ni, e);
        float be = g_beta[(size_t)(J*64 + r)*HH + h];
        float2 md, mk;
        md.x = (r > c    ) ?  be*am [mi][ni][e]   : 0.f;
        md.y = (r > c + 1) ?  be*am [mi][ni][e+1] : 0.f;
        mk.x = (r > c    ) ? -be*amk[mi][ni][e]   : 0.f;
        mk.y = (r > c + 1) ? -be*amk[mi][ni][e+1] : 0.f;
        *(float2*)&g_Md [ofs + r*64 + c] = md;
        *(float2*)&g_MkD[ofs + r*64 + c] = mk;
    }
}

// ---------------- invert unit-lower diagonal blocks --------------------------------
__global__ void inv_diag_kernel()
{
    int J = blockIdx.x, h = blockIdx.y;
    int c = threadIdx.x;
    __shared__ float L[64][65];
    __shared__ float X[64][65];
    const float* Mt = &g_Md[((size_t)h*NT + J)*4096];
    for (int r = 0; r < 64; r++) {
        L[r][c] = Mt[r*64 + c] + ((r == c) ? 1.f : 0.f);
        X[r][c] = (r == c) ? 1.f : 0.f;
    }
    __syncthreads();
    for (int r = 1; r < 64; r++) {
        if (c < r) {
            float a = 0.f;
            for (int s = c; s < r; s++) a += L[r][s] * X[s][c];
            X[r][c] = -a;
        }
        __syncthreads();
    }
    float* out = &g_invA[((size_t)h*NT + J)*4096];
    for (int r = 0; r < 64; r++) out[r*64 + c] = X[r][c];
}

// ---------------- fused row scan: solve + S + softmax + PV --------------------------
__global__ __launch_bounds__(512) void row_kernel()
{
    extern __shared__ float sm[];
    float (*Psm)[PA_]  = (float(*)[PA_])(sm);
    float (*Gtmp)[PA_] = (float(*)[PA_])(sm + ASZ);
    float (*Wrow)[PA_] = (float(*)[PA_])(sm + 2*ASZ);
    float (*Krow)[PA_] = (float(*)[PA_])(sm + 3*ASZ);
    float (*Binv)[PB_] = (float(*)[PB_])(sm + 4*ASZ);
    float (*MkDs)[PB_] = (float(*)[PB_])(sm + 4*ASZ + BSZ);
    float (*BWs)[PB_]  = (float(*)[PB_])(sm + 4*ASZ + 2*BSZ);
    __shared__ float rmax[64], rinv[64], red[64][8];
    int h = blockIdx.x;
    int I = NT - 1 - blockIdx.y;
    size_t base = (size_t)h*TT*TT;
    WARP_IDX16;

    float P[2][4] = {};
    for (int J = I; J >= 0; J--) {
        if (J < I) {
#pragma unroll
            for (int ni = 0; ni < 2; ni++) {
                int c0 = wc + ni*8 + tig*2;
                Psm[wr+g  ][c0]   = to_tf32(P[ni][0]);
                Psm[wr+g  ][c0+1] = to_tf32(P[ni][1]);
                Psm[wr+g+8][c0]   = to_tf32(P[ni][2]);
                Psm[wr+g+8][c0+1] = to_tf32(P[ni][3]);
            }
            stage512f<PA_, true >(Wrow, &g_w[(size_t)(J*64)*DMM + h*64], DMM);
            stage512f<PA_, true >(Krow, &g_k[(size_t)(J*64)*DMM + h*64], DMM);
        }
        stage512f<PB_, false>(Binv, &g_invA[((size_t)h*NT + J)*4096], 64);
        stage512f<PB_, false>(MkDs, &g_MkD [((size_t)h*NT + J)*4096], 64);
        stageBW512(BWs, &g_w[(size_t)(J*64)*DMM + h*64], &g_beta[(size_t)(J*64)*HH + h]);
        __syncthreads();

        float acc[2][4], sacc[2][4];
        {
            const float* Ap = &g_G[base + (size_t)(I*64)*TT + J*64];
            const float* Sp = &g_S[base + (size_t)(I*64)*TT + J*64];
#pragma unroll
            for (int ni = 0; ni < 2; ni++) {
                int c0 = wc + ni*8 + tig*2;
                float2 a0 = *(const float2*)(Ap + (size_t)(wr+g)*TT + c0);
                float2 a1 = *(const float2*)(Ap + (size_t)(wr+g+8)*TT + c0);
                acc[ni][0] = a0.x; acc[ni][1] = a0.y; acc[ni][2] = a1.x; acc[ni][3] = a1.y;
                float2 s0 = *(const float2*)(Sp + (size_t)(wr+g)*TT + c0);
                float2 s1 = *(const float2*)(Sp + (size_t)(wr+g+8)*TT + c0);
                sacc[ni][0] = s0.x; sacc[ni][1] = s0.y; sacc[ni][2] = s1.x; sacc[ni][3] = s1.y;
            }
        }
        if (J < I) {
            mma_tile16r(Psm, Wrow, acc,  wr, wc, g, tig);
            mma_tile16r(Psm, Krow, sacc, wr, wc, g, tig);
        }
#pragma unroll
        for (int ni = 0; ni < 2; ni++) {
            int c0 = wc + ni*8 + tig*2;
            Gtmp[wr+g  ][c0]   = to_tf32(acc[ni][0]);
            Gtmp[wr+g  ][c0+1] = to_tf32(acc[ni][1]);
            Gtmp[wr+g+8][c0]   = to_tf32(acc[ni][2]);
            Gtmp[wr+g+8][c0+1] = to_tf32(acc[ni][3]);
        }
        __syncthreads();
        float Gf[2][4] = {};
        mma_tile16(Gtmp, Binv, Gf, wr, wc, g, tig);
        __syncthreads();
#pragma unroll
        for (int ni = 0; ni < 2; ni++) {
            int c0 = wc + ni*8 + tig*2;
            Gtmp[wr+g  ][c0]   = to_tf32(Gf[ni][0]);
            Gtmp[wr+g  ][c0+1] = to_tf32(Gf[ni][1]);
            Gtmp[wr+g+8][c0]   = to_tf32(Gf[ni][2]);
            Gtmp[wr+g+8][c0+1] = to_tf32(Gf[ni][3]);
        }
        __syncthreads();
        mma_tile16(Gtmp, MkDs, sacc, wr, wc, g, tig);
        mma_tile16(Gtmp, BWs,  P,    wr, wc, g, tig);
        float* So = &g_S[base + (size_t)(I*64)*TT + J*64];
#pragma unroll
        for (int ni = 0; ni < 2; ni++) {
            int c0 = wc + ni*8 + tig*2;
            int r0 = wr + g, r1 = wr + g + 8;
            float2 v0, v1;
            v0.x = sacc[ni][0]*SCALE; v0.y = sacc[ni][1]*SCALE;
            v1.x = sacc[ni][2]*SCALE; v1.y = sacc[ni][3]*SCALE;
            if (J == I) {
                if (c0     > r0) v0.x = -1e30f;
                if (c0 + 1 > r0) v0.y = -1e30f;
                if (c0     > r1) v1.x = -1e30f;
                if (c0 + 1 > r1) v1.y = -1e30f;
            }
            *(float2*)(So + (size_t)r0*TT + c0) = v0;
            *(float2*)(So + (size_t)r1*TT + c0) = v1;
        }
        __syncthreads();
    }

    // ---- row softmax stats ----
    {
        int r = tid >> 3, part = tid & 7;
        const float* Srow = &g_S[base + (size_t)(I*64 + r)*TT];
        int ncols = (I + 1) * 64;
        float m = -1e30f;
        for (int c = part*4; c < ncols; c += 32) {
            float4 v = *(const float4*)&Srow[c];
            m = fmaxf(m, fmaxf(fmaxf(v.x, v.y), fmaxf(v.z, v.w)));
        }
        red[r][part] = m;
        __syncthreads();
#pragma unroll
        for (int u = 0; u < 8; u++) m = fmaxf(m, red[r][u]);
        float s = 0.f;
        for (int c = part*4; c < ncols; c += 32) {
            float4 v = *(const float4*)&Srow[c];
            s += __expf(v.x - m) + __expf(v.y - m) + __expf(v.z - m) + __expf(v.w - m);
        }
        __syncthreads();
        red[r][part] = s;
        __syncthreads();
        if (part == 0) {
            float tsum = 0.f;
#pragma unroll
            for (int u = 0; u < 8; u++) tsum += red[r][u];
            rmax[r] = m;
            rinv[r] = 1.f / tsum;
        }
        __syncthreads();
    }

    // ---- o[I] = softmax(S) @ V ----
    float O[2][4] = {};
    for (int bj = 0; bj <= I; bj++) {
        {
            int t = tid * 4;
            const float* Sp = &g_S[base + (size_t)(I*64)*TT + bj*64];
#pragma unroll
            for (int u = 0; u < 2; u++) {
                int l = t + u*2048, r = l >> 6, c = l & 63;
                float4 v = *(const float4*)(Sp + (size_t)r*TT + c);
                float mr = rmax[r], iv = rinv[r];
                v.x = to_tf32(__expf(v.x - mr) * iv);
                v.y = to_tf32(__expf(v.y - mr) * iv);
                v.z = to_tf32(__expf(v.z - mr) * iv);
                v.w = to_tf32(__expf(v.w - mr) * iv);
                *(float4*)&Wrow[r][c] = v;
            }
            stage512f<PB_, false>(Binv, &g_v[(size_t)(bj*64)*DMM + h*64], DMM);
        }
        __syncthreads();
        mma_tile16(Wrow, Binv, O, wr, wc, g, tig);
        __syncthreads();
    }
#pragma unroll
    for (int ni = 0; ni < 2; ni++) {
        int c0 = wc + ni*8 + tig*2;
        float2 v0 = make_float2(O[ni][0], O[ni][1]);
        float2 v1 = make_float2(O[ni][2], O[ni][3]);
        *(float2*)&g_o[(size_t)(I*64 + wr + g    )*DMM + h*64 + c0] = v0;
        *(float2*)&g_o[(size_t)(I*64 + wr + g + 8)*DMM + h*64 + c0] = v1;
    }
}

// ---------------- launcher ----------------------------------------------------------
extern "C" void kernel_launch(void* const* d_in, const int* in_sizes, int n_in,
                              void* d_out, int out_size)
{
    const float* x     = (const float*)d_in[0];
    const float* Wq    = (const float*)d_in[1];
    const float* Wk    = (const float*)d_in[2];
    const float* Wv    = (const float*)d_in[3];
    const float* Ww1   = (const float*)d_in[4];
    const float* Ww2   = (const float*)d_in[5];
    const float* convw = (const float*)d_in[6];
    const float* Wb    = (const float*)d_in[7];
    const float* Wo    = (const float*)d_in[8];

    float *xw1, *wpre, *o;
    cudaGetSymbolAddress((void**)&xw1,  g_xw1);
    cudaGetSymbolAddress((void**)&wpre, g_wpre);
    cudaGetSymbolAddress((void**)&o,    g_o);

    const int SM_DB  = (2*ASZ + 2*BSZ) * 4;
    const int SM_HD2 = 3*ASZ*4;
    const int SM_ROW = (4*ASZ + 3*BSZ) * 4;
    static bool attr_set = false;
    if (!attr_set) {
        cudaFuncSetAttribute(proj_kernel,     cudaFuncAttributeMaxDynamicSharedMemorySize, SM_DB);
        cudaFuncSetAttribute(gemm_tc,         cudaFuncAttributeMaxDynamicSharedMemorySize, SM_DB);
        cudaFuncSetAttribute(headdot2_kernel, cudaFuncAttributeMaxDynamicSharedMemorySize, SM_HD2);
        cudaFuncSetAttribute(row_kernel,      cudaFuncAttributeMaxDynamicSharedMemorySize, SM_ROW);
        attr_set = true;
    }

    dim3 blk(256);

    proj_kernel<<<dim3((NPROJ + 63)/64, 16), blk, SM_DB>>>(x, Wq, Wk, Wv, Ww1, Wb);
    gemm_tc<<<dim3(16, 16), blk, SM_DB>>>(xw1, Ww2, wpre, DMM, RNK);
    conv_norm_kernel<<<TT, 1024>>>(convw);
    headdot2_kernel<<<dim3(NPAIR, HH), blk, SM_HD2>>>();
    diagblk_kernel<<<dim3(NT, HH), blk>>>();
    inv_diag_kernel<<<dim3(NT, HH), 64>>>();
    row_kernel<<<dim3(HH, NT), 512, SM_ROW>>>();
    gemm_tc<<<dim3(16, 16), blk, SM_DB>>>(o, Wo, (float*)d_out, DMM, DMM);
}

// round 10
// speedup vs baseline: 6.1118x; 1.1097x over previous
#include <cuda_runtime.h>
#include <math.h>
#include <stdint.h>

#define TT   1024
#define DMM  1024
#define HH   16
#define RNK  32
#define NT   16
#define SCALE 0.125f
#define NPROJ 3120     // 3*1024 + 32 + 16

#define PA_  68
#define PB_  72
#define ASZ  (64*PA_)
#define BSZ  (64*PB_)

// ---------------- scratch (device globals) ----------------------------------
__device__ float g_q   [TT*DMM];
__device__ float g_k   [TT*DMM];
__device__ float g_v   [TT*DMM];
__device__ float g_wpre[TT*DMM];
__device__ float g_w   [TT*DMM];
__device__ float g_xw1 [TT*RNK];
__device__ float g_beta[TT*HH];
__device__ float g_S [HH*TT*TT];     // scaled logits (written by row scan)
__device__ float g_invA[HH*NT*64*64];
__device__ float g_Md [HH*NT*64*64]; // strict diag M blocks
__device__ float g_MkD[HH*NT*64*64]; // strict diag Mk blocks, NEGATED
__device__ float g_o [TT*DMM];

// ---------------- tf32 helpers ------------------------------------------------
__device__ __forceinline__ float to_tf32(float x) {
    uint32_t u; asm("cvt.rna.tf32.f32 %0, %1;" : "=r"(u) : "f"(x));
    return __uint_as_float(u);
}
__device__ __forceinline__ float4 tf4(float4 v) {
    v.x = to_tf32(v.x); v.y = to_tf32(v.y); v.z = to_tf32(v.z); v.w = to_tf32(v.w);
    return v;
}

__device__ __forceinline__ void mma8(float (&c)[4], const uint32_t (&a)[4],
                                     const uint32_t (&b)[2]) {
    asm volatile(
        "mma.sync.aligned.m16n8k8.row.col.f32.tf32.tf32.f32 "
        "{%0,%1,%2,%3},{%4,%5,%6,%7},{%8,%9},{%0,%1,%2,%3};"
        : "+f"(c[0]), "+f"(c[1]), "+f"(c[2]), "+f"(c[3])
        : "r"(a[0]), "r"(a[1]), "r"(a[2]), "r"(a[3]), "r"(b[0]), "r"(b[1]));
}

// ---- 8-warp layout (256 threads, warp tile 32x16) ----
#define WARP_IDX                                   \
    int tid = threadIdx.x;                         \
    int lane = tid & 31, wid = tid >> 5;           \
    int wr = (wid >> 2) * 32, wc = (wid & 3) * 16; \
    int g = lane >> 2, tig = lane & 3;

#define ACC_ROW(mi,e) (wr + (mi)*16 + g + ((e)>>1)*8)
#define ACC_COL(ni,e) (wc + (ni)*8 + tig*2 + ((e)&1))

__device__ __forceinline__ void mma_tile8(const float (*As)[PA_], const float (*Bs)[PB_],
                                          float (&acc)[2][2][4],
                                          int wr, int wc, int g, int tig)
{
#pragma unroll
    for (int kb = 0; kb < 64; kb += 8) {
        uint32_t a[2][4], b[2][2];
#pragma unroll
        for (int mi = 0; mi < 2; mi++) {
            int r0 = wr + mi*16 + g;
            a[mi][0] = __float_as_uint(As[r0    ][kb + tig    ]);
            a[mi][1] = __float_as_uint(As[r0 + 8][kb + tig    ]);
            a[mi][2] = __float_as_uint(As[r0    ][kb + tig + 4]);
            a[mi][3] = __float_as_uint(As[r0 + 8][kb + tig + 4]);
        }
#pragma unroll
        for (int ni = 0; ni < 2; ni++) {
            int c0 = wc + ni*8 + g;
            b[ni][0] = __float_as_uint(Bs[kb + tig    ][c0]);
            b[ni][1] = __float_as_uint(Bs[kb + tig + 4][c0]);
        }
#pragma unroll
        for (int mi = 0; mi < 2; mi++)
#pragma unroll
            for (int ni = 0; ni < 2; ni++)
                mma8(acc[mi][ni], a[mi], b[ni]);
    }
}

__device__ __forceinline__ void mma_tile2r(const float (*As)[PA_],
        const float (*B1)[PA_], const float (*B2)[PA_],
        float (&c1)[2][2][4], float (&c2)[2][2][4],
        int wr, int wc, int g, int tig)
{
#pragma unroll
    for (int kb = 0; kb < 64; kb += 8) {
        uint32_t a[2][4], b1[2][2], b2[2][2];
#pragma unroll
        for (int mi = 0; mi < 2; mi++) {
            int r0 = wr + mi*16 + g;
            a[mi][0] = __float_as_uint(As[r0    ][kb + tig    ]);
            a[mi][1] = __float_as_uint(As[r0 + 8][kb + tig    ]);
            a[mi][2] = __float_as_uint(As[r0    ][kb + tig + 4]);
            a[mi][3] = __float_as_uint(As[r0 + 8][kb + tig + 4]);
        }
#pragma unroll
        for (int ni = 0; ni < 2; ni++) {
            int c0 = wc + ni*8 + g;
            b1[ni][0] = __float_as_uint(B1[c0][kb + tig    ]);
            b1[ni][1] = __float_as_uint(B1[c0][kb + tig + 4]);
            b2[ni][0] = __float_as_uint(B2[c0][kb + tig    ]);
            b2[ni][1] = __float_as_uint(B2[c0][kb + tig + 4]);
        }
#pragma unroll
        for (int mi = 0; mi < 2; mi++)
#pragma unroll
        for (int ni = 0; ni < 2; ni++) {
            mma8(c1[mi][ni], a[mi], b1[ni]);
            mma8(c2[mi][ni], a[mi], b2[ni]);
        }
    }
}

// ---- 16-warp layout (512 threads, warp tile 16x16) ----
#define WARP_IDX16                                 \
    int tid = threadIdx.x;                         \
    int lane = tid & 31, wid = tid >> 5;           \
    int wr = (wid >> 2) * 16, wc = (wid & 3) * 16; \
    int g = lane >> 2, tig = lane & 3;

__device__ __forceinline__ void mma_tile16(const float (*As)[PA_], const float (*Bs)[PB_],
                                           float (&acc)[2][4],
                                           int wr, int wc, int g, int tig)
{
#pragma unroll
    for (int kb = 0; kb < 64; kb += 8) {
        uint32_t a[4], b[2][2];
        a[0] = __float_as_uint(As[wr + g    ][kb + tig    ]);
        a[1] = __float_as_uint(As[wr + g + 8][kb + tig    ]);
        a[2] = __float_as_uint(As[wr + g    ][kb + tig + 4]);
        a[3] = __float_as_uint(As[wr + g + 8][kb + tig + 4]);
#pragma unroll
        for (int ni = 0; ni < 2; ni++) {
            int c0 = wc + ni*8 + g;
            b[ni][0] = __float_as_uint(Bs[kb + tig    ][c0]);
            b[ni][1] = __float_as_uint(Bs[kb + tig + 4][c0]);
        }
        mma8(acc[0], a, b[0]);
        mma8(acc[1], a, b[1]);
    }
}

__device__ __forceinline__ void mma_tile16r(const float (*As)[PA_], const float (*Bs)[PA_],
                                            float (&acc)[2][4],
                                            int wr, int wc, int g, int tig)
{
#pragma unroll
    for (int kb = 0; kb < 64; kb += 8) {
        uint32_t a[4], b[2][2];
        a[0] = __float_as_uint(As[wr + g    ][kb + tig    ]);
        a[1] = __float_as_uint(As[wr + g + 8][kb + tig    ]);
        a[2] = __float_as_uint(As[wr + g    ][kb + tig + 4]);
        a[3] = __float_as_uint(As[wr + g + 8][kb + tig + 4]);
#pragma unroll
        for (int ni = 0; ni < 2; ni++) {
            int c0 = wc + ni*8 + g;
            b[ni][0] = __float_as_uint(Bs[c0][kb + tig    ]);
            b[ni][1] = __float_as_uint(Bs[c0][kb + tig + 4]);
        }
        mma8(acc[0], a, b[0]);
        mma8(acc[1], a, b[1]);
    }
}

// ---------------- staging helpers ----------------------------------------------
__device__ __forceinline__ void ldg4_256(const float* __restrict__ p, int ld, float4 (&v)[4]) {
    int t = threadIdx.x * 4;
#pragma unroll
    for (int u = 0; u < 4; u++) {
        int l = t + u*1024;
        v[u] = *(const float4*)(p + (size_t)(l >> 6)*ld + (l & 63));
    }
}
template<int P>
__device__ __forceinline__ void sts4_256(float (*Ts)[P], const float4 (&v)[4]) {
    int t = threadIdx.x * 4;
#pragma unroll
    for (int u = 0; u < 4; u++) {
        int l = t + u*1024;
        *(float4*)&Ts[l >> 6][l & 63] = tf4(v[u]);
    }
}
template<int P>
__device__ __forceinline__ void stage512f(float (*Ts)[P], const float* __restrict__ p, int ld) {
    int t = threadIdx.x * 4;
#pragma unroll
    for (int u = 0; u < 2; u++) {
        int l = t + u*2048, r = l >> 6, c = l & 63;
        float4 v = *(const float4*)(p + (size_t)r*ld + c);
        *(float4*)&Ts[r][c] = tf4(v);
    }
}
// load w once; write W (positive, pad PA_) and -beta*w (pad PB_)
__device__ __forceinline__ void stageW_BWn(float (*Wt)[PA_], float (*Bt)[PB_],
                                           const float* __restrict__ wp,
                                           const float* __restrict__ bp) {
    int t = threadIdx.x * 4;
#pragma unroll
    for (int u = 0; u < 2; u++) {
        int l = t + u*2048, r = l >> 6, c = l & 63;
        float4 v = *(const float4*)(wp + (size_t)r*DMM + c);
        *(float4*)&Wt[r][c] = tf4(v);
        float nb = -bp[r*HH];
        float4 w4 = make_float4(v.x*nb, v.y*nb, v.z*nb, v.w*nb);
        *(float4*)&Bt[r][c] = tf4(w4);
    }
}

// ---------------- fused projection ----------------------------------------------
__global__ __launch_bounds__(256, 2) void proj_kernel(
    const float* __restrict__ x,  const float* __restrict__ Wq,
    const float* __restrict__ Wk, const float* __restrict__ Wv,
    const float* __restrict__ Ww1,const float* __restrict__ Wb)
{
    extern __shared__ float sm[];
    float (*Ab0)[PA_] = (float(*)[PA_])sm;
    float (*Ab1)[PA_] = (float(*)[PA_])(sm + ASZ);
    float (*Bb0)[PB_] = (float(*)[PB_])(sm + 2*ASZ);
    float (*Bb1)[PB_] = (float(*)[PB_])(sm + 2*ASZ + BSZ);
    float (*Ab[2])[PA_] = {Ab0, Ab1};
    float (*Bb[2])[PB_] = {Bb0, Bb1};
    WARP_IDX;
    int bm = blockIdx.y * 64, bn = blockIdx.x * 64;
    float acc[2][2][4] = {};
    float4 va[4], vb[4];

    auto ldB = [&](int kt) {
        int t = tid * 4;
#pragma unroll
        for (int u = 0; u < 4; u++) {
            int l = t + u*1024, r = l >> 6, c = l & 63;
            int kk = kt + r;
            if (bn < 3072) {
                const float* W = (bn < 1024) ? Wq : (bn < 2048) ? Wk : Wv;
                vb[u] = *(const float4*)&W[(size_t)kk*DMM + ((bn + c) & 1023)];
            } else {
                float tv[4];
#pragma unroll
                for (int q2 = 0; q2 < 4; q2++) {
                    int nn = bn + c + q2;
                    tv[q2] = (nn < 3104) ? Ww1[kk*RNK + (nn - 3072)]
                           : (nn < NPROJ) ? Wb[kk*HH + (nn - 3104)] : 0.f;
                }
                vb[u] = make_float4(tv[0], tv[1], tv[2], tv[3]);
            }
        }
    };

    ldg4_256(&x[(size_t)bm*DMM], DMM, va);
    ldB(0);
    sts4_256<PA_>(Ab[0], va);
    sts4_256<PB_>(Bb[0], vb);
    __syncthreads();
    int cur = 0;
    for (int i = 0; i < 16; i++) {
        if (i < 15) { ldg4_256(&x[(size_t)bm*DMM + (i+1)*64], DMM, va); ldB((i+1)*64); }
        mma_tile8(Ab[cur], Bb[cur], acc, wr, wc, g, tig);
        if (i < 15) {
            sts4_256<PA_>(Ab[cur^1], va);
            sts4_256<PB_>(Bb[cur^1], vb);
            __syncthreads();
            cur ^= 1;
        }
    }
#pragma unroll
    for (int mi = 0; mi < 2; mi++)
#pragma unroll
    for (int ni = 0; ni < 2; ni++)
#pragma unroll
    for (int e = 0; e < 4; e++) {
        int row = bm + ACC_ROW(mi, e);
        int col = bn + ACC_COL(ni, e);
        float v = acc[mi][ni][e];
        if      (col < 1024)  g_q[(size_t)row*DMM + col] = v;
        else if (col < 2048)  g_k[(size_t)row*DMM + (col - 1024)] = v;
        else if (col < 3072)  g_v[(size_t)row*DMM + (col - 2048)] = v;
        else if (col < 3104)  g_xw1[row*RNK + (col - 3072)] = v;
        else if (col < NPROJ) g_beta[row*HH + (col - 3104)] = 2.f/(1.f + expf(-v));
    }
}

// ---------------- generic C = A@B -------------------------------------------------
__global__ __launch_bounds__(256, 2) void gemm_tc(
    const float* __restrict__ A, const float* __restrict__ B,
    float* __restrict__ C, int N, int K)
{
    extern __shared__ float sm[];
    float (*Ab0)[PA_] = (float(*)[PA_])sm;
    float (*Ab1)[PA_] = (float(*)[PA_])(sm + ASZ);
    float (*Bb0)[PB_] = (float(*)[PB_])(sm + 2*ASZ);
    float (*Bb1)[PB_] = (float(*)[PB_])(sm + 2*ASZ + BSZ);
    float (*Ab[2])[PA_] = {Ab0, Ab1};
    float (*Bb[2])[PB_] = {Bb0, Bb1};
    WARP_IDX;
    int bm = blockIdx.y * 64, bn = blockIdx.x * 64;
    float acc[2][2][4] = {};
    float4 va[4], vb[4];

    auto ldA = [&](int kt) {
        int t = tid * 4;
#pragma unroll
        for (int u = 0; u < 4; u++) {
            int l = t + u*1024, r = l >> 6, c = l & 63;
            va[u] = (kt + c < K) ? *(const float4*)&A[(size_t)(bm + r)*K + kt + c]
                                 : make_float4(0.f, 0.f, 0.f, 0.f);
        }
    };
    auto ldB = [&](int kt) {
        int t = tid * 4;
#pragma unroll
        for (int u = 0; u < 4; u++) {
            int l = t + u*1024, r = l >> 6, c = l & 63;
            vb[u] = (kt + r < K) ? *(const float4*)&B[(size_t)(kt + r)*N + bn + c]
                                 : make_float4(0.f, 0.f, 0.f, 0.f);
        }
    };

    int nk = (K + 63) / 64;
    ldA(0); ldB(0);
    sts4_256<PA_>(Ab[0], va);
    sts4_256<PB_>(Bb[0], vb);
    __syncthreads();
    int cur = 0;
    for (int i = 0; i < nk; i++) {
        if (i < nk - 1) { ldA((i+1)*64); ldB((i+1)*64); }
        mma_tile8(Ab[cur], Bb[cur], acc, wr, wc, g, tig);
        if (i < nk - 1) {
            sts4_256<PA_>(Ab[cur^1], va);
            sts4_256<PB_>(Bb[cur^1], vb);
            __syncthreads();
            cur ^= 1;
        }
    }
#pragma unroll
    for (int mi = 0; mi < 2; mi++)
#pragma unroll
    for (int ni = 0; ni < 2; ni++)
#pragma unroll
    for (int e = 0; e < 4; e++)
        C[(size_t)(bm + ACC_ROW(mi, e))*N + bn + ACC_COL(ni, e)] = acc[mi][ni][e];
}

// ---------------- conv + SiLU + per-head L2 norm ----------------------------------
__global__ void conv_norm_kernel(const float* __restrict__ conv_w)
{
    int t = blockIdx.x;
    int c = threadIdx.x;
    float x0  = g_wpre[t*DMM + c];
    float xm1 = (t >= 1) ? g_wpre[(t-1)*DMM + c] : 0.f;
    float xm2 = (t >= 2) ? g_wpre[(t-2)*DMM + c] : 0.f;
    float y = conv_w[c*3+0]*xm2 + conv_w[c*3+1]*xm1 + conv_w[c*3+2]*x0;
    y = y / (1.f + expf(-y));
    float y2 = y * y;
#pragma unroll
    for (int o = 16; o; o >>= 1) y2 += __shfl_xor_sync(0xffffffffu, y2, o);
    __shared__ float wsum[32];
    if ((c & 31) == 0) wsum[c >> 5] = y2;
    __syncthreads();
    int h = c >> 6;
    float ss = wsum[2*h] + wsum[2*h+1];
    g_w[t*DMM + c] = y * rsqrtf(ss + 1e-6f);
}

// ---------------- diag blocks: Md (strict) and -MkD (strict) ----------------------
__global__ __launch_bounds__(256) void diagblk_kernel()
{
    __shared__ float Aw[64][PA_];
    __shared__ float Bk[64][PA_];
    int J = blockIdx.x, h = blockIdx.y;
    WARP_IDX;
    {
        int t = tid * 4;
#pragma unroll
        for (int u = 0; u < 4; u++) {
            int l = t + u*1024, r = l >> 6, c = l & 63;
            *(float4*)&Aw[r][c] = tf4(*(const float4*)&g_w[(size_t)(J*64 + r)*DMM + h*64 + c]);
            *(float4*)&Bk[r][c] = tf4(*(const float4*)&g_k[(size_t)(J*64 + r)*DMM + h*64 + c]);
        }
    }
    __syncthreads();
    float am[2][2][4] = {}, amk[2][2][4] = {};
    mma_tile2r(Aw, Aw, Bk, am, amk, wr, wc, g, tig);
    size_t ofs = ((size_t)h*NT + J)*4096;
#pragma unroll
    for (int mi = 0; mi < 2; mi++)
#pragma unroll
    for (int ni = 0; ni < 2; ni++)
#pragma unroll
    for (int e = 0; e < 4; e += 2) {
        int r = ACC_ROW(mi, e), c = ACC_COL(ni, e);
        float be = g_beta[(size_t)(J*64 + r)*HH + h];
        float2 md, mk;
        md.x = (r > c    ) ?  be*am [mi][ni][e]   : 0.f;
        md.y = (r > c + 1) ?  be*am [mi][ni][e+1] : 0.f;
        mk.x = (r > c    ) ? -be*amk[mi][ni][e]   : 0.f;
        mk.y = (r > c + 1) ? -be*amk[mi][ni][e+1] : 0.f;
        *(float2*)&g_Md [ofs + r*64 + c] = md;
        *(float2*)&g_MkD[ofs + r*64 + c] = mk;
    }
}

// ---------------- invert unit-lower diagonal blocks --------------------------------
__global__ void inv_diag_kernel()
{
    int J = blockIdx.x, h = blockIdx.y;
    int c = threadIdx.x;
    __shared__ float L[64][65];
    __shared__ float X[64][65];
    const float* Mt = &g_Md[((size_t)h*NT + J)*4096];
    for (int r = 0; r < 64; r++) {
        L[r][c] = Mt[r*64 + c] + ((r == c) ? 1.f : 0.f);
        X[r][c] = (r == c) ? 1.f : 0.f;
    }
    __syncthreads();
    for (int r = 1; r < 64; r++) {
        if (c < r) {
            float a = 0.f;
            for (int s = c; s < r; s++) a += L[r][s] * X[s][c];
            X[r][c] = -a;
        }
        __syncthreads();
    }
    float* out = &g_invA[((size_t)h*NT + J)*4096];
    for (int r = 0; r < 64; r++) out[r*64 + c] = X[r][c];
}

// ---------------- fused row scan: Aqw/QK + solve + S + softmax + PV ----------------
__global__ __launch_bounds__(512) void row_kernel()
{
    extern __shared__ float sm[];
    float (*Qsm)[PA_]  = (float(*)[PA_])(sm);
    float (*Psm)[PA_]  = (float(*)[PA_])(sm + ASZ);       // holds Pneg = -P
    float (*Gtmp)[PA_] = (float(*)[PA_])(sm + 2*ASZ);
    float (*Wrow)[PA_] = (float(*)[PA_])(sm + 3*ASZ);     // w_J positive
    float (*Krow)[PA_] = (float(*)[PA_])(sm + 4*ASZ);     // k_J positive
    float (*Binv)[PB_] = (float(*)[PB_])(sm + 5*ASZ);
    float (*MkDs)[PB_] = (float(*)[PB_])(sm + 5*ASZ + BSZ);
    float (*BWn)[PB_]  = (float(*)[PB_])(sm + 5*ASZ + 2*BSZ);  // -beta*w_J
    __shared__ float rmax[64], rinv[64], red[64][8];
    int h = blockIdx.x;
    int I = NT - 1 - blockIdx.y;       // heavy rows launch first
    size_t base = (size_t)h*TT*TT;
    WARP_IDX16;

    // stage Q_I once (constant for this CTA)
    stage512f<PA_>(Qsm, &g_q[(size_t)(I*64)*DMM + h*64], DMM);

    float Pn[2][4] = {};               // Pneg state = -sum_{S>J} G[:,S] BW_S
    for (int J = I; J >= 0; J--) {
        // stage this step's operands
        stageW_BWn(Wrow, BWn, &g_w[(size_t)(J*64)*DMM + h*64],
                   &g_beta[(size_t)(J*64)*HH + h]);
        stage512f<PA_>(Krow, &g_k[(size_t)(J*64)*DMM + h*64], DMM);
        stage512f<PB_>(Binv, &g_invA[((size_t)h*NT + J)*4096], 64);
        stage512f<PB_>(MkDs, &g_MkD [((size_t)h*NT + J)*4096], 64);
        if (J < I) {
#pragma unroll
            for (int ni = 0; ni < 2; ni++) {
                int c0 = wc + ni*8 + tig*2;
                Psm[wr+g  ][c0]   = to_tf32(Pn[ni][0]);
                Psm[wr+g  ][c0+1] = to_tf32(Pn[ni][1]);
                Psm[wr+g+8][c0]   = to_tf32(Pn[ni][2]);
                Psm[wr+g+8][c0+1] = to_tf32(Pn[ni][3]);
            }
        }
        __syncthreads();

        // acc = Q@W^T (+ Pneg@W^T), sacc = Q@K^T (+ Pneg@K^T)
        float acc[2][4] = {}, sacc[2][4] = {};
        mma_tile16r(Qsm, Wrow, acc,  wr, wc, g, tig);
        mma_tile16r(Qsm, Krow, sacc, wr, wc, g, tig);
        if (J < I) {
            mma_tile16r(Psm, Wrow, acc,  wr, wc, g, tig);
            mma_tile16r(Psm, Krow, sacc, wr, wc, g, tig);
        } else {
            // diagonal tile: causal mask on Aqw (keep c <= r)
#pragma unroll
            for (int ni = 0; ni < 2; ni++) {
                int c0 = wc + ni*8 + tig*2;
                int r0 = wr + g, r1 = wr + g + 8;
                if (c0     > r0) acc[ni][0] = 0.f;
                if (c0 + 1 > r0) acc[ni][1] = 0.f;
                if (c0     > r1) acc[ni][2] = 0.f;
                if (c0 + 1 > r1) acc[ni][3] = 0.f;
            }
        }
        // acc -> Gtmp for invA multiply
#pragma unroll
        for (int ni = 0; ni < 2; ni++) {
            int c0 = wc + ni*8 + tig*2;
            Gtmp[wr+g  ][c0]   = to_tf32(acc[ni][0]);
            Gtmp[wr+g  ][c0+1] = to_tf32(acc[ni][1]);
            Gtmp[wr+g+8][c0]   = to_tf32(acc[ni][2]);
            Gtmp[wr+g+8][c0+1] = to_tf32(acc[ni][3]);
        }
        __syncthreads();
        float Gf[2][4] = {};
        mma_tile16(Gtmp, Binv, Gf, wr, wc, g, tig);
        __syncthreads();
#pragma unroll
        for (int ni = 0; ni < 2; ni++) {
            int c0 = wc + ni*8 + tig*2;
            Gtmp[wr+g  ][c0]   = to_tf32(Gf[ni][0]);
            Gtmp[wr+g  ][c0+1] = to_tf32(Gf[ni][1]);
            Gtmp[wr+g+8][c0]   = to_tf32(Gf[ni][2]);
            Gtmp[wr+g+8][c0+1] = to_tf32(Gf[ni][3]);
        }
        __syncthreads();
        mma_tile16(Gtmp, MkDs, sacc, wr, wc, g, tig);   // sacc -= G@MkD (preneg)
        mma_tile16(Gtmp, BWn,  Pn,   wr, wc, g, tig);   // Pneg -= G@BW
        // store scaled/masked S tile
        float* So = &g_S[base + (size_t)(I*64)*TT + J*64];
#pragma unroll
        for (int ni = 0; ni < 2; ni++) {
            int c0 = wc + ni*8 + tig*2;
            int r0 = wr + g, r1 = wr + g + 8;
            float2 v0, v1;
            v0.x = sacc[ni][0]*SCALE; v0.y = sacc[ni][1]*SCALE;
            v1.x = sacc[ni][2]*SCALE; v1.y = sacc[ni][3]*SCALE;
            if (J == I) {
                if (c0     > r0) v0.x = -1e30f;
                if (c0 + 1 > r0) v0.y = -1e30f;
                if (c0     > r1) v1.x = -1e30f;
                if (c0 + 1 > r1) v1.y = -1e30f;
            }
            *(float2*)(So + (size_t)r0*TT + c0) = v0;
            *(float2*)(So + (size_t)r1*TT + c0) = v1;
        }
        __syncthreads();
    }

    // ---- row softmax stats ----
    {
        int r = tid >> 3, part = tid & 7;
        const float* Srow = &g_S[base + (size_t)(I*64 + r)*TT];
        int ncols = (I + 1) * 64;
        float m = -1e30f;
        for (int c = part*4; c < ncols; c += 32) {
            float4 v = *(const float4*)&Srow[c];
            m = fmaxf(m, fmaxf(fmaxf(v.x, v.y), fmaxf(v.z, v.w)));
        }
        red[r][part] = m;
        __syncthreads();
#pragma unroll
        for (int u = 0; u < 8; u++) m = fmaxf(m, red[r][u]);
        float s = 0.f;
        for (int c = part*4; c < ncols; c += 32) {
            float4 v = *(const float4*)&Srow[c];
            s += __expf(v.x - m) + __expf(v.y - m) + __expf(v.z - m) + __expf(v.w - m);
        }
        __syncthreads();
        red[r][part] = s;
        __syncthreads();
        if (part == 0) {
            float tsum = 0.f;
#pragma unroll
            for (int u = 0; u < 8; u++) tsum += red[r][u];
            rmax[r] = m;
            rinv[r] = 1.f / tsum;
        }
        __syncthreads();
    }

    // ---- o[I] = softmax(S) @ V ----
    float O[2][4] = {};
    for (int bj = 0; bj <= I; bj++) {
        {
            int t = tid * 4;
            const float* Sp = &g_S[base + (size_t)(I*64)*TT + bj*64];
#pragma unroll
            for (int u = 0; u < 2; u++) {
                int l = t + u*2048, r = l >> 6, c = l & 63;
                float4 v = *(const float4*)(Sp + (size_t)r*TT + c);
                float mr = rmax[r], iv = rinv[r];
                v.x = to_tf32(__expf(v.x - mr) * iv);
                v.y = to_tf32(__expf(v.y - mr) * iv);
                v.z = to_tf32(__expf(v.z - mr) * iv);
                v.w = to_tf32(__expf(v.w - mr) * iv);
                *(float4*)&Wrow[r][c] = v;
            }
            stage512f<PB_>(Binv, &g_v[(size_t)(bj*64)*DMM + h*64], DMM);
        }
        __syncthreads();
        mma_tile16(Wrow, Binv, O, wr, wc, g, tig);
        __syncthreads();
    }
#pragma unroll
    for (int ni = 0; ni < 2; ni++) {
        int c0 = wc + ni*8 + tig*2;
        float2 v0 = make_float2(O[ni][0], O[ni][1]);
        float2 v1 = make_float2(O[ni][2], O[ni][3]);
        *(float2*)&g_o[(size_t)(I*64 + wr + g    )*DMM + h*64 + c0] = v0;
        *(float2*)&g_o[(size_t)(I*64 + wr + g + 8)*DMM + h*64 + c0] = v1;
    }
}

// ---------------- launcher ----------------------------------------------------------
extern "C" void kernel_launch(void* const* d_in, const int* in_sizes, int n_in,
                              void* d_out, int out_size)
{
    const float* x     = (const float*)d_in[0];
    const float* Wq    = (const float*)d_in[1];
    const float* Wk    = (const float*)d_in[2];
    const float* Wv    = (const float*)d_in[3];
    const float* Ww1   = (const float*)d_in[4];
    const float* Ww2   = (const float*)d_in[5];
    const float* convw = (const float*)d_in[6];
    const float* Wb    = (const float*)d_in[7];
    const float* Wo    = (const float*)d_in[8];

    float *xw1, *wpre, *o;
    cudaGetSymbolAddress((void**)&xw1,  g_xw1);
    cudaGetSymbolAddress((void**)&wpre, g_wpre);
    cudaGetSymbolAddress((void**)&o,    g_o);

    const int SM_DB  = (2*ASZ + 2*BSZ) * 4;     // 71680 B
    const int SM_ROW = (5*ASZ + 3*BSZ) * 4;     // 142336 B
    static bool attr_set = false;
    if (!attr_set) {
        cudaFuncSetAttribute(proj_kernel, cudaFuncAttributeMaxDynamicSharedMemorySize, SM_DB);
        cudaFuncSetAttribute(gemm_tc,     cudaFuncAttributeMaxDynamicSharedMemorySize, SM_DB);
        cudaFuncSetAttribute(row_kernel,  cudaFuncAttributeMaxDynamicSharedMemorySize, SM_ROW);
        attr_set = true;
    }

    dim3 blk(256);

    proj_kernel<<<dim3((NPROJ + 63)/64, 16), blk, SM_DB>>>(x, Wq, Wk, Wv, Ww1, Wb);
    gemm_tc<<<dim3(16, 16), blk, SM_DB>>>(xw1, Ww2, wpre, DMM, RNK);
    conv_norm_kernel<<<TT, 1024>>>(convw);
    diagblk_kernel<<<dim3(NT, HH), blk>>>();
    inv_diag_kernel<<<dim3(NT, HH), 64>>>();
    row_kernel<<<dim3(HH, NT), 512, SM_ROW>>>();
    gemm_tc<<<dim3(16, 16), blk, SM_DB>>>(o, Wo, (float*)d_out, DMM, DMM);
}

// round 11
// speedup vs baseline: 6.3173x; 1.0336x over previous
#include <cuda_runtime.h>
#include <math.h>
#include <stdint.h>

#define TT   1024
#define DMM  1024
#define HH   16
#define RNK  32
#define NT   16
#define SCALE 0.125f
#define NPROJ 3120     // 3*1024 + 32 + 16

#define PA_  68
#define PB_  72
#define ASZ  (64*PA_)
#define BSZ  (64*PB_)

// ---------------- scratch (device globals) ----------------------------------
__device__ float g_q   [TT*DMM];
__device__ float g_k   [TT*DMM];
__device__ float g_v   [TT*DMM];
__device__ float g_wpre[TT*DMM];
__device__ float g_w   [TT*DMM];
__device__ float g_xw1 [TT*RNK];
__device__ float g_beta[TT*HH];
__device__ float g_invA[HH*NT*64*64];
__device__ float g_Md [HH*NT*64*64]; // strict diag M blocks
__device__ float g_MkD[HH*NT*64*64]; // strict diag Mk blocks, NEGATED
__device__ float g_o [TT*DMM];

// ---------------- tf32 helpers ------------------------------------------------
__device__ __forceinline__ float to_tf32(float x) {
    uint32_t u; asm("cvt.rna.tf32.f32 %0, %1;" : "=r"(u) : "f"(x));
    return __uint_as_float(u);
}
__device__ __forceinline__ float4 tf4(float4 v) {
    v.x = to_tf32(v.x); v.y = to_tf32(v.y); v.z = to_tf32(v.z); v.w = to_tf32(v.w);
    return v;
}

__device__ __forceinline__ void mma8(float (&c)[4], const uint32_t (&a)[4],
                                     const uint32_t (&b)[2]) {
    asm volatile(
        "mma.sync.aligned.m16n8k8.row.col.f32.tf32.tf32.f32 "
        "{%0,%1,%2,%3},{%4,%5,%6,%7},{%8,%9},{%0,%1,%2,%3};"
        : "+f"(c[0]), "+f"(c[1]), "+f"(c[2]), "+f"(c[3])
        : "r"(a[0]), "r"(a[1]), "r"(a[2]), "r"(a[3]), "r"(b[0]), "r"(b[1]));
}

// ---- 8-warp layout (256 threads, warp tile 32x16) ----
#define WARP_IDX                                   \
    int tid = threadIdx.x;                         \
    int lane = tid & 31, wid = tid >> 5;           \
    int wr = (wid >> 2) * 32, wc = (wid & 3) * 16; \
    int g = lane >> 2, tig = lane & 3;

#define ACC_ROW(mi,e) (wr + (mi)*16 + g + ((e)>>1)*8)
#define ACC_COL(ni,e) (wc + (ni)*8 + tig*2 + ((e)&1))

__device__ __forceinline__ void mma_tile8(const float (*As)[PA_], const float (*Bs)[PB_],
                                          float (&acc)[2][2][4],
                                          int wr, int wc, int g, int tig)
{
#pragma unroll
    for (int kb = 0; kb < 64; kb += 8) {
        uint32_t a[2][4], b[2][2];
#pragma unroll
        for (int mi = 0; mi < 2; mi++) {
            int r0 = wr + mi*16 + g;
            a[mi][0] = __float_as_uint(As[r0    ][kb + tig    ]);
            a[mi][1] = __float_as_uint(As[r0 + 8][kb + tig    ]);
            a[mi][2] = __float_as_uint(As[r0    ][kb + tig + 4]);
            a[mi][3] = __float_as_uint(As[r0 + 8][kb + tig + 4]);
        }
#pragma unroll
        for (int ni = 0; ni < 2; ni++) {
            int c0 = wc + ni*8 + g;
            b[ni][0] = __float_as_uint(Bs[kb + tig    ][c0]);
            b[ni][1] = __float_as_uint(Bs[kb + tig + 4][c0]);
        }
#pragma unroll
        for (int mi = 0; mi < 2; mi++)
#pragma unroll
            for (int ni = 0; ni < 2; ni++)
                mma8(acc[mi][ni], a[mi], b[ni]);
    }
}

__device__ __forceinline__ void mma_tile2r(const float (*As)[PA_],
        const float (*B1)[PA_], const float (*B2)[PA_],
        float (&c1)[2][2][4], float (&c2)[2][2][4],
        int wr, int wc, int g, int tig)
{
#pragma unroll
    for (int kb = 0; kb < 64; kb += 8) {
        uint32_t a[2][4], b1[2][2], b2[2][2];
#pragma unroll
        for (int mi = 0; mi < 2; mi++) {
            int r0 = wr + mi*16 + g;
            a[mi][0] = __float_as_uint(As[r0    ][kb + tig    ]);
            a[mi][1] = __float_as_uint(As[r0 + 8][kb + tig    ]);
            a[mi][2] = __float_as_uint(As[r0    ][kb + tig + 4]);
            a[mi][3] = __float_as_uint(As[r0 + 8][kb + tig + 4]);
        }
#pragma unroll
        for (int ni = 0; ni < 2; ni++) {
            int c0 = wc + ni*8 + g;
            b1[ni][0] = __float_as_uint(B1[c0][kb + tig    ]);
            b1[ni][1] = __float_as_uint(B1[c0][kb + tig + 4]);
            b2[ni][0] = __float_as_uint(B2[c0][kb + tig    ]);
            b2[ni][1] = __float_as_uint(B2[c0][kb + tig + 4]);
        }
#pragma unroll
        for (int mi = 0; mi < 2; mi++)
#pragma unroll
        for (int ni = 0; ni < 2; ni++) {
            mma8(c1[mi][ni], a[mi], b1[ni]);
            mma8(c2[mi][ni], a[mi], b2[ni]);
        }
    }
}

// ---- 16-warp layout (512 threads, warp tile 16x16) ----
#define WARP_IDX16                                 \
    int tid = threadIdx.x;                         \
    int lane = tid & 31, wid = tid >> 5;           \
    int wr = (wid >> 2) * 16, wc = (wid & 3) * 16; \
    int g = lane >> 2, tig = lane & 3;

__device__ __forceinline__ void mma_tile16(const float (*As)[PA_], const float (*Bs)[PB_],
                                           float (&acc)[2][4],
                                           int wr, int wc, int g, int tig)
{
#pragma unroll
    for (int kb = 0; kb < 64; kb += 8) {
        uint32_t a[4], b[2][2];
        a[0] = __float_as_uint(As[wr + g    ][kb + tig    ]);
        a[1] = __float_as_uint(As[wr + g + 8][kb + tig    ]);
        a[2] = __float_as_uint(As[wr + g    ][kb + tig + 4]);
        a[3] = __float_as_uint(As[wr + g + 8][kb + tig + 4]);
#pragma unroll
        for (int ni = 0; ni < 2; ni++) {
            int c0 = wc + ni*8 + g;
            b[ni][0] = __float_as_uint(Bs[kb + tig    ][c0]);
            b[ni][1] = __float_as_uint(Bs[kb + tig + 4][c0]);
        }
        mma8(acc[0], a, b[0]);
        mma8(acc[1], a, b[1]);
    }
}

__device__ __forceinline__ void mma_tile16r(const float (*As)[PA_], const float (*Bs)[PA_],
                                            float (&acc)[2][4],
                                            int wr, int wc, int g, int tig)
{
#pragma unroll
    for (int kb = 0; kb < 64; kb += 8) {
        uint32_t a[4], b[2][2];
        a[0] = __float_as_uint(As[wr + g    ][kb + tig    ]);
        a[1] = __float_as_uint(As[wr + g + 8][kb + tig    ]);
        a[2] = __float_as_uint(As[wr + g    ][kb + tig + 4]);
        a[3] = __float_as_uint(As[wr + g + 8][kb + tig + 4]);
#pragma unroll
        for (int ni = 0; ni < 2; ni++) {
            int c0 = wc + ni*8 + g;
            b[ni][0] = __float_as_uint(Bs[c0][kb + tig    ]);
            b[ni][1] = __float_as_uint(Bs[c0][kb + tig + 4]);
        }
        mma8(acc[0], a, b[0]);
        mma8(acc[1], a, b[1]);
    }
}

// ---------------- staging helpers ----------------------------------------------
__device__ __forceinline__ void ldg4_256(const float* __restrict__ p, int ld, float4 (&v)[4]) {
    int t = threadIdx.x * 4;
#pragma unroll
    for (int u = 0; u < 4; u++) {
        int l = t + u*1024;
        v[u] = *(const float4*)(p + (size_t)(l >> 6)*ld + (l & 63));
    }
}
template<int P>
__device__ __forceinline__ void sts4_256(float (*Ts)[P], const float4 (&v)[4]) {
    int t = threadIdx.x * 4;
#pragma unroll
    for (int u = 0; u < 4; u++) {
        int l = t + u*1024;
        *(float4*)&Ts[l >> 6][l & 63] = tf4(v[u]);
    }
}
template<int P>
__device__ __forceinline__ void stage512f(float (*Ts)[P], const float* __restrict__ p, int ld) {
    int t = threadIdx.x * 4;
#pragma unroll
    for (int u = 0; u < 2; u++) {
        int l = t + u*2048, r = l >> 6, c = l & 63;
        float4 v = *(const float4*)(p + (size_t)r*ld + c);
        *(float4*)&Ts[r][c] = tf4(v);
    }
}
// load w once; write W (positive, pad PA_) and -beta*w (pad PB_)
__device__ __forceinline__ void stageW_BWn(float (*Wt)[PA_], float (*Bt)[PB_],
                                           const float* __restrict__ wp,
                                           const float* __restrict__ bp) {
    int t = threadIdx.x * 4;
#pragma unroll
    for (int u = 0; u < 2; u++) {
        int l = t + u*2048, r = l >> 6, c = l & 63;
        float4 v = *(const float4*)(wp + (size_t)r*DMM + c);
        *(float4*)&Wt[r][c] = tf4(v);
        float nb = -bp[r*HH];
        float4 w4 = make_float4(v.x*nb, v.y*nb, v.z*nb, v.w*nb);
        *(float4*)&Bt[r][c] = tf4(w4);
    }
}

// ---------------- fused projection ----------------------------------------------
__global__ __launch_bounds__(256, 2) void proj_kernel(
    const float* __restrict__ x,  const float* __restrict__ Wq,
    const float* __restrict__ Wk, const float* __restrict__ Wv,
    const float* __restrict__ Ww1,const float* __restrict__ Wb)
{
    extern __shared__ float sm[];
    float (*Ab0)[PA_] = (float(*)[PA_])sm;
    float (*Ab1)[PA_] = (float(*)[PA_])(sm + ASZ);
    float (*Bb0)[PB_] = (float(*)[PB_])(sm + 2*ASZ);
    float (*Bb1)[PB_] = (float(*)[PB_])(sm + 2*ASZ + BSZ);
    float (*Ab[2])[PA_] = {Ab0, Ab1};
    float (*Bb[2])[PB_] = {Bb0, Bb1};
    WARP_IDX;
    int bm = blockIdx.y * 64, bn = blockIdx.x * 64;
    float acc[2][2][4] = {};
    float4 va[4], vb[4];

    auto ldB = [&](int kt) {
        int t = tid * 4;
#pragma unroll
        for (int u = 0; u < 4; u++) {
            int l = t + u*1024, r = l >> 6, c = l & 63;
            int kk = kt + r;
            if (bn < 3072) {
                const float* W = (bn < 1024) ? Wq : (bn < 2048) ? Wk : Wv;
                vb[u] = *(const float4*)&W[(size_t)kk*DMM + ((bn + c) & 1023)];
            } else {
                float tv[4];
#pragma unroll
                for (int q2 = 0; q2 < 4; q2++) {
                    int nn = bn + c + q2;
                    tv[q2] = (nn < 3104) ? Ww1[kk*RNK + (nn - 3072)]
                           : (nn < NPROJ) ? Wb[kk*HH + (nn - 3104)] : 0.f;
                }
                vb[u] = make_float4(tv[0], tv[1], tv[2], tv[3]);
            }
        }
    };

    ldg4_256(&x[(size_t)bm*DMM], DMM, va);
    ldB(0);
    sts4_256<PA_>(Ab[0], va);
    sts4_256<PB_>(Bb[0], vb);
    __syncthreads();
    int cur = 0;
    for (int i = 0; i < 16; i++) {
        if (i < 15) { ldg4_256(&x[(size_t)bm*DMM + (i+1)*64], DMM, va); ldB((i+1)*64); }
        mma_tile8(Ab[cur], Bb[cur], acc, wr, wc, g, tig);
        if (i < 15) {
            sts4_256<PA_>(Ab[cur^1], va);
            sts4_256<PB_>(Bb[cur^1], vb);
            __syncthreads();
            cur ^= 1;
        }
    }
#pragma unroll
    for (int mi = 0; mi < 2; mi++)
#pragma unroll
    for (int ni = 0; ni < 2; ni++)
#pragma unroll
    for (int e = 0; e < 4; e++) {
        int row = bm + ACC_ROW(mi, e);
        int col = bn + ACC_COL(ni, e);
        float v = acc[mi][ni][e];
        if      (col < 1024)  g_q[(size_t)row*DMM + col] = v;
        else if (col < 2048)  g_k[(size_t)row*DMM + (col - 1024)] = v;
        else if (col < 3072)  g_v[(size_t)row*DMM + (col - 2048)] = v;
        else if (col < 3104)  g_xw1[row*RNK + (col - 3072)] = v;
        else if (col < NPROJ) g_beta[row*HH + (col - 3104)] = 2.f/(1.f + expf(-v));
    }
}

// ---------------- generic C = A@B -------------------------------------------------
__global__ __launch_bounds__(256, 2) void gemm_tc(
    const float* __restrict__ A, const float* __restrict__ B,
    float* __restrict__ C, int N, int K)
{
    extern __shared__ float sm[];
    float (*Ab0)[PA_] = (float(*)[PA_])sm;
    float (*Ab1)[PA_] = (float(*)[PA_])(sm + ASZ);
    float (*Bb0)[PB_] = (float(*)[PB_])(sm + 2*ASZ);
    float (*Bb1)[PB_] = (float(*)[PB_])(sm + 2*ASZ + BSZ);
    float (*Ab[2])[PA_] = {Ab0, Ab1};
    float (*Bb[2])[PB_] = {Bb0, Bb1};
    WARP_IDX;
    int bm = blockIdx.y * 64, bn = blockIdx.x * 64;
    float acc[2][2][4] = {};
    float4 va[4], vb[4];

    auto ldA = [&](int kt) {
        int t = tid * 4;
#pragma unroll
        for (int u = 0; u < 4; u++) {
            int l = t + u*1024, r = l >> 6, c = l & 63;
            va[u] = (kt + c < K) ? *(const float4*)&A[(size_t)(bm + r)*K + kt + c]
                                 : make_float4(0.f, 0.f, 0.f, 0.f);
        }
    };
    auto ldB = [&](int kt) {
        int t = tid * 4;
#pragma unroll
        for (int u = 0; u < 4; u++) {
            int l = t + u*1024, r = l >> 6, c = l & 63;
            vb[u] = (kt + r < K) ? *(const float4*)&B[(size_t)(kt + r)*N + bn + c]
                                 : make_float4(0.f, 0.f, 0.f, 0.f);
        }
    };

    int nk = (K + 63) / 64;
    ldA(0); ldB(0);
    sts4_256<PA_>(Ab[0], va);
    sts4_256<PB_>(Bb[0], vb);
    __syncthreads();
    int cur = 0;
    for (int i = 0; i < nk; i++) {
        if (i < nk - 1) { ldA((i+1)*64); ldB((i+1)*64); }
        mma_tile8(Ab[cur], Bb[cur], acc, wr, wc, g, tig);
        if (i < nk - 1) {
            sts4_256<PA_>(Ab[cur^1], va);
            sts4_256<PB_>(Bb[cur^1], vb);
            __syncthreads();
            cur ^= 1;
        }
    }
#pragma unroll
    for (int mi = 0; mi < 2; mi++)
#pragma unroll
    for (int ni = 0; ni < 2; ni++)
#pragma unroll
    for (int e = 0; e < 4; e++)
        C[(size_t)(bm + ACC_ROW(mi, e))*N + bn + ACC_COL(ni, e)] = acc[mi][ni][e];
}

// ---------------- conv + SiLU + per-head L2 norm ----------------------------------
__global__ void conv_norm_kernel(const float* __restrict__ conv_w)
{
    int t = blockIdx.x;
    int c = threadIdx.x;
    float x0  = g_wpre[t*DMM + c];
    float xm1 = (t >= 1) ? g_wpre[(t-1)*DMM + c] : 0.f;
    float xm2 = (t >= 2) ? g_wpre[(t-2)*DMM + c] : 0.f;
    float y = conv_w[c*3+0]*xm2 + conv_w[c*3+1]*xm1 + conv_w[c*3+2]*x0;
    y = y / (1.f + expf(-y));
    float y2 = y * y;
#pragma unroll
    for (int o = 16; o; o >>= 1) y2 += __shfl_xor_sync(0xffffffffu, y2, o);
    __shared__ float wsum[32];
    if ((c & 31) == 0) wsum[c >> 5] = y2;
    __syncthreads();
    int h = c >> 6;
    float ss = wsum[2*h] + wsum[2*h+1];
    g_w[t*DMM + c] = y * rsqrtf(ss + 1e-6f);
}

// ---------------- diag blocks: Md (strict) and -MkD (strict) ----------------------
__global__ __launch_bounds__(256) void diagblk_kernel()
{
    __shared__ float Aw[64][PA_];
    __shared__ float Bk[64][PA_];
    int J = blockIdx.x, h = blockIdx.y;
    WARP_IDX;
    {
        int t = tid * 4;
#pragma unroll
        for (int u = 0; u < 4; u++) {
            int l = t + u*1024, r = l >> 6, c = l & 63;
            *(float4*)&Aw[r][c] = tf4(*(const float4*)&g_w[(size_t)(J*64 + r)*DMM + h*64 + c]);
            *(float4*)&Bk[r][c] = tf4(*(const float4*)&g_k[(size_t)(J*64 + r)*DMM + h*64 + c]);
        }
    }
    __syncthreads();
    float am[2][2][4] = {}, amk[2][2][4] = {};
    mma_tile2r(Aw, Aw, Bk, am, amk, wr, wc, g, tig);
    size_t ofs = ((size_t)h*NT + J)*4096;
#pragma unroll
    for (int mi = 0; mi < 2; mi++)
#pragma unroll
    for (int ni = 0; ni < 2; ni++)
#pragma unroll
    for (int e = 0; e < 4; e += 2) {
        int r = ACC_ROW(mi, e), c = ACC_COL(ni, e);
        float be = g_beta[(size_t)(J*64 + r)*HH + h];
        float2 md, mk;
        md.x = (r > c    ) ?  be*am [mi][ni][e]   : 0.f;
        md.y = (r > c + 1) ?  be*am [mi][ni][e+1] : 0.f;
        mk.x = (r > c    ) ? -be*amk[mi][ni][e]   : 0.f;
        mk.y = (r > c + 1) ? -be*amk[mi][ni][e+1] : 0.f;
        *(float2*)&g_Md [ofs + r*64 + c] = md;
        *(float2*)&g_MkD[ofs + r*64 + c] = mk;
    }
}

// ---------------- invert unit-lower diagonal blocks --------------------------------
__global__ void inv_diag_kernel()
{
    int J = blockIdx.x, h = blockIdx.y;
    int c = threadIdx.x;
    __shared__ float L[64][65];
    __shared__ float X[64][65];
    const float* Mt = &g_Md[((size_t)h*NT + J)*4096];
    for (int r = 0; r < 64; r++) {
        L[r][c] = Mt[r*64 + c] + ((r == c) ? 1.f : 0.f);
        X[r][c] = (r == c) ? 1.f : 0.f;
    }
    __syncthreads();
    for (int r = 1; r < 64; r++) {
        if (c < r) {
            float a = 0.f;
            for (int s = c; s < r; s++) a += L[r][s] * X[s][c];
            X[r][c] = -a;
        }
        __syncthreads();
    }
    float* out = &g_invA[((size_t)h*NT + J)*4096];
    for (int r = 0; r < 64; r++) out[r*64 + c] = X[r][c];
}

// ---------------- fused row scan: Aqw/QK + solve + online softmax + PV -------------
__global__ __launch_bounds__(512) void row_kernel()
{
    extern __shared__ float sm[];
    float (*Qsm)[PA_]  = (float(*)[PA_])(sm);
    float (*Psm)[PA_]  = (float(*)[PA_])(sm + ASZ);       // Pneg = -P state
    float (*Gtmp)[PA_] = (float(*)[PA_])(sm + 2*ASZ);
    float (*Wrow)[PA_] = (float(*)[PA_])(sm + 3*ASZ);     // w_J, then exp(P) tile
    float (*Krow)[PA_] = (float(*)[PA_])(sm + 4*ASZ);     // k_J
    float (*Binv)[PB_] = (float(*)[PB_])(sm + 5*ASZ);
    float (*MkDs)[PB_] = (float(*)[PB_])(sm + 5*ASZ + BSZ);
    float (*BWn)[PB_]  = (float(*)[PB_])(sm + 5*ASZ + 2*BSZ);  // -beta*w_J
    float (*Vsm)[PB_]  = (float(*)[PB_])(sm + 5*ASZ + 3*BSZ);  // v_J
    __shared__ float red[64][8];    // cols 0-3: max partials, 4-7: sum partials
    int h = blockIdx.x;
    int I = NT - 1 - blockIdx.y;    // heavy rows launch first
    WARP_IDX16;
    int wcg = wid & 3;
    int r0 = wr + g, r1 = wr + g + 8;

    // stage Q_I once (constant for this CTA)
    stage512f<PA_>(Qsm, &g_q[(size_t)(I*64)*DMM + h*64], DMM);

    float Pn[2][4] = {};            // Pneg state
    float O[2][4]  = {};            // output accumulator (unnormalized)
    float m0 = -1e30f, m1 = -1e30f; // running row maxes
    float s0 = 0.f,    s1 = 0.f;    // running row sums

    for (int J = I; J >= 0; J--) {
        stageW_BWn(Wrow, BWn, &g_w[(size_t)(J*64)*DMM + h*64],
                   &g_beta[(size_t)(J*64)*HH + h]);
        stage512f<PA_>(Krow, &g_k[(size_t)(J*64)*DMM + h*64], DMM);
        stage512f<PB_>(Binv, &g_invA[((size_t)h*NT + J)*4096], 64);
        stage512f<PB_>(MkDs, &g_MkD [((size_t)h*NT + J)*4096], 64);
        stage512f<PB_>(Vsm,  &g_v[(size_t)(J*64)*DMM + h*64], DMM);
        if (J < I) {
#pragma unroll
            for (int ni = 0; ni < 2; ni++) {
                int c0 = wc + ni*8 + tig*2;
                Psm[r0][c0]   = to_tf32(Pn[ni][0]);
                Psm[r0][c0+1] = to_tf32(Pn[ni][1]);
                Psm[r1][c0]   = to_tf32(Pn[ni][2]);
                Psm[r1][c0+1] = to_tf32(Pn[ni][3]);
            }
        }
        __syncthreads();

        // acc = Q@W^T (+ Pneg@W^T), sacc = Q@K^T (+ Pneg@K^T)
        float acc[2][4] = {}, sacc[2][4] = {};
        mma_tile16r(Qsm, Wrow, acc,  wr, wc, g, tig);
        mma_tile16r(Qsm, Krow, sacc, wr, wc, g, tig);
        if (J < I) {
            mma_tile16r(Psm, Wrow, acc,  wr, wc, g, tig);
            mma_tile16r(Psm, Krow, sacc, wr, wc, g, tig);
        } else {
            // diagonal tile: causal mask on Aqw (keep c <= r)
#pragma unroll
            for (int ni = 0; ni < 2; ni++) {
                int c0 = wc + ni*8 + tig*2;
                if (c0     > r0) acc[ni][0] = 0.f;
                if (c0 + 1 > r0) acc[ni][1] = 0.f;
                if (c0     > r1) acc[ni][2] = 0.f;
                if (c0 + 1 > r1) acc[ni][3] = 0.f;
            }
        }
        // acc -> Gtmp for invA multiply
#pragma unroll
        for (int ni = 0; ni < 2; ni++) {
            int c0 = wc + ni*8 + tig*2;
            Gtmp[r0][c0]   = to_tf32(acc[ni][0]);
            Gtmp[r0][c0+1] = to_tf32(acc[ni][1]);
            Gtmp[r1][c0]   = to_tf32(acc[ni][2]);
            Gtmp[r1][c0+1] = to_tf32(acc[ni][3]);
        }
        __syncthreads();
        float Gf[2][4] = {};
        mma_tile16(Gtmp, Binv, Gf, wr, wc, g, tig);
        __syncthreads();
#pragma unroll
        for (int ni = 0; ni < 2; ni++) {
            int c0 = wc + ni*8 + tig*2;
            Gtmp[r0][c0]   = to_tf32(Gf[ni][0]);
            Gtmp[r0][c0+1] = to_tf32(Gf[ni][1]);
            Gtmp[r1][c0]   = to_tf32(Gf[ni][2]);
            Gtmp[r1][c0+1] = to_tf32(Gf[ni][3]);
        }
        __syncthreads();
        mma_tile16(Gtmp, MkDs, sacc, wr, wc, g, tig);   // sacc -= G@MkD (preneg)
        mma_tile16(Gtmp, BWn,  Pn,   wr, wc, g, tig);   // Pneg -= G@BW

        // ---- online softmax on this tile ----
        float tv[2][4];
        float lm0 = -1e30f, lm1 = -1e30f;
#pragma unroll
        for (int ni = 0; ni < 2; ni++) {
            int c0 = wc + ni*8 + tig*2;
#pragma unroll
            for (int e = 0; e < 4; e++) {
                float v = sacc[ni][e] * SCALE;
                int rr = (e < 2) ? r0 : r1;
                int cc = c0 + (e & 1);
                if (J == I && cc > rr) v = -1e30f;
                tv[ni][e] = v;
                if (e < 2) lm0 = fmaxf(lm0, v); else lm1 = fmaxf(lm1, v);
            }
        }
#pragma unroll
        for (int o = 1; o < 4; o <<= 1) {
            lm0 = fmaxf(lm0, __shfl_xor_sync(0xffffffffu, lm0, o));
            lm1 = fmaxf(lm1, __shfl_xor_sync(0xffffffffu, lm1, o));
        }
        if (tig == 0) { red[r0][wcg] = lm0; red[r1][wcg] = lm1; }
        __syncthreads();
        float m0n = fmaxf(m0, fmaxf(fmaxf(red[r0][0], red[r0][1]),
                                    fmaxf(red[r0][2], red[r0][3])));
        float m1n = fmaxf(m1, fmaxf(fmaxf(red[r1][0], red[r1][1]),
                                    fmaxf(red[r1][2], red[r1][3])));
        float sc0 = __expf(m0 - m0n), sc1 = __expf(m1 - m1n);
        m0 = m0n; m1 = m1n;
        s0 *= sc0; s1 *= sc1;
#pragma unroll
        for (int ni = 0; ni < 2; ni++)
#pragma unroll
        for (int e = 0; e < 4; e++)
            O[ni][e] *= (e < 2) ? sc0 : sc1;

        // exp tile -> Wrow (free now) + local sums
        float ls0 = 0.f, ls1 = 0.f;
#pragma unroll
        for (int ni = 0; ni < 2; ni++) {
            int c0 = wc + ni*8 + tig*2;
#pragma unroll
            for (int e = 0; e < 4; e++) {
                float p = __expf(tv[ni][e] - ((e < 2) ? m0 : m1));
                if (e < 2) ls0 += p; else ls1 += p;
                int rr = (e < 2) ? r0 : r1;
                Wrow[rr][c0 + (e & 1)] = to_tf32(p);
            }
        }
#pragma unroll
        for (int o = 1; o < 4; o <<= 1) {
            ls0 += __shfl_xor_sync(0xffffffffu, ls0, o);
            ls1 += __shfl_xor_sync(0xffffffffu, ls1, o);
        }
        if (tig == 0) { red[r0][4 + wcg] = ls0; red[r1][4 + wcg] = ls1; }
        __syncthreads();
        s0 += red[r0][4] + red[r0][5] + red[r0][6] + red[r0][7];
        s1 += red[r1][4] + red[r1][5] + red[r1][6] + red[r1][7];

        mma_tile16(Wrow, Vsm, O, wr, wc, g, tig);       // O += exp(P) @ V_J
        __syncthreads();
    }

    // normalize and write output
    float i0 = 1.f / s0, i1 = 1.f / s1;
#pragma unroll
    for (int ni = 0; ni < 2; ni++) {
        int c0 = wc + ni*8 + tig*2;
        float2 v0 = make_float2(O[ni][0]*i0, O[ni][1]*i0);
        float2 v1 = make_float2(O[ni][2]*i1, O[ni][3]*i1);
        *(float2*)&g_o[(size_t)(I*64 + r0)*DMM + h*64 + c0] = v0;
        *(float2*)&g_o[(size_t)(I*64 + r1)*DMM + h*64 + c0] = v1;
    }
}

// ---------------- launcher ----------------------------------------------------------
extern "C" void kernel_launch(void* const* d_in, const int* in_sizes, int n_in,
                              void* d_out, int out_size)
{
    const float* x     = (const float*)d_in[0];
    const float* Wq    = (const float*)d_in[1];
    const float* Wk    = (const float*)d_in[2];
    const float* Wv    = (const float*)d_in[3];
    const float* Ww1   = (const float*)d_in[4];
    const float* Ww2   = (const float*)d_in[5];
    const float* convw = (const float*)d_in[6];
    const float* Wb    = (const float*)d_in[7];
    const float* Wo    = (const float*)d_in[8];

    float *xw1, *wpre, *o;
    cudaGetSymbolAddress((void**)&xw1,  g_xw1);
    cudaGetSymbolAddress((void**)&wpre, g_wpre);
    cudaGetSymbolAddress((void**)&o,    g_o);

    const int SM_DB  = (2*ASZ + 2*BSZ) * 4;     // 71680 B
    const int SM_ROW = (5*ASZ + 4*BSZ) * 4;     // 160768 B
    static bool attr_set = false;
    if (!attr_set) {
        cudaFuncSetAttribute(proj_kernel, cudaFuncAttributeMaxDynamicSharedMemorySize, SM_DB);
        cudaFuncSetAttribute(gemm_tc,     cudaFuncAttributeMaxDynamicSharedMemorySize, SM_DB);
        cudaFuncSetAttribute(row_kernel,  cudaFuncAttributeMaxDynamicSharedMemorySize, SM_ROW);
        attr_set = true;
    }

    dim3 blk(256);

    proj_kernel<<<dim3((NPROJ + 63)/64, 16), blk, SM_DB>>>(x, Wq, Wk, Wv, Ww1, Wb);
    gemm_tc<<<dim3(16, 16), blk, SM_DB>>>(xw1, Ww2, wpre, DMM, RNK);
    conv_norm_kernel<<<TT, 1024>>>(convw);
    diagblk_kernel<<<dim3(NT, HH), blk>>>();
    inv_diag_kernel<<<dim3(NT, HH), 64>>>();
    row_kernel<<<dim3(HH, NT), 512, SM_ROW>>>();
    gemm_tc<<<dim3(16, 16), blk, SM_DB>>>(o, Wo, (float*)d_out, DMM, DMM);
}